// round 1
// baseline (speedup 1.0000x reference)
#include <cuda_runtime.h>
#include <cuda_bf16.h>
#include <math.h>

// ---------------------------------------------------------------------------
// CLIP ViT-B/16 visual tower, fp32 baseline.
// B=32, R=224, P=16, D=768, H=12, HD=64, F=3072, L=12, S=197, O=512
// ---------------------------------------------------------------------------

#define Bsz 32
#define Dm  768
#define Hh  12
#define HD  64
#define Ff  3072
#define Ll  12
#define Ss  197
#define Oo  512
#define NPATCH 196
#define NTOK (Bsz * Ss)        // 6304
#define NPROW (Bsz * NPATCH)   // 6272

// ------------------------- scratch (static device globals) -----------------
__device__ float g_xp[NPROW * Dm];      // normalized patch matrix
__device__ float g_x [NTOK * Dm];       // residual stream
__device__ float g_h [NTOK * Dm];       // LN output
__device__ float g_qkv[NTOK * 3 * Dm];  // fused qkv
__device__ float g_attn[NTOK * Dm];     // attn out (also reused as patch-embed out)
__device__ float g_mlp[NTOK * Ff];      // mlp hidden
__device__ float g_cls[Bsz * Dm];       // ln_post(cls)

// ------------------------- patchify + normalize ----------------------------
__global__ void k_patchify(const float* __restrict__ img, float* __restrict__ xp)
{
    const float mean[3] = {0.48145466f, 0.4578275f, 0.40821073f};
    const float istd[3] = {1.f/0.26862954f, 1.f/0.26130258f, 1.f/0.27577711f};
    int idx = blockIdx.x * blockDim.x + threadIdx.x;
    if (idx >= NPROW * Dm) return;
    int col = idx % Dm;           // c*256 + ph*16 + pw
    int row = idx / Dm;           // b*196 + py*14 + px
    int b  = row / NPATCH;
    int p  = row % NPATCH;
    int py = p / 14, px = p % 14;
    int c  = col >> 8;
    int rem = col & 255;
    int ph = rem >> 4, pw = rem & 15;
    float v = img[(((size_t)b * 3 + c) * 224 + py * 16 + ph) * 224 + px * 16 + pw];
    xp[idx] = (v - mean[c]) * istd[c];
}

// ------------------------- generic SGEMM: C = A @ W^T (+bias)(+gelu)(+res) --
// A[M,K] row-major, W[N,K] row-major, C[M,N]. N % 64 == 0, K % 16 == 0.
template<bool BIAS, bool RES, bool GELU_>
__global__ void k_gemm(const float* __restrict__ A, const float* __restrict__ W,
                       const float* __restrict__ bias, const float* __restrict__ res,
                       float* __restrict__ C, int M, int N, int K)
{
    __shared__ float As[16][65];
    __shared__ float Bs[16][65];
    int tid = threadIdx.x;
    int tx = tid & 15, ty = tid >> 4;
    int bm = blockIdx.y * 64, bn = blockIdx.x * 64;
    float acc[4][4] = {};

    for (int k0 = 0; k0 < K; k0 += 16) {
        #pragma unroll
        for (int i = 0; i < 4; i++) {
            int idx = tid + i * 256;
            int kk = idx & 15, m = idx >> 4;
            int arow = bm + m;
            As[kk][m] = (arow < M) ? A[(size_t)arow * K + k0 + kk] : 0.f;
            Bs[kk][m] = W[(size_t)(bn + m) * K + k0 + kk];
        }
        __syncthreads();
        #pragma unroll
        for (int kk = 0; kk < 16; kk++) {
            float a[4], b[4];
            #pragma unroll
            for (int i = 0; i < 4; i++) a[i] = As[kk][ty * 4 + i];
            #pragma unroll
            for (int j = 0; j < 4; j++) b[j] = Bs[kk][tx * 4 + j];
            #pragma unroll
            for (int i = 0; i < 4; i++)
                #pragma unroll
                for (int j = 0; j < 4; j++) acc[i][j] += a[i] * b[j];
        }
        __syncthreads();
    }

    #pragma unroll
    for (int i = 0; i < 4; i++) {
        int row = bm + ty * 4 + i;
        if (row >= M) continue;
        #pragma unroll
        for (int j = 0; j < 4; j++) {
            int col = bn + tx * 4 + j;
            float v = acc[i][j];
            if (BIAS)  v += bias[col];
            if (GELU_) v = v / (1.f + __expf(-1.702f * v));   // QuickGELU
            if (RES)   v += res[(size_t)row * N + col];
            C[(size_t)row * N + col] = v;
        }
    }
}

// ------------------------- assemble tokens (cls + patches + pos) -----------
__global__ void k_assemble(const float* __restrict__ pe, const float* __restrict__ cls,
                           const float* __restrict__ pos, float* __restrict__ x)
{
    int idx = blockIdx.x * blockDim.x + threadIdx.x;
    if (idx >= NTOK * Dm) return;
    int d = idx % Dm;
    int t = idx / Dm;
    int s = t % Ss, b = t / Ss;
    float v = (s == 0) ? cls[d] : pe[((size_t)b * NPATCH + (s - 1)) * Dm + d];
    x[idx] = v + pos[(size_t)s * Dm + d];
}

// ------------------------- LayerNorm ---------------------------------------
// one block (256 thr) per row of 768
__global__ void k_ln(const float* __restrict__ in, float* __restrict__ out,
                     const float* __restrict__ sc, const float* __restrict__ bi,
                     long in_stride, long out_stride)
{
    __shared__ float red[2][32];
    long row = blockIdx.x;
    const float* ip = in + row * in_stride;
    float* op = out + row * out_stride;
    int tid = threadIdx.x;
    float v[3];
    float s = 0.f, sq = 0.f;
    #pragma unroll
    for (int i = 0; i < 3; i++) {
        v[i] = ip[tid + i * 256];
        s += v[i]; sq += v[i] * v[i];
    }
    #pragma unroll
    for (int o = 16; o > 0; o >>= 1) {
        s  += __shfl_xor_sync(~0u, s, o);
        sq += __shfl_xor_sync(~0u, sq, o);
    }
    int lane = tid & 31, w = tid >> 5;
    if (lane == 0) { red[0][w] = s; red[1][w] = sq; }
    __syncthreads();
    if (w == 0) {
        float a = (lane < 8) ? red[0][lane] : 0.f;
        float b = (lane < 8) ? red[1][lane] : 0.f;
        #pragma unroll
        for (int o = 4; o > 0; o >>= 1) {
            a += __shfl_xor_sync(~0u, a, o);
            b += __shfl_xor_sync(~0u, b, o);
        }
        if (lane == 0) { red[0][0] = a; red[1][0] = b; }
    }
    __syncthreads();
    float mean = red[0][0] * (1.f / Dm);
    float var  = red[1][0] * (1.f / Dm) - mean * mean;
    float r = rsqrtf(var + 1e-5f);
    #pragma unroll
    for (int i = 0; i < 3; i++) {
        int d = tid + i * 256;
        op[d] = (v[i] - mean) * r * sc[d] + bi[d];
    }
}

// ------------------------- fused attention ---------------------------------
// one block per (b, head). K,V in smem, warp-per-query softmax.
__global__ void k_attn(const float* __restrict__ QKV, float* __restrict__ out)
{
    extern __shared__ float sm[];
    float* Ks = sm;                       // 197*65
    float* Vs = Ks + Ss * 65;             // 197*65
    float* Qs = Vs + Ss * 65;             // 8*64
    float* Ps = Qs + 8 * 64;              // 8*200
    int bh = blockIdx.x;
    int b = bh / Hh, h = bh % Hh;
    int tid = threadIdx.x, lane = tid & 31, w = tid >> 5;
    const size_t base = (size_t)b * Ss * (3 * Dm) + (size_t)h * HD;

    for (int idx = tid; idx < Ss * HD; idx += 256) {
        int s = idx >> 6, d = idx & 63;
        Ks[s * 65 + d] = QKV[base + (size_t)s * (3 * Dm) + Dm + d];
        Vs[s * 65 + d] = QKV[base + (size_t)s * (3 * Dm) + 2 * Dm + d];
    }
    __syncthreads();

    for (int q = w; q < Ss; q += 8) {
        Qs[w * 64 + lane]      = QKV[base + (size_t)q * (3 * Dm) + lane] * 0.125f;
        Qs[w * 64 + lane + 32] = QKV[base + (size_t)q * (3 * Dm) + lane + 32] * 0.125f;
        __syncwarp();
        float mx = -1e30f;
        for (int k = lane; k < Ss; k += 32) {
            float s = 0.f;
            #pragma unroll
            for (int d = 0; d < HD; d++) s += Qs[w * 64 + d] * Ks[k * 65 + d];
            Ps[w * 200 + k] = s;
            mx = fmaxf(mx, s);
        }
        #pragma unroll
        for (int o = 16; o > 0; o >>= 1) mx = fmaxf(mx, __shfl_xor_sync(~0u, mx, o));
        float sum = 0.f;
        for (int k = lane; k < Ss; k += 32) {
            float p = __expf(Ps[w * 200 + k] - mx);
            Ps[w * 200 + k] = p;
            sum += p;
        }
        #pragma unroll
        for (int o = 16; o > 0; o >>= 1) sum += __shfl_xor_sync(~0u, sum, o);
        float inv = 1.f / sum;
        __syncwarp();
        float o0 = 0.f, o1 = 0.f;
        for (int k = 0; k < Ss; k++) {
            float p = Ps[w * 200 + k];
            o0 += p * Vs[k * 65 + lane];
            o1 += p * Vs[k * 65 + lane + 32];
        }
        size_t orow = ((size_t)b * Ss + q) * Dm + h * HD;
        out[orow + lane]      = o0 * inv;
        out[orow + lane + 32] = o1 * inv;
        __syncwarp();
    }
}

// ------------------------- head: cls_ln @ vis_proj -------------------------
__global__ void k_head(const float* __restrict__ cls, const float* __restrict__ Wp,
                       float* __restrict__ out)
{
    __shared__ float row[Dm];
    int b = blockIdx.x;
    for (int i = threadIdx.x; i < Dm; i += 256) row[i] = cls[(size_t)b * Dm + i];
    __syncthreads();
    for (int o = threadIdx.x; o < Oo; o += 256) {
        float acc = 0.f;
        for (int d = 0; d < Dm; d++) acc += row[d] * Wp[(size_t)d * Oo + o];
        out[(size_t)b * Oo + o] = acc;
    }
}

// ---------------------------------------------------------------------------
extern "C" void kernel_launch(void* const* d_in, const int* in_sizes, int n_in,
                              void* d_out, int out_size)
{
    const float* images   = (const float*)d_in[0];
    const float* conv_w   = (const float*)d_in[1];
    const float* cls_emb  = (const float*)d_in[2];
    const float* pos_emb  = (const float*)d_in[3];
    const float* ln_pre_s = (const float*)d_in[4];
    const float* ln_pre_b = (const float*)d_in[5];
    const float* ln1_s    = (const float*)d_in[6];
    const float* ln1_b    = (const float*)d_in[7];
    const float* qkv_w    = (const float*)d_in[8];
    const float* qkv_b    = (const float*)d_in[9];
    const float* out_w    = (const float*)d_in[10];
    const float* out_b    = (const float*)d_in[11];
    const float* ln2_s    = (const float*)d_in[12];
    const float* ln2_b    = (const float*)d_in[13];
    const float* fc_w     = (const float*)d_in[14];
    const float* fc_b     = (const float*)d_in[15];
    const float* proj_w   = (const float*)d_in[16];
    const float* proj_b   = (const float*)d_in[17];
    const float* lnp_s    = (const float*)d_in[18];
    const float* lnp_b    = (const float*)d_in[19];
    const float* vis_proj = (const float*)d_in[20];
    float* outp = (float*)d_out;

    float *xp, *x, *h, *qkv, *attn, *mlp, *cls;
    cudaGetSymbolAddress((void**)&xp,   g_xp);
    cudaGetSymbolAddress((void**)&x,    g_x);
    cudaGetSymbolAddress((void**)&h,    g_h);
    cudaGetSymbolAddress((void**)&qkv,  g_qkv);
    cudaGetSymbolAddress((void**)&attn, g_attn);
    cudaGetSymbolAddress((void**)&mlp,  g_mlp);
    cudaGetSymbolAddress((void**)&cls,  g_cls);

    int attn_smem = (2 * Ss * 65 + 8 * 64 + 8 * 200) * sizeof(float);   // ~111 KB
    cudaFuncSetAttribute(k_attn, cudaFuncAttributeMaxDynamicSharedMemorySize, attn_smem);

    // 1. patchify + normalize
    k_patchify<<<(NPROW * Dm + 255) / 256, 256>>>(images, xp);
    // 2. patch embedding GEMM: [6272,768] @ [768,768]^T  (no bias) -> attn buf
    k_gemm<false, false, false><<<dim3(Dm / 64, NPROW / 64), 256>>>(
        xp, conv_w, nullptr, nullptr, attn, NPROW, Dm, Dm);
    // 3. assemble tokens + pos emb
    k_assemble<<<(NTOK * Dm + 255) / 256, 256>>>(attn, cls_emb, pos_emb, x);
    // 4. ln_pre (in place)
    k_ln<<<NTOK, 256>>>(x, x, ln_pre_s, ln_pre_b, Dm, Dm);

    for (int l = 0; l < Ll; l++) {
        const float* l1s = ln1_s + (size_t)l * Dm;
        const float* l1b = ln1_b + (size_t)l * Dm;
        const float* qw  = qkv_w + (size_t)l * 3 * Dm * Dm;
        const float* qb  = qkv_b + (size_t)l * 3 * Dm;
        const float* ow  = out_w + (size_t)l * Dm * Dm;
        const float* ob  = out_b + (size_t)l * Dm;
        const float* l2s = ln2_s + (size_t)l * Dm;
        const float* l2b = ln2_b + (size_t)l * Dm;
        const float* fw  = fc_w  + (size_t)l * Ff * Dm;
        const float* fb  = fc_b  + (size_t)l * Ff;
        const float* pw  = proj_w + (size_t)l * Dm * Ff;
        const float* pb  = proj_b + (size_t)l * Dm;

        k_ln<<<NTOK, 256>>>(x, h, l1s, l1b, Dm, Dm);
        k_gemm<true, false, false><<<dim3(3 * Dm / 64, (NTOK + 63) / 64), 256>>>(
            h, qw, qb, nullptr, qkv, NTOK, 3 * Dm, Dm);
        k_attn<<<Bsz * Hh, 256, attn_smem>>>(qkv, attn);
        k_gemm<true, true, false><<<dim3(Dm / 64, (NTOK + 63) / 64), 256>>>(
            attn, ow, ob, x, x, NTOK, Dm, Dm);
        k_ln<<<NTOK, 256>>>(x, h, l2s, l2b, Dm, Dm);
        k_gemm<true, false, true><<<dim3(Ff / 64, (NTOK + 63) / 64), 256>>>(
            h, fw, fb, nullptr, mlp, NTOK, Ff, Dm);
        k_gemm<true, true, false><<<dim3(Dm / 64, (NTOK + 63) / 64), 256>>>(
            mlp, pw, pb, x, x, NTOK, Dm, Ff);
    }

    // ln_post on cls tokens only (row stride 197*768)
    k_ln<<<Bsz, 256>>>(x, cls, lnp_s, lnp_b, (long)Ss * Dm, Dm);
    // final projection [32,768] @ [768,512]
    k_head<<<Bsz, 256>>>(cls, vis_proj, outp);
}

// round 3
// speedup vs baseline: 3.1998x; 3.1998x over previous
#include <cuda_runtime.h>
#include <cuda_bf16.h>
#include <math.h>
#include <cstdint>

// ---------------------------------------------------------------------------
// CLIP ViT-B/16 visual tower on GB300 — mma.sync bf16 split-precision GEMMs.
// (tcgen05 unusable: harness PTX target is sm_103, not sm_103a)
// ---------------------------------------------------------------------------

#define Bsz 32
#define Dm  768
#define Hh  12
#define HD  64
#define Ff  3072
#define Ll  12
#define Ss  197
#define Oo  512
#define NPATCH 196
#define NTOK (Bsz * Ss)        // 6304
#define NPROW (Bsz * NPATCH)   // 6272

// ------------------------- helpers -----------------------------------------
__device__ __forceinline__ uint32_t smem_u32(const void* p) {
    uint32_t a;
    asm("{ .reg .u64 t; cvta.to.shared.u64 t, %1; cvt.u32.u64 %0, t; }"
        : "=r"(a) : "l"(p));
    return a;
}
__device__ __forceinline__ void cpa16(uint32_t dst, const void* src, uint32_t vsz) {
    asm volatile("cp.async.cg.shared.global [%0], [%1], 16, %2;"
                 :: "r"(dst), "l"(src), "r"(vsz) : "memory");
}
#define CP_COMMIT() asm volatile("cp.async.commit_group;" ::: "memory")
#define CP_WAIT0()  asm volatile("cp.async.wait_group 0;" ::: "memory")

#define MMA16816(c, a0, a1, a2, a3, b0, b1) \
    asm volatile("mma.sync.aligned.m16n8k16.row.col.f32.bf16.bf16.f32 " \
        "{%0,%1,%2,%3}, {%4,%5,%6,%7}, {%8,%9}, {%0,%1,%2,%3};" \
        : "+f"((c)[0]), "+f"((c)[1]), "+f"((c)[2]), "+f"((c)[3]) \
        : "r"(a0), "r"(a1), "r"(a2), "r"(a3), "r"(b0), "r"(b1))

// ------------------------- scratch (static device globals) -----------------
#define OFF_CONV 0ul
#define OFF_QKV  589824ul
#define OFF_OUT  21823488ul
#define OFF_FC   28901376ul
#define OFF_PROJ 57212928ul
#define WTOT     85524480ul

__device__ __align__(16) __nv_bfloat16 g_wh[WTOT];
__device__ __align__(16) __nv_bfloat16 g_wl[WTOT];
__device__ __align__(16) __nv_bfloat16 g_xph[NPROW * Dm];
__device__ __align__(16) __nv_bfloat16 g_xpl[NPROW * Dm];
__device__ float g_pe[NPROW * Dm];
__device__ float g_x [NTOK * Dm];
__device__ __align__(16) __nv_bfloat16 g_hh[NTOK * Dm];
__device__ __align__(16) __nv_bfloat16 g_hl[NTOK * Dm];
__device__ float g_qkv[NTOK * 3 * Dm];
__device__ __align__(16) __nv_bfloat16 g_aoh[NTOK * Dm];
__device__ __align__(16) __nv_bfloat16 g_aol[NTOK * Dm];
__device__ __align__(16) __nv_bfloat16 g_mlph[NTOK * Ff];
__device__ __align__(16) __nv_bfloat16 g_mlpl[NTOK * Ff];
__device__ float g_cls[Bsz * Dm];

// ------------------------- weight fp32 -> bf16 hi/lo -----------------------
__global__ void k_cvt(const float* __restrict__ src, __nv_bfloat16* __restrict__ hi,
                      __nv_bfloat16* __restrict__ lo, long n)
{
    long i = (long)blockIdx.x * blockDim.x + threadIdx.x;
    if (i >= n) return;
    float v = src[i];
    __nv_bfloat16 h = __float2bfloat16(v);
    hi[i] = h;
    lo[i] = __float2bfloat16(v - __bfloat162float(h));
}

// ------------------------- patchify + normalize -> hi/lo -------------------
__global__ void k_patchify(const float* __restrict__ img,
                           __nv_bfloat16* __restrict__ xh, __nv_bfloat16* __restrict__ xl)
{
    const float mean[3] = {0.48145466f, 0.4578275f, 0.40821073f};
    const float istd[3] = {1.f/0.26862954f, 1.f/0.26130258f, 1.f/0.27577711f};
    int idx = blockIdx.x * blockDim.x + threadIdx.x;
    if (idx >= NPROW * Dm) return;
    int col = idx % Dm;
    int row = idx / Dm;
    int b  = row / NPATCH;
    int p  = row % NPATCH;
    int py = p / 14, px = p % 14;
    int c  = col >> 8;
    int rem = col & 255;
    int ph = rem >> 4, pw = rem & 15;
    float v = img[(((size_t)b * 3 + c) * 224 + py * 16 + ph) * 224 + px * 16 + pw];
    v = (v - mean[c]) * istd[c];
    __nv_bfloat16 h = __float2bfloat16(v);
    xh[idx] = h;
    xl[idx] = __float2bfloat16(v - __bfloat162float(h));
}

// ------------------------- mma.sync split-bf16 GEMM ------------------------
// C[M,N] = A[M,K] @ W[N,K]^T (+bias)(+QuickGELU)(+res). N%128==0, K%64==0.
// Tile 128x128 per CTA, 8 warps (4x2), warp tile 32x64, K chunks of 64,
// double-buffered via cp.async. Smem row stride 72 bf16 (144 B).
#define STG_MAT   18432            // 128 rows * 144 B
#define STG_BYTES 73728            // 4 matrices (Ah, Al, Bh, Bl)
#define MM_SMEM   (2 * STG_BYTES)  // 147456

template<bool BIAS, bool RES, bool GELU_, bool BF16O>
__global__ __launch_bounds__(256) void k_mm(
    const __nv_bfloat16* __restrict__ Ah, const __nv_bfloat16* __restrict__ Al,
    const __nv_bfloat16* __restrict__ Bh, const __nv_bfloat16* __restrict__ Bl,
    const float* __restrict__ bias, const float* __restrict__ resi,
    float* __restrict__ C, __nv_bfloat16* __restrict__ Ch, __nv_bfloat16* __restrict__ Cl,
    int M, int N, int K)
{
    extern __shared__ char smc[];
    const uint32_t sb = smem_u32(smc);
    const int tid = threadIdx.x, lane = tid & 31, wid = tid >> 5;
    const int warp_m = wid & 3, warp_n = wid >> 2;
    const int bm = blockIdx.y * 128, bn = blockIdx.x * 128;
    const int Kd8 = K >> 3, nch = K >> 6;

    const uint4* A4[2] = {(const uint4*)Ah, (const uint4*)Al};
    const uint4* B4[2] = {(const uint4*)Bh, (const uint4*)Bl};

    float acc[2][8][4];
    #pragma unroll
    for (int a = 0; a < 2; a++)
        #pragma unroll
        for (int b = 0; b < 8; b++)
            #pragma unroll
            for (int c = 0; c < 4; c++) acc[a][b][c] = 0.f;

    // ---- chunk loader: chunk i -> stage s ----
    auto load_chunk = [&](int i, int s) {
        int k0d8 = i << 3;
        uint32_t stg = sb + s * STG_BYTES;
        #pragma unroll
        for (int t = tid; t < 4096; t += 256) {
            int mat = t >> 10, r = (t >> 3) & 127, c8 = t & 7;
            uint32_t dst = stg + mat * STG_MAT + r * 144 + c8 * 16;
            if (mat < 2) {
                int grow = bm + r;
                int ok = grow < M;
                const uint4* src = A4[mat] + (size_t)(ok ? grow : 0) * Kd8 + k0d8 + c8;
                cpa16(dst, src, ok ? 16u : 0u);
            } else {
                const uint4* src = B4[mat - 2] + (size_t)(bn + r) * Kd8 + k0d8 + c8;
                cpa16(dst, src, 16u);
            }
        }
        CP_COMMIT();
    };

    load_chunk(0, 0);
    CP_WAIT0();
    __syncthreads();

    const int qrow = lane >> 2;           // 0..7
    const int qk   = (lane & 3) << 2;     // byte offset of k-pair within 32B half

    for (int i = 0; i < nch; i++) {
        int s = i & 1;
        if (i + 1 < nch) load_chunk(i + 1, s ^ 1);

        const char* stg = smc + s * STG_BYTES;
        #pragma unroll
        for (int k16 = 0; k16 < 4; k16++) {
            int kb = k16 * 32 + qk;       // byte offset in row for this thread's k-pair
            uint32_t ah[2][4], al[2][4];
            #pragma unroll
            for (int mf = 0; mf < 2; mf++) {
                int r0 = (warp_m * 32 + mf * 16 + qrow) * 144;
                const char* pah = stg + r0;
                const char* pal = stg + STG_MAT + r0;
                ah[mf][0] = *(const uint32_t*)(pah + kb);
                ah[mf][1] = *(const uint32_t*)(pah + 8 * 144 + kb);
                ah[mf][2] = *(const uint32_t*)(pah + kb + 16);
                ah[mf][3] = *(const uint32_t*)(pah + 8 * 144 + kb + 16);
                al[mf][0] = *(const uint32_t*)(pal + kb);
                al[mf][1] = *(const uint32_t*)(pal + 8 * 144 + kb);
                al[mf][2] = *(const uint32_t*)(pal + kb + 16);
                al[mf][3] = *(const uint32_t*)(pal + 8 * 144 + kb + 16);
            }
            #pragma unroll
            for (int nf = 0; nf < 8; nf++) {
                int rn = (warp_n * 64 + nf * 8 + qrow) * 144;
                const char* pbh = stg + 2 * STG_MAT + rn;
                const char* pbl = stg + 3 * STG_MAT + rn;
                uint32_t bh0 = *(const uint32_t*)(pbh + kb);
                uint32_t bh1 = *(const uint32_t*)(pbh + kb + 16);
                uint32_t bl0 = *(const uint32_t*)(pbl + kb);
                uint32_t bl1 = *(const uint32_t*)(pbl + kb + 16);
                #pragma unroll
                for (int mf = 0; mf < 2; mf++) {
                    MMA16816(acc[mf][nf], ah[mf][0], ah[mf][1], ah[mf][2], ah[mf][3], bh0, bh1);
                    MMA16816(acc[mf][nf], al[mf][0], al[mf][1], al[mf][2], al[mf][3], bh0, bh1);
                    MMA16816(acc[mf][nf], ah[mf][0], ah[mf][1], ah[mf][2], ah[mf][3], bl0, bl1);
                }
            }
        }
        if (i + 1 < nch) CP_WAIT0();
        __syncthreads();
    }

    // ---- epilogue ----
    #pragma unroll
    for (int mf = 0; mf < 2; mf++) {
        #pragma unroll
        for (int nf = 0; nf < 8; nf++) {
            int rbase = bm + warp_m * 32 + mf * 16 + qrow;
            int cbase = bn + warp_n * 64 + nf * 8 + ((lane & 3) << 1);
            #pragma unroll
            for (int e = 0; e < 4; e++) {
                int row = rbase + ((e >> 1) << 3);
                int col = cbase + (e & 1);
                if (row >= M) continue;
                float v = acc[mf][nf][e];
                if (BIAS)  v += bias[col];
                if (GELU_) v = v / (1.f + __expf(-1.702f * v));
                if (RES)   v += resi[(size_t)row * N + col];
                if (BF16O) {
                    __nv_bfloat16 h = __float2bfloat16(v);
                    Ch[(size_t)row * N + col] = h;
                    Cl[(size_t)row * N + col] = __float2bfloat16(v - __bfloat162float(h));
                } else {
                    C[(size_t)row * N + col] = v;
                }
            }
        }
    }
}

// ------------------------- assemble tokens ---------------------------------
__global__ void k_assemble(const float* __restrict__ pe, const float* __restrict__ cls,
                           const float* __restrict__ pos, float* __restrict__ x)
{
    int idx = blockIdx.x * blockDim.x + threadIdx.x;
    if (idx >= NTOK * Dm) return;
    int d = idx % Dm;
    int t = idx / Dm;
    int s = t % Ss, b = t / Ss;
    float v = (s == 0) ? cls[d] : pe[((size_t)b * NPATCH + (s - 1)) * Dm + d];
    x[idx] = v + pos[(size_t)s * Dm + d];
}

// ------------------------- LayerNorm (fp32 out / hi-lo out) ----------------
template<bool HL>
__global__ void k_ln(const float* __restrict__ in, float* __restrict__ outf,
                     __nv_bfloat16* __restrict__ oh, __nv_bfloat16* __restrict__ ol,
                     const float* __restrict__ sc, const float* __restrict__ bi,
                     long in_stride, long out_stride)
{
    __shared__ float red[2][32];
    long row = blockIdx.x;
    const float* ip = in + row * in_stride;
    int tid = threadIdx.x;
    float v[3];
    float s = 0.f, sq = 0.f;
    #pragma unroll
    for (int i = 0; i < 3; i++) {
        v[i] = ip[tid + i * 256];
        s += v[i]; sq += v[i] * v[i];
    }
    #pragma unroll
    for (int o = 16; o > 0; o >>= 1) {
        s  += __shfl_xor_sync(~0u, s, o);
        sq += __shfl_xor_sync(~0u, sq, o);
    }
    int lane = tid & 31, w = tid >> 5;
    if (lane == 0) { red[0][w] = s; red[1][w] = sq; }
    __syncthreads();
    if (w == 0) {
        float a = (lane < 8) ? red[0][lane] : 0.f;
        float b = (lane < 8) ? red[1][lane] : 0.f;
        #pragma unroll
        for (int o = 4; o > 0; o >>= 1) {
            a += __shfl_xor_sync(~0u, a, o);
            b += __shfl_xor_sync(~0u, b, o);
        }
        if (lane == 0) { red[0][0] = a; red[1][0] = b; }
    }
    __syncthreads();
    float mean = red[0][0] * (1.f / Dm);
    float var  = red[1][0] * (1.f / Dm) - mean * mean;
    float r = rsqrtf(var + 1e-5f);
    #pragma unroll
    for (int i = 0; i < 3; i++) {
        int d = tid + i * 256;
        float y = (v[i] - mean) * r * sc[d] + bi[d];
        if (HL) {
            __nv_bfloat16 h = __float2bfloat16(y);
            oh[row * out_stride + d] = h;
            ol[row * out_stride + d] = __float2bfloat16(y - __bfloat162float(h));
        } else {
            outf[row * out_stride + d] = y;
        }
    }
}

// ------------------------- fused attention ---------------------------------
__global__ __launch_bounds__(256) void k_attn(const float* __restrict__ QKV,
                                              __nv_bfloat16* __restrict__ oh,
                                              __nv_bfloat16* __restrict__ ol)
{
    extern __shared__ float sm[];
    float* Ks = sm;                       // 197*65
    float* Vs = Ks + Ss * 65;             // 197*65
    float* Qs = Vs + Ss * 65;             // 8*64
    float* Ps = Qs + 8 * 64;              // 8*200
    int bh = blockIdx.x;
    int b = bh / Hh, h = bh % Hh;
    int tid = threadIdx.x, lane = tid & 31, w = tid >> 5;
    const size_t base = (size_t)b * Ss * (3 * Dm) + (size_t)h * HD;

    for (int idx = tid; idx < Ss * HD; idx += 256) {
        int s = idx >> 6, d = idx & 63;
        Ks[s * 65 + d] = QKV[base + (size_t)s * (3 * Dm) + Dm + d];
        Vs[s * 65 + d] = QKV[base + (size_t)s * (3 * Dm) + 2 * Dm + d];
    }
    __syncthreads();

    for (int q = w; q < Ss; q += 8) {
        Qs[w * 64 + lane]      = QKV[base + (size_t)q * (3 * Dm) + lane] * 0.125f;
        Qs[w * 64 + lane + 32] = QKV[base + (size_t)q * (3 * Dm) + lane + 32] * 0.125f;
        __syncwarp();
        float mx = -1e30f;
        for (int k = lane; k < Ss; k += 32) {
            float s = 0.f;
            #pragma unroll
            for (int d = 0; d < HD; d++) s += Qs[w * 64 + d] * Ks[k * 65 + d];
            Ps[w * 200 + k] = s;
            mx = fmaxf(mx, s);
        }
        #pragma unroll
        for (int o = 16; o > 0; o >>= 1) mx = fmaxf(mx, __shfl_xor_sync(~0u, mx, o));
        float sum = 0.f;
        for (int k = lane; k < Ss; k += 32) {
            float p = __expf(Ps[w * 200 + k] - mx);
            Ps[w * 200 + k] = p;
            sum += p;
        }
        #pragma unroll
        for (int o = 16; o > 0; o >>= 1) sum += __shfl_xor_sync(~0u, sum, o);
        float inv = 1.f / sum;
        __syncwarp();
        float o0 = 0.f, o1 = 0.f;
        #pragma unroll 4
        for (int k = 0; k < Ss; k++) {
            float p = Ps[w * 200 + k];
            o0 += p * Vs[k * 65 + lane];
            o1 += p * Vs[k * 65 + lane + 32];
        }
        o0 *= inv; o1 *= inv;
        size_t orow = ((size_t)b * Ss + q) * Dm + h * HD;
        __nv_bfloat16 h0 = __float2bfloat16(o0);
        __nv_bfloat16 h1 = __float2bfloat16(o1);
        oh[orow + lane]      = h0;
        ol[orow + lane]      = __float2bfloat16(o0 - __bfloat162float(h0));
        oh[orow + lane + 32] = h1;
        ol[orow + lane + 32] = __float2bfloat16(o1 - __bfloat162float(h1));
        __syncwarp();
    }
}

// ------------------------- head: cls_ln @ vis_proj -------------------------
__global__ void k_head(const float* __restrict__ cls, const float* __restrict__ Wp,
                       float* __restrict__ out)
{
    __shared__ float row[Dm];
    int b = blockIdx.x;
    for (int i = threadIdx.x; i < Dm; i += 256) row[i] = cls[(size_t)b * Dm + i];
    __syncthreads();
    for (int o = threadIdx.x; o < Oo; o += 256) {
        float acc = 0.f;
        for (int d = 0; d < Dm; d++) acc += row[d] * Wp[(size_t)d * Oo + o];
        out[(size_t)b * Oo + o] = acc;
    }
}

// ---------------------------------------------------------------------------
extern "C" void kernel_launch(void* const* d_in, const int* in_sizes, int n_in,
                              void* d_out, int out_size)
{
    const float* images   = (const float*)d_in[0];
    const float* conv_w   = (const float*)d_in[1];
    const float* cls_emb  = (const float*)d_in[2];
    const float* pos_emb  = (const float*)d_in[3];
    const float* ln_pre_s = (const float*)d_in[4];
    const float* ln_pre_b = (const float*)d_in[5];
    const float* ln1_s    = (const float*)d_in[6];
    const float* ln1_b    = (const float*)d_in[7];
    const float* qkv_w    = (const float*)d_in[8];
    const float* qkv_b    = (const float*)d_in[9];
    const float* out_w    = (const float*)d_in[10];
    const float* out_b    = (const float*)d_in[11];
    const float* ln2_s    = (const float*)d_in[12];
    const float* ln2_b    = (const float*)d_in[13];
    const float* fc_w     = (const float*)d_in[14];
    const float* fc_b     = (const float*)d_in[15];
    const float* proj_w   = (const float*)d_in[16];
    const float* proj_b   = (const float*)d_in[17];
    const float* lnp_s    = (const float*)d_in[18];
    const float* lnp_b    = (const float*)d_in[19];
    const float* vis_proj = (const float*)d_in[20];
    float* outp = (float*)d_out;

    __nv_bfloat16 *wh, *wl, *xph, *xpl, *hh, *hl, *aoh, *aol, *mlph, *mlpl;
    float *pe, *x, *qkv, *cls;
    cudaGetSymbolAddress((void**)&wh,   g_wh);
    cudaGetSymbolAddress((void**)&wl,   g_wl);
    cudaGetSymbolAddress((void**)&xph,  g_xph);
    cudaGetSymbolAddress((void**)&xpl,  g_xpl);
    cudaGetSymbolAddress((void**)&pe,   g_pe);
    cudaGetSymbolAddress((void**)&x,    g_x);
    cudaGetSymbolAddress((void**)&hh,   g_hh);
    cudaGetSymbolAddress((void**)&hl,   g_hl);
    cudaGetSymbolAddress((void**)&qkv,  g_qkv);
    cudaGetSymbolAddress((void**)&aoh,  g_aoh);
    cudaGetSymbolAddress((void**)&aol,  g_aol);
    cudaGetSymbolAddress((void**)&mlph, g_mlph);
    cudaGetSymbolAddress((void**)&mlpl, g_mlpl);
    cudaGetSymbolAddress((void**)&cls,  g_cls);

    cudaFuncSetAttribute(k_mm<false,false,false,false>, cudaFuncAttributeMaxDynamicSharedMemorySize, MM_SMEM);
    cudaFuncSetAttribute(k_mm<true, false,false,false>, cudaFuncAttributeMaxDynamicSharedMemorySize, MM_SMEM);
    cudaFuncSetAttribute(k_mm<true, true, false,false>, cudaFuncAttributeMaxDynamicSharedMemorySize, MM_SMEM);
    cudaFuncSetAttribute(k_mm<true, false,true, true >, cudaFuncAttributeMaxDynamicSharedMemorySize, MM_SMEM);
    int attn_smem = (2 * Ss * 65 + 8 * 64 + 8 * 200) * sizeof(float);
    cudaFuncSetAttribute(k_attn, cudaFuncAttributeMaxDynamicSharedMemorySize, attn_smem);

    // ---- weight fp32 -> bf16 hi/lo ----
    {
        long n;
        n = 589824;    k_cvt<<<(n + 255) / 256, 256>>>(conv_w, wh + OFF_CONV, wl + OFF_CONV, n);
        n = 21233664;  k_cvt<<<(n + 255) / 256, 256>>>(qkv_w,  wh + OFF_QKV,  wl + OFF_QKV,  n);
        n = 7077888;   k_cvt<<<(n + 255) / 256, 256>>>(out_w,  wh + OFF_OUT,  wl + OFF_OUT,  n);
        n = 28311552;  k_cvt<<<(n + 255) / 256, 256>>>(fc_w,   wh + OFF_FC,   wl + OFF_FC,   n);
        n = 28311552;  k_cvt<<<(n + 255) / 256, 256>>>(proj_w, wh + OFF_PROJ, wl + OFF_PROJ, n);
    }

    // ---- stem ----
    k_patchify<<<(NPROW * Dm + 255) / 256, 256>>>(images, xph, xpl);
    k_mm<false,false,false,false><<<dim3(Dm / 128, (NPROW + 127) / 128), 256, MM_SMEM>>>(
        xph, xpl, wh + OFF_CONV, wl + OFF_CONV, nullptr, nullptr,
        pe, nullptr, nullptr, NPROW, Dm, Dm);
    k_assemble<<<(NTOK * Dm + 255) / 256, 256>>>(pe, cls_emb, pos_emb, x);
    k_ln<false><<<NTOK, 256>>>(x, x, nullptr, nullptr, ln_pre_s, ln_pre_b, Dm, Dm);

    // ---- transformer layers ----
    for (int l = 0; l < Ll; l++) {
        const float* l1s = ln1_s + (size_t)l * Dm;
        const float* l1b = ln1_b + (size_t)l * Dm;
        const float* qb  = qkv_b + (size_t)l * 3 * Dm;
        const float* ob  = out_b + (size_t)l * Dm;
        const float* l2s = ln2_s + (size_t)l * Dm;
        const float* l2b = ln2_b + (size_t)l * Dm;
        const float* fb  = fc_b  + (size_t)l * Ff;
        const float* pb  = proj_b + (size_t)l * Dm;
        const __nv_bfloat16* qwh = wh + OFF_QKV  + (size_t)l * 2304 * 768;
        const __nv_bfloat16* qwl = wl + OFF_QKV  + (size_t)l * 2304 * 768;
        const __nv_bfloat16* owh = wh + OFF_OUT  + (size_t)l * 768 * 768;
        const __nv_bfloat16* owl = wl + OFF_OUT  + (size_t)l * 768 * 768;
        const __nv_bfloat16* fwh = wh + OFF_FC   + (size_t)l * 3072 * 768;
        const __nv_bfloat16* fwl = wl + OFF_FC   + (size_t)l * 3072 * 768;
        const __nv_bfloat16* pwh = wh + OFF_PROJ + (size_t)l * 768 * 3072;
        const __nv_bfloat16* pwl = wl + OFF_PROJ + (size_t)l * 768 * 3072;

        k_ln<true><<<NTOK, 256>>>(x, nullptr, hh, hl, l1s, l1b, Dm, Dm);
        k_mm<true,false,false,false><<<dim3(3 * Dm / 128, (NTOK + 127) / 128), 256, MM_SMEM>>>(
            hh, hl, qwh, qwl, qb, nullptr, qkv, nullptr, nullptr, NTOK, 3 * Dm, Dm);
        k_attn<<<Bsz * Hh, 256, attn_smem>>>(qkv, aoh, aol);
        k_mm<true,true,false,false><<<dim3(Dm / 128, (NTOK + 127) / 128), 256, MM_SMEM>>>(
            aoh, aol, owh, owl, ob, x, x, nullptr, nullptr, NTOK, Dm, Dm);
        k_ln<true><<<NTOK, 256>>>(x, nullptr, hh, hl, l2s, l2b, Dm, Dm);
        k_mm<true,false,true,true><<<dim3(Ff / 128, (NTOK + 127) / 128), 256, MM_SMEM>>>(
            hh, hl, fwh, fwl, fb, nullptr, nullptr, mlph, mlpl, NTOK, Ff, Dm);
        k_mm<true,true,false,false><<<dim3(Dm / 128, (NTOK + 127) / 128), 256, MM_SMEM>>>(
            mlph, mlpl, pwh, pwl, pb, x, x, nullptr, nullptr, NTOK, Dm, Ff);
    }

    // ---- head ----
    k_ln<false><<<Bsz, 256>>>(x, cls, nullptr, nullptr, lnp_s, lnp_b, (long)Ss * Dm, Dm);
    k_head<<<Bsz, 256>>>(cls, vis_proj, outp);
}

// round 4
// speedup vs baseline: 3.2713x; 1.0223x over previous
#include <cuda_runtime.h>
#include <cuda_bf16.h>
#include <math.h>
#include <cstdint>

// ---------------------------------------------------------------------------
// CLIP ViT-B/16 visual tower on GB300 — mma.sync bf16 split-precision GEMMs.
// Round 4: ldmatrix fragment loads + 3-stage cp.async pipeline.
// ---------------------------------------------------------------------------

#define Bsz 32
#define Dm  768
#define Hh  12
#define HD  64
#define Ff  3072
#define Ll  12
#define Ss  197
#define Oo  512
#define NPATCH 196
#define NTOK (Bsz * Ss)        // 6304
#define NPROW (Bsz * NPATCH)   // 6272

// ------------------------- helpers -----------------------------------------
__device__ __forceinline__ uint32_t smem_u32(const void* p) {
    uint32_t a;
    asm("{ .reg .u64 t; cvta.to.shared.u64 t, %1; cvt.u32.u64 %0, t; }"
        : "=r"(a) : "l"(p));
    return a;
}
__device__ __forceinline__ void cpa16(uint32_t dst, const void* src, uint32_t vsz) {
    asm volatile("cp.async.cg.shared.global [%0], [%1], 16, %2;"
                 :: "r"(dst), "l"(src), "r"(vsz) : "memory");
}
#define CP_COMMIT() asm volatile("cp.async.commit_group;" ::: "memory")
#define CP_WAIT0()  asm volatile("cp.async.wait_group 0;" ::: "memory")
#define CP_WAIT1()  asm volatile("cp.async.wait_group 1;" ::: "memory")

#define MMA16816(c, a0, a1, a2, a3, b0, b1) \
    asm volatile("mma.sync.aligned.m16n8k16.row.col.f32.bf16.bf16.f32 " \
        "{%0,%1,%2,%3}, {%4,%5,%6,%7}, {%8,%9}, {%0,%1,%2,%3};" \
        : "+f"((c)[0]), "+f"((c)[1]), "+f"((c)[2]), "+f"((c)[3]) \
        : "r"(a0), "r"(a1), "r"(a2), "r"(a3), "r"(b0), "r"(b1))

#define LDSM4(r0, r1, r2, r3, addr) \
    asm volatile("ldmatrix.sync.aligned.m8n8.x4.shared.b16 {%0,%1,%2,%3}, [%4];" \
        : "=r"(r0), "=r"(r1), "=r"(r2), "=r"(r3) : "r"(addr))

// ------------------------- scratch (static device globals) -----------------
#define OFF_CONV 0ul
#define OFF_QKV  589824ul
#define OFF_OUT  21823488ul
#define OFF_FC   28901376ul
#define OFF_PROJ 57212928ul
#define WTOT     85524480ul

__device__ __align__(16) __nv_bfloat16 g_wh[WTOT];
__device__ __align__(16) __nv_bfloat16 g_wl[WTOT];
__device__ __align__(16) __nv_bfloat16 g_xph[NPROW * Dm];
__device__ __align__(16) __nv_bfloat16 g_xpl[NPROW * Dm];
__device__ float g_pe[NPROW * Dm];
__device__ float g_x [NTOK * Dm];
__device__ __align__(16) __nv_bfloat16 g_hh[NTOK * Dm];
__device__ __align__(16) __nv_bfloat16 g_hl[NTOK * Dm];
__device__ float g_qkv[NTOK * 3 * Dm];
__device__ __align__(16) __nv_bfloat16 g_aoh[NTOK * Dm];
__device__ __align__(16) __nv_bfloat16 g_aol[NTOK * Dm];
__device__ __align__(16) __nv_bfloat16 g_mlph[NTOK * Ff];
__device__ __align__(16) __nv_bfloat16 g_mlpl[NTOK * Ff];
__device__ float g_cls[Bsz * Dm];

// ------------------------- weight fp32 -> bf16 hi/lo (vectorized) ----------
__global__ void k_cvt(const float4* __restrict__ src, __nv_bfloat162* __restrict__ hi,
                      __nv_bfloat162* __restrict__ lo, long n4)
{
    long i = (long)blockIdx.x * blockDim.x + threadIdx.x;
    if (i >= n4) return;
    float4 v = src[i];
    __nv_bfloat16 hx = __float2bfloat16(v.x), hy = __float2bfloat16(v.y);
    __nv_bfloat16 hz = __float2bfloat16(v.z), hw = __float2bfloat16(v.w);
    __nv_bfloat162 h0; h0.x = hx; h0.y = hy;
    __nv_bfloat162 h1; h1.x = hz; h1.y = hw;
    __nv_bfloat162 l0, l1;
    l0.x = __float2bfloat16(v.x - __bfloat162float(hx));
    l0.y = __float2bfloat16(v.y - __bfloat162float(hy));
    l1.x = __float2bfloat16(v.z - __bfloat162float(hz));
    l1.y = __float2bfloat16(v.w - __bfloat162float(hw));
    hi[2 * i] = h0; hi[2 * i + 1] = h1;
    lo[2 * i] = l0; lo[2 * i + 1] = l1;
}

// ------------------------- patchify + normalize -> hi/lo -------------------
__global__ void k_patchify(const float* __restrict__ img,
                           __nv_bfloat16* __restrict__ xh, __nv_bfloat16* __restrict__ xl)
{
    const float mean[3] = {0.48145466f, 0.4578275f, 0.40821073f};
    const float istd[3] = {1.f/0.26862954f, 1.f/0.26130258f, 1.f/0.27577711f};
    int idx = blockIdx.x * blockDim.x + threadIdx.x;
    if (idx >= NPROW * Dm) return;
    int col = idx % Dm;
    int row = idx / Dm;
    int b  = row / NPATCH;
    int p  = row % NPATCH;
    int py = p / 14, px = p % 14;
    int c  = col >> 8;
    int rem = col & 255;
    int ph = rem >> 4, pw = rem & 15;
    float v = img[(((size_t)b * 3 + c) * 224 + py * 16 + ph) * 224 + px * 16 + pw];
    v = (v - mean[c]) * istd[c];
    __nv_bfloat16 h = __float2bfloat16(v);
    xh[idx] = h;
    xl[idx] = __float2bfloat16(v - __bfloat162float(h));
}

// ------------------------- mma.sync split-bf16 GEMM ------------------------
// C[M,N] = A[M,K] @ W[N,K]^T (+bias)(+QuickGELU)(+res). N%128==0, K%64==0.
// Tile 128x128 per CTA, 8 warps (4x2), warp tile 32x64, K chunks of 64,
// 3-stage cp.async pipeline, ldmatrix fragment loads. Row stride 144 B.
#define STG_MAT   18432            // 128 rows * 144 B
#define STG_BYTES 73728            // 4 matrices (Ah, Al, Bh, Bl)
#define MM_SMEM   (3 * STG_BYTES)  // 221184

template<bool BIAS, bool RES, bool GELU_, bool BF16O>
__global__ __launch_bounds__(256) void k_mm(
    const __nv_bfloat16* __restrict__ Ah, const __nv_bfloat16* __restrict__ Al,
    const __nv_bfloat16* __restrict__ Bh, const __nv_bfloat16* __restrict__ Bl,
    const float* __restrict__ bias, const float* __restrict__ resi,
    float* __restrict__ C, __nv_bfloat16* __restrict__ Ch, __nv_bfloat16* __restrict__ Cl,
    int M, int N, int K)
{
    extern __shared__ char smc[];
    const uint32_t sb = smem_u32(smc);
    const int tid = threadIdx.x, lane = tid & 31, wid = tid >> 5;
    const int warp_m = wid & 3, warp_n = wid >> 2;
    const int bm = blockIdx.y * 128, bn = blockIdx.x * 128;
    const int Kd8 = K >> 3, nch = K >> 6;

    const uint4* A4[2] = {(const uint4*)Ah, (const uint4*)Al};
    const uint4* B4[2] = {(const uint4*)Bh, (const uint4*)Bl};

    float acc[2][8][4];
    #pragma unroll
    for (int a = 0; a < 2; a++)
        #pragma unroll
        for (int b = 0; b < 8; b++)
            #pragma unroll
            for (int c = 0; c < 4; c++) acc[a][b][c] = 0.f;

    auto load_chunk = [&](int i, int s) {
        int k0d8 = i << 3;
        uint32_t stg = sb + s * STG_BYTES;
        #pragma unroll
        for (int t = tid; t < 4096; t += 256) {
            int mat = t >> 10, r = (t >> 3) & 127, c8 = t & 7;
            uint32_t dst = stg + mat * STG_MAT + r * 144 + c8 * 16;
            if (mat < 2) {
                int grow = bm + r;
                int ok = grow < M;
                const uint4* src = A4[mat] + (size_t)(ok ? grow : 0) * Kd8 + k0d8 + c8;
                cpa16(dst, src, ok ? 16u : 0u);
            } else {
                const uint4* src = B4[mat - 2] + (size_t)(bn + r) * Kd8 + k0d8 + c8;
                cpa16(dst, src, 16u);
            }
        }
        CP_COMMIT();
    };

    load_chunk(0, 0);
    load_chunk(1, 1);

    // per-warp fragment base offsets (stage-relative)
    const uint32_t aoff = (uint32_t)((warp_m * 32 + (lane & 15)) * 144 + ((lane >> 4) << 4));
    const int brow = (lane & 7) + ((lane >> 4) << 3);
    const uint32_t boff = (uint32_t)(2 * STG_MAT + (warp_n * 64 + brow) * 144
                                     + (((lane >> 3) & 1) << 4));

    int s = 0;
    for (int i = 0; i < nch; i++) {
        if (i + 1 < nch) CP_WAIT1(); else CP_WAIT0();
        __syncthreads();
        if (i + 2 < nch) {
            int s2 = s + 2; if (s2 >= 3) s2 -= 3;
            load_chunk(i + 2, s2);
        }
        uint32_t stg = sb + s * STG_BYTES;
        uint32_t aH = stg + aoff, aL = aH + STG_MAT;
        uint32_t bH = stg + boff, bL = bH + STG_MAT;
        #pragma unroll
        for (int k16 = 0; k16 < 4; k16++) {
            uint32_t ah[2][4], al[2][4];
            #pragma unroll
            for (int mf = 0; mf < 2; mf++) {
                LDSM4(ah[mf][0], ah[mf][1], ah[mf][2], ah[mf][3],
                      aH + mf * (16 * 144) + k16 * 32);
                LDSM4(al[mf][0], al[mf][1], al[mf][2], al[mf][3],
                      aL + mf * (16 * 144) + k16 * 32);
            }
            #pragma unroll
            for (int p = 0; p < 4; p++) {
                uint32_t bh[4], bl[4];
                LDSM4(bh[0], bh[1], bh[2], bh[3], bH + p * (16 * 144) + k16 * 32);
                LDSM4(bl[0], bl[1], bl[2], bl[3], bL + p * (16 * 144) + k16 * 32);
                #pragma unroll
                for (int sub = 0; sub < 2; sub++) {
                    int nf = p * 2 + sub;
                    #pragma unroll
                    for (int mf = 0; mf < 2; mf++) {
                        MMA16816(acc[mf][nf], ah[mf][0], ah[mf][1], ah[mf][2], ah[mf][3],
                                 bh[2 * sub], bh[2 * sub + 1]);
                        MMA16816(acc[mf][nf], al[mf][0], al[mf][1], al[mf][2], al[mf][3],
                                 bh[2 * sub], bh[2 * sub + 1]);
                        MMA16816(acc[mf][nf], ah[mf][0], ah[mf][1], ah[mf][2], ah[mf][3],
                                 bl[2 * sub], bl[2 * sub + 1]);
                    }
                }
            }
        }
        s++; if (s == 3) s = 0;
    }

    // ---- epilogue ----
    const int qrow = lane >> 2;
    #pragma unroll
    for (int mf = 0; mf < 2; mf++) {
        #pragma unroll
        for (int nf = 0; nf < 8; nf++) {
            int rbase = bm + warp_m * 32 + mf * 16 + qrow;
            int cbase = bn + warp_n * 64 + nf * 8 + ((lane & 3) << 1);
            #pragma unroll
            for (int e = 0; e < 4; e++) {
                int row = rbase + ((e >> 1) << 3);
                int col = cbase + (e & 1);
                if (row >= M) continue;
                float v = acc[mf][nf][e];
                if (BIAS)  v += bias[col];
                if (GELU_) v = v / (1.f + __expf(-1.702f * v));
                if (RES)   v += resi[(size_t)row * N + col];
                if (BF16O) {
                    __nv_bfloat16 h = __float2bfloat16(v);
                    Ch[(size_t)row * N + col] = h;
                    Cl[(size_t)row * N + col] = __float2bfloat16(v - __bfloat162float(h));
                } else {
                    C[(size_t)row * N + col] = v;
                }
            }
        }
    }
}

// ------------------------- assemble tokens ---------------------------------
__global__ void k_assemble(const float* __restrict__ pe, const float* __restrict__ cls,
                           const float* __restrict__ pos, float* __restrict__ x)
{
    int idx = blockIdx.x * blockDim.x + threadIdx.x;
    if (idx >= NTOK * Dm) return;
    int d = idx % Dm;
    int t = idx / Dm;
    int s = t % Ss, b = t / Ss;
    float v = (s == 0) ? cls[d] : pe[((size_t)b * NPATCH + (s - 1)) * Dm + d];
    x[idx] = v + pos[(size_t)s * Dm + d];
}

// ------------------------- LayerNorm (fp32 out / hi-lo out) ----------------
template<bool HL>
__global__ void k_ln(const float* __restrict__ in, float* __restrict__ outf,
                     __nv_bfloat16* __restrict__ oh, __nv_bfloat16* __restrict__ ol,
                     const float* __restrict__ sc, const float* __restrict__ bi,
                     long in_stride, long out_stride)
{
    __shared__ float red[2][32];
    long row = blockIdx.x;
    const float* ip = in + row * in_stride;
    int tid = threadIdx.x;
    float v[3];
    float s = 0.f, sq = 0.f;
    #pragma unroll
    for (int i = 0; i < 3; i++) {
        v[i] = ip[tid + i * 256];
        s += v[i]; sq += v[i] * v[i];
    }
    #pragma unroll
    for (int o = 16; o > 0; o >>= 1) {
        s  += __shfl_xor_sync(~0u, s, o);
        sq += __shfl_xor_sync(~0u, sq, o);
    }
    int lane = tid & 31, w = tid >> 5;
    if (lane == 0) { red[0][w] = s; red[1][w] = sq; }
    __syncthreads();
    if (w == 0) {
        float a = (lane < 8) ? red[0][lane] : 0.f;
        float b = (lane < 8) ? red[1][lane] : 0.f;
        #pragma unroll
        for (int o = 4; o > 0; o >>= 1) {
            a += __shfl_xor_sync(~0u, a, o);
            b += __shfl_xor_sync(~0u, b, o);
        }
        if (lane == 0) { red[0][0] = a; red[1][0] = b; }
    }
    __syncthreads();
    float mean = red[0][0] * (1.f / Dm);
    float var  = red[1][0] * (1.f / Dm) - mean * mean;
    float r = rsqrtf(var + 1e-5f);
    #pragma unroll
    for (int i = 0; i < 3; i++) {
        int d = tid + i * 256;
        float y = (v[i] - mean) * r * sc[d] + bi[d];
        if (HL) {
            __nv_bfloat16 h = __float2bfloat16(y);
            oh[row * out_stride + d] = h;
            ol[row * out_stride + d] = __float2bfloat16(y - __bfloat162float(h));
        } else {
            outf[row * out_stride + d] = y;
        }
    }
}

// ------------------------- fused attention ---------------------------------
__global__ __launch_bounds__(256) void k_attn(const float* __restrict__ QKV,
                                              __nv_bfloat16* __restrict__ oh,
                                              __nv_bfloat16* __restrict__ ol)
{
    extern __shared__ float sm[];
    float* Ks = sm;                       // 197*65
    float* Vs = Ks + Ss * 65;             // 197*65
    float* Qs = Vs + Ss * 65;             // 8*64
    float* Ps = Qs + 8 * 64;              // 8*200
    int bh = blockIdx.x;
    int b = bh / Hh, h = bh % Hh;
    int tid = threadIdx.x, lane = tid & 31, w = tid >> 5;
    const size_t base = (size_t)b * Ss * (3 * Dm) + (size_t)h * HD;

    for (int idx = tid; idx < Ss * HD; idx += 256) {
        int s = idx >> 6, d = idx & 63;
        Ks[s * 65 + d] = QKV[base + (size_t)s * (3 * Dm) + Dm + d];
        Vs[s * 65 + d] = QKV[base + (size_t)s * (3 * Dm) + 2 * Dm + d];
    }
    __syncthreads();

    for (int q = w; q < Ss; q += 8) {
        Qs[w * 64 + lane]      = QKV[base + (size_t)q * (3 * Dm) + lane] * 0.125f;
        Qs[w * 64 + lane + 32] = QKV[base + (size_t)q * (3 * Dm) + lane + 32] * 0.125f;
        __syncwarp();
        float mx = -1e30f;
        for (int k = lane; k < Ss; k += 32) {
            float s = 0.f;
            #pragma unroll
            for (int d = 0; d < HD; d++) s += Qs[w * 64 + d] * Ks[k * 65 + d];
            Ps[w * 200 + k] = s;
            mx = fmaxf(mx, s);
        }
        #pragma unroll
        for (int o = 16; o > 0; o >>= 1) mx = fmaxf(mx, __shfl_xor_sync(~0u, mx, o));
        float sum = 0.f;
        for (int k = lane; k < Ss; k += 32) {
            float p = __expf(Ps[w * 200 + k] - mx);
            Ps[w * 200 + k] = p;
            sum += p;
        }
        #pragma unroll
        for (int o = 16; o > 0; o >>= 1) sum += __shfl_xor_sync(~0u, sum, o);
        float inv = 1.f / sum;
        __syncwarp();
        float o0 = 0.f, o1 = 0.f;
        #pragma unroll 4
        for (int k = 0; k < Ss; k++) {
            float p = Ps[w * 200 + k];
            o0 += p * Vs[k * 65 + lane];
            o1 += p * Vs[k * 65 + lane + 32];
        }
        o0 *= inv; o1 *= inv;
        size_t orow = ((size_t)b * Ss + q) * Dm + h * HD;
        __nv_bfloat16 h0 = __float2bfloat16(o0);
        __nv_bfloat16 h1 = __float2bfloat16(o1);
        oh[orow + lane]      = h0;
        ol[orow + lane]      = __float2bfloat16(o0 - __bfloat162float(h0));
        oh[orow + lane + 32] = h1;
        ol[orow + lane + 32] = __float2bfloat16(o1 - __bfloat162float(h1));
        __syncwarp();
    }
}

// ------------------------- head: cls_ln @ vis_proj -------------------------
__global__ void k_head(const float* __restrict__ cls, const float* __restrict__ Wp,
                       float* __restrict__ out)
{
    __shared__ float row[Dm];
    int b = blockIdx.x;
    for (int i = threadIdx.x; i < Dm; i += 256) row[i] = cls[(size_t)b * Dm + i];
    __syncthreads();
    for (int o = threadIdx.x; o < Oo; o += 256) {
        float acc = 0.f;
        for (int d = 0; d < Dm; d++) acc += row[d] * Wp[(size_t)d * Oo + o];
        out[(size_t)b * Oo + o] = acc;
    }
}

// ---------------------------------------------------------------------------
extern "C" void kernel_launch(void* const* d_in, const int* in_sizes, int n_in,
                              void* d_out, int out_size)
{
    const float* images   = (const float*)d_in[0];
    const float* conv_w   = (const float*)d_in[1];
    const float* cls_emb  = (const float*)d_in[2];
    const float* pos_emb  = (const float*)d_in[3];
    const float* ln_pre_s = (const float*)d_in[4];
    const float* ln_pre_b = (const float*)d_in[5];
    const float* ln1_s    = (const float*)d_in[6];
    const float* ln1_b    = (const float*)d_in[7];
    const float* qkv_w    = (const float*)d_in[8];
    const float* qkv_b    = (const float*)d_in[9];
    const float* out_w    = (const float*)d_in[10];
    const float* out_b    = (const float*)d_in[11];
    const float* ln2_s    = (const float*)d_in[12];
    const float* ln2_b    = (const float*)d_in[13];
    const float* fc_w     = (const float*)d_in[14];
    const float* fc_b     = (const float*)d_in[15];
    const float* proj_w   = (const float*)d_in[16];
    const float* proj_b   = (const float*)d_in[17];
    const float* lnp_s    = (const float*)d_in[18];
    const float* lnp_b    = (const float*)d_in[19];
    const float* vis_proj = (const float*)d_in[20];
    float* outp = (float*)d_out;

    __nv_bfloat16 *wh, *wl, *xph, *xpl, *hh, *hl, *aoh, *aol, *mlph, *mlpl;
    float *pe, *x, *qkv, *cls;
    cudaGetSymbolAddress((void**)&wh,   g_wh);
    cudaGetSymbolAddress((void**)&wl,   g_wl);
    cudaGetSymbolAddress((void**)&xph,  g_xph);
    cudaGetSymbolAddress((void**)&xpl,  g_xpl);
    cudaGetSymbolAddress((void**)&pe,   g_pe);
    cudaGetSymbolAddress((void**)&x,    g_x);
    cudaGetSymbolAddress((void**)&hh,   g_hh);
    cudaGetSymbolAddress((void**)&hl,   g_hl);
    cudaGetSymbolAddress((void**)&qkv,  g_qkv);
    cudaGetSymbolAddress((void**)&aoh,  g_aoh);
    cudaGetSymbolAddress((void**)&aol,  g_aol);
    cudaGetSymbolAddress((void**)&mlph, g_mlph);
    cudaGetSymbolAddress((void**)&mlpl, g_mlpl);
    cudaGetSymbolAddress((void**)&cls,  g_cls);

    cudaFuncSetAttribute(k_mm<false,false,false,false>, cudaFuncAttributeMaxDynamicSharedMemorySize, MM_SMEM);
    cudaFuncSetAttribute(k_mm<true, false,false,false>, cudaFuncAttributeMaxDynamicSharedMemorySize, MM_SMEM);
    cudaFuncSetAttribute(k_mm<true, true, false,false>, cudaFuncAttributeMaxDynamicSharedMemorySize, MM_SMEM);
    cudaFuncSetAttribute(k_mm<true, false,true, true >, cudaFuncAttributeMaxDynamicSharedMemorySize, MM_SMEM);
    int attn_smem = (2 * Ss * 65 + 8 * 64 + 8 * 200) * sizeof(float);
    cudaFuncSetAttribute(k_attn, cudaFuncAttributeMaxDynamicSharedMemorySize, attn_smem);

    // ---- weight fp32 -> bf16 hi/lo ----
    {
        long n4;
        n4 = 589824 / 4;
        k_cvt<<<(n4 + 255) / 256, 256>>>((const float4*)conv_w,
            (__nv_bfloat162*)(wh + OFF_CONV), (__nv_bfloat162*)(wl + OFF_CONV), n4);
        n4 = 21233664 / 4;
        k_cvt<<<(n4 + 255) / 256, 256>>>((const float4*)qkv_w,
            (__nv_bfloat162*)(wh + OFF_QKV), (__nv_bfloat162*)(wl + OFF_QKV), n4);
        n4 = 7077888 / 4;
        k_cvt<<<(n4 + 255) / 256, 256>>>((const float4*)out_w,
            (__nv_bfloat162*)(wh + OFF_OUT), (__nv_bfloat162*)(wl + OFF_OUT), n4);
        n4 = 28311552 / 4;
        k_cvt<<<(n4 + 255) / 256, 256>>>((const float4*)fc_w,
            (__nv_bfloat162*)(wh + OFF_FC), (__nv_bfloat162*)(wl + OFF_FC), n4);
        n4 = 28311552 / 4;
        k_cvt<<<(n4 + 255) / 256, 256>>>((const float4*)proj_w,
            (__nv_bfloat162*)(wh + OFF_PROJ), (__nv_bfloat162*)(wl + OFF_PROJ), n4);
    }

    // ---- stem ----
    k_patchify<<<(NPROW * Dm + 255) / 256, 256>>>(images, xph, xpl);
    k_mm<false,false,false,false><<<dim3(Dm / 128, (NPROW + 127) / 128), 256, MM_SMEM>>>(
        xph, xpl, wh + OFF_CONV, wl + OFF_CONV, nullptr, nullptr,
        pe, nullptr, nullptr, NPROW, Dm, Dm);
    k_assemble<<<(NTOK * Dm + 255) / 256, 256>>>(pe, cls_emb, pos_emb, x);
    k_ln<false><<<NTOK, 256>>>(x, x, nullptr, nullptr, ln_pre_s, ln_pre_b, Dm, Dm);

    // ---- transformer layers ----
    for (int l = 0; l < Ll; l++) {
        const float* l1s = ln1_s + (size_t)l * Dm;
        const float* l1b = ln1_b + (size_t)l * Dm;
        const float* qb  = qkv_b + (size_t)l * 3 * Dm;
        const float* ob  = out_b + (size_t)l * Dm;
        const float* l2s = ln2_s + (size_t)l * Dm;
        const float* l2b = ln2_b + (size_t)l * Dm;
        const float* fb  = fc_b  + (size_t)l * Ff;
        const float* pb  = proj_b + (size_t)l * Dm;
        const __nv_bfloat16* qwh = wh + OFF_QKV  + (size_t)l * 2304 * 768;
        const __nv_bfloat16* qwl = wl + OFF_QKV  + (size_t)l * 2304 * 768;
        const __nv_bfloat16* owh = wh + OFF_OUT  + (size_t)l * 768 * 768;
        const __nv_bfloat16* owl = wl + OFF_OUT  + (size_t)l * 768 * 768;
        const __nv_bfloat16* fwh = wh + OFF_FC   + (size_t)l * 3072 * 768;
        const __nv_bfloat16* fwl = wl + OFF_FC   + (size_t)l * 3072 * 768;
        const __nv_bfloat16* pwh = wh + OFF_PROJ + (size_t)l * 768 * 3072;
        const __nv_bfloat16* pwl = wl + OFF_PROJ + (size_t)l * 768 * 3072;

        k_ln<true><<<NTOK, 256>>>(x, nullptr, hh, hl, l1s, l1b, Dm, Dm);
        k_mm<true,false,false,false><<<dim3(3 * Dm / 128, (NTOK + 127) / 128), 256, MM_SMEM>>>(
            hh, hl, qwh, qwl, qb, nullptr, qkv, nullptr, nullptr, NTOK, 3 * Dm, Dm);
        k_attn<<<Bsz * Hh, 256, attn_smem>>>(qkv, aoh, aol);
        k_mm<true,true,false,false><<<dim3(Dm / 128, (NTOK + 127) / 128), 256, MM_SMEM>>>(
            aoh, aol, owh, owl, ob, x, x, nullptr, nullptr, NTOK, Dm, Dm);
        k_ln<true><<<NTOK, 256>>>(x, nullptr, hh, hl, l2s, l2b, Dm, Dm);
        k_mm<true,false,true,true><<<dim3(Ff / 128, (NTOK + 127) / 128), 256, MM_SMEM>>>(
            hh, hl, fwh, fwl, fb, nullptr, nullptr, mlph, mlpl, NTOK, Ff, Dm);
        k_mm<true,true,false,false><<<dim3(Dm / 128, (NTOK + 127) / 128), 256, MM_SMEM>>>(
            mlph, mlpl, pwh, pwl, pb, x, x, nullptr, nullptr, NTOK, Dm, Ff);
    }

    // ---- head ----
    k_ln<false><<<Bsz, 256>>>(x, cls, nullptr, nullptr, lnp_s, lnp_b, (long)Ss * Dm, Dm);
    k_head<<<Bsz, 256>>>(cls, vis_proj, outp);
}

// round 5
// speedup vs baseline: 3.3037x; 1.0099x over previous
#include <cuda_runtime.h>
#include <cuda_bf16.h>
#include <math.h>
#include <cstdint>

// ---------------------------------------------------------------------------
// CLIP ViT-B/16 visual tower on GB300 — mma.sync bf16 split-precision GEMMs.
// Round 5: term-major MMA ordering (16-deep accumulator RAW distance).
// ---------------------------------------------------------------------------

#define Bsz 32
#define Dm  768
#define Hh  12
#define HD  64
#define Ff  3072
#define Ll  12
#define Ss  197
#define Oo  512
#define NPATCH 196
#define NTOK (Bsz * Ss)        // 6304
#define NPROW (Bsz * NPATCH)   // 6272

// ------------------------- helpers -----------------------------------------
__device__ __forceinline__ uint32_t smem_u32(const void* p) {
    uint32_t a;
    asm("{ .reg .u64 t; cvta.to.shared.u64 t, %1; cvt.u32.u64 %0, t; }"
        : "=r"(a) : "l"(p));
    return a;
}
__device__ __forceinline__ void cpa16(uint32_t dst, const void* src, uint32_t vsz) {
    asm volatile("cp.async.cg.shared.global [%0], [%1], 16, %2;"
                 :: "r"(dst), "l"(src), "r"(vsz) : "memory");
}
#define CP_COMMIT() asm volatile("cp.async.commit_group;" ::: "memory")
#define CP_WAIT0()  asm volatile("cp.async.wait_group 0;" ::: "memory")
#define CP_WAIT1()  asm volatile("cp.async.wait_group 1;" ::: "memory")

#define MMA16816(c, a0, a1, a2, a3, b0, b1) \
    asm volatile("mma.sync.aligned.m16n8k16.row.col.f32.bf16.bf16.f32 " \
        "{%0,%1,%2,%3}, {%4,%5,%6,%7}, {%8,%9}, {%0,%1,%2,%3};" \
        : "+f"((c)[0]), "+f"((c)[1]), "+f"((c)[2]), "+f"((c)[3]) \
        : "r"(a0), "r"(a1), "r"(a2), "r"(a3), "r"(b0), "r"(b1))

#define LDSM4(r0, r1, r2, r3, addr) \
    asm volatile("ldmatrix.sync.aligned.m8n8.x4.shared.b16 {%0,%1,%2,%3}, [%4];" \
        : "=r"(r0), "=r"(r1), "=r"(r2), "=r"(r3) : "r"(addr))

// ------------------------- scratch (static device globals) -----------------
#define OFF_CONV 0ul
#define OFF_QKV  589824ul
#define OFF_OUT  21823488ul
#define OFF_FC   28901376ul
#define OFF_PROJ 57212928ul
#define WTOT     85524480ul

__device__ __align__(16) __nv_bfloat16 g_wh[WTOT];
__device__ __align__(16) __nv_bfloat16 g_wl[WTOT];
__device__ __align__(16) __nv_bfloat16 g_xph[NPROW * Dm];
__device__ __align__(16) __nv_bfloat16 g_xpl[NPROW * Dm];
__device__ float g_pe[NPROW * Dm];
__device__ float g_x [NTOK * Dm];
__device__ __align__(16) __nv_bfloat16 g_hh[NTOK * Dm];
__device__ __align__(16) __nv_bfloat16 g_hl[NTOK * Dm];
__device__ float g_qkv[NTOK * 3 * Dm];
__device__ __align__(16) __nv_bfloat16 g_aoh[NTOK * Dm];
__device__ __align__(16) __nv_bfloat16 g_aol[NTOK * Dm];
__device__ __align__(16) __nv_bfloat16 g_mlph[NTOK * Ff];
__device__ __align__(16) __nv_bfloat16 g_mlpl[NTOK * Ff];
__device__ float g_cls[Bsz * Dm];

// ------------------------- weight fp32 -> bf16 hi/lo (vectorized) ----------
__global__ void k_cvt(const float4* __restrict__ src, __nv_bfloat162* __restrict__ hi,
                      __nv_bfloat162* __restrict__ lo, long n4)
{
    long i = (long)blockIdx.x * blockDim.x + threadIdx.x;
    if (i >= n4) return;
    float4 v = src[i];
    __nv_bfloat16 hx = __float2bfloat16(v.x), hy = __float2bfloat16(v.y);
    __nv_bfloat16 hz = __float2bfloat16(v.z), hw = __float2bfloat16(v.w);
    __nv_bfloat162 h0; h0.x = hx; h0.y = hy;
    __nv_bfloat162 h1; h1.x = hz; h1.y = hw;
    __nv_bfloat162 l0, l1;
    l0.x = __float2bfloat16(v.x - __bfloat162float(hx));
    l0.y = __float2bfloat16(v.y - __bfloat162float(hy));
    l1.x = __float2bfloat16(v.z - __bfloat162float(hz));
    l1.y = __float2bfloat16(v.w - __bfloat162float(hw));
    hi[2 * i] = h0; hi[2 * i + 1] = h1;
    lo[2 * i] = l0; lo[2 * i + 1] = l1;
}

// ------------------------- patchify + normalize -> hi/lo -------------------
__global__ void k_patchify(const float* __restrict__ img,
                           __nv_bfloat16* __restrict__ xh, __nv_bfloat16* __restrict__ xl)
{
    const float mean[3] = {0.48145466f, 0.4578275f, 0.40821073f};
    const float istd[3] = {1.f/0.26862954f, 1.f/0.26130258f, 1.f/0.27577711f};
    int idx = blockIdx.x * blockDim.x + threadIdx.x;
    if (idx >= NPROW * Dm) return;
    int col = idx % Dm;
    int row = idx / Dm;
    int b  = row / NPATCH;
    int p  = row % NPATCH;
    int py = p / 14, px = p % 14;
    int c  = col >> 8;
    int rem = col & 255;
    int ph = rem >> 4, pw = rem & 15;
    float v = img[(((size_t)b * 3 + c) * 224 + py * 16 + ph) * 224 + px * 16 + pw];
    v = (v - mean[c]) * istd[c];
    __nv_bfloat16 h = __float2bfloat16(v);
    xh[idx] = h;
    xl[idx] = __float2bfloat16(v - __bfloat162float(h));
}

// ------------------------- mma.sync split-bf16 GEMM ------------------------
// C[M,N] = A[M,K] @ W[N,K]^T (+bias)(+QuickGELU)(+res). N%128==0, K%64==0.
// Tile 128x128 per CTA, 8 warps (4x2), warp tile 32x64, K chunks of 64,
// 3-stage cp.async pipeline, ldmatrix loads, term-major MMA ordering.
#define STG_MAT   18432            // 128 rows * 144 B
#define STG_BYTES 73728            // 4 matrices (Ah, Al, Bh, Bl)
#define MM_SMEM   (3 * STG_BYTES)  // 221184

template<bool BIAS, bool RES, bool GELU_, bool BF16O>
__global__ __launch_bounds__(256) void k_mm(
    const __nv_bfloat16* __restrict__ Ah, const __nv_bfloat16* __restrict__ Al,
    const __nv_bfloat16* __restrict__ Bh, const __nv_bfloat16* __restrict__ Bl,
    const float* __restrict__ bias, const float* __restrict__ resi,
    float* __restrict__ C, __nv_bfloat16* __restrict__ Ch, __nv_bfloat16* __restrict__ Cl,
    int M, int N, int K)
{
    extern __shared__ char smc[];
    const uint32_t sb = smem_u32(smc);
    const int tid = threadIdx.x, lane = tid & 31, wid = tid >> 5;
    const int warp_m = wid & 3, warp_n = wid >> 2;
    const int bm = blockIdx.y * 128, bn = blockIdx.x * 128;
    const int Kd8 = K >> 3, nch = K >> 6;

    const uint4* A4[2] = {(const uint4*)Ah, (const uint4*)Al};
    const uint4* B4[2] = {(const uint4*)Bh, (const uint4*)Bl};

    float acc[2][8][4];
    #pragma unroll
    for (int a = 0; a < 2; a++)
        #pragma unroll
        for (int b = 0; b < 8; b++)
            #pragma unroll
            for (int c = 0; c < 4; c++) acc[a][b][c] = 0.f;

    auto load_chunk = [&](int i, int s) {
        int k0d8 = i << 3;
        uint32_t stg = sb + s * STG_BYTES;
        #pragma unroll
        for (int t = tid; t < 4096; t += 256) {
            int mat = t >> 10, r = (t >> 3) & 127, c8 = t & 7;
            uint32_t dst = stg + mat * STG_MAT + r * 144 + c8 * 16;
            if (mat < 2) {
                int grow = bm + r;
                int ok = grow < M;
                const uint4* src = A4[mat] + (size_t)(ok ? grow : 0) * Kd8 + k0d8 + c8;
                cpa16(dst, src, ok ? 16u : 0u);
            } else {
                const uint4* src = B4[mat - 2] + (size_t)(bn + r) * Kd8 + k0d8 + c8;
                cpa16(dst, src, 16u);
            }
        }
        CP_COMMIT();
    };

    load_chunk(0, 0);
    load_chunk(1, 1);

    // per-warp fragment base offsets (stage-relative)
    const uint32_t aoff = (uint32_t)((warp_m * 32 + (lane & 15)) * 144 + ((lane >> 4) << 4));
    const int brow = (lane & 7) + ((lane >> 4) << 3);
    const uint32_t boff = (uint32_t)(2 * STG_MAT + (warp_n * 64 + brow) * 144
                                     + (((lane >> 3) & 1) << 4));

    int s = 0;
    for (int i = 0; i < nch; i++) {
        if (i + 1 < nch) CP_WAIT1(); else CP_WAIT0();
        __syncthreads();
        if (i + 2 < nch) {
            int s2 = s + 2; if (s2 >= 3) s2 -= 3;
            load_chunk(i + 2, s2);
        }
        uint32_t stg = sb + s * STG_BYTES;
        uint32_t aH = stg + aoff, aL = aH + STG_MAT;
        uint32_t bH = stg + boff, bL = bH + STG_MAT;
        #pragma unroll
        for (int k16 = 0; k16 < 4; k16++) {
            uint32_t ah[2][4], al[2][4], bh[4][4], bl[4][4];
            #pragma unroll
            for (int mf = 0; mf < 2; mf++) {
                LDSM4(ah[mf][0], ah[mf][1], ah[mf][2], ah[mf][3],
                      aH + mf * (16 * 144) + k16 * 32);
                LDSM4(al[mf][0], al[mf][1], al[mf][2], al[mf][3],
                      aL + mf * (16 * 144) + k16 * 32);
            }
            #pragma unroll
            for (int p = 0; p < 4; p++) {
                LDSM4(bh[p][0], bh[p][1], bh[p][2], bh[p][3],
                      bH + p * (16 * 144) + k16 * 32);
                LDSM4(bl[p][0], bl[p][1], bl[p][2], bl[p][3],
                      bL + p * (16 * 144) + k16 * 32);
            }
            // term 1: Ah * Bh  (16 independent accumulators)
            #pragma unroll
            for (int p = 0; p < 4; p++)
                #pragma unroll
                for (int sub = 0; sub < 2; sub++)
                    #pragma unroll
                    for (int mf = 0; mf < 2; mf++)
                        MMA16816(acc[mf][p * 2 + sub],
                                 ah[mf][0], ah[mf][1], ah[mf][2], ah[mf][3],
                                 bh[p][2 * sub], bh[p][2 * sub + 1]);
            // term 2: Al * Bh
            #pragma unroll
            for (int p = 0; p < 4; p++)
                #pragma unroll
                for (int sub = 0; sub < 2; sub++)
                    #pragma unroll
                    for (int mf = 0; mf < 2; mf++)
                        MMA16816(acc[mf][p * 2 + sub],
                                 al[mf][0], al[mf][1], al[mf][2], al[mf][3],
                                 bh[p][2 * sub], bh[p][2 * sub + 1]);
            // term 3: Ah * Bl
            #pragma unroll
            for (int p = 0; p < 4; p++)
                #pragma unroll
                for (int sub = 0; sub < 2; sub++)
                    #pragma unroll
                    for (int mf = 0; mf < 2; mf++)
                        MMA16816(acc[mf][p * 2 + sub],
                                 ah[mf][0], ah[mf][1], ah[mf][2], ah[mf][3],
                                 bl[p][2 * sub], bl[p][2 * sub + 1]);
        }
        s++; if (s == 3) s = 0;
    }

    // ---- epilogue ----
    const int qrow = lane >> 2;
    #pragma unroll
    for (int mf = 0; mf < 2; mf++) {
        #pragma unroll
        for (int nf = 0; nf < 8; nf++) {
            int rbase = bm + warp_m * 32 + mf * 16 + qrow;
            int cbase = bn + warp_n * 64 + nf * 8 + ((lane & 3) << 1);
            #pragma unroll
            for (int e = 0; e < 4; e++) {
                int row = rbase + ((e >> 1) << 3);
                int col = cbase + (e & 1);
                if (row >= M) continue;
                float v = acc[mf][nf][e];
                if (BIAS)  v += bias[col];
                if (GELU_) v = v / (1.f + __expf(-1.702f * v));
                if (RES)   v += resi[(size_t)row * N + col];
                if (BF16O) {
                    __nv_bfloat16 h = __float2bfloat16(v);
                    Ch[(size_t)row * N + col] = h;
                    Cl[(size_t)row * N + col] = __float2bfloat16(v - __bfloat162float(h));
                } else {
                    C[(size_t)row * N + col] = v;
                }
            }
        }
    }
}

// ------------------------- assemble tokens ---------------------------------
__global__ void k_assemble(const float* __restrict__ pe, const float* __restrict__ cls,
                           const float* __restrict__ pos, float* __restrict__ x)
{
    int idx = blockIdx.x * blockDim.x + threadIdx.x;
    if (idx >= NTOK * Dm) return;
    int d = idx % Dm;
    int t = idx / Dm;
    int s = t % Ss, b = t / Ss;
    float v = (s == 0) ? cls[d] : pe[((size_t)b * NPATCH + (s - 1)) * Dm + d];
    x[idx] = v + pos[(size_t)s * Dm + d];
}

// ------------------------- LayerNorm (fp32 out / hi-lo out) ----------------
template<bool HL>
__global__ void k_ln(const float* __restrict__ in, float* __restrict__ outf,
                     __nv_bfloat16* __restrict__ oh, __nv_bfloat16* __restrict__ ol,
                     const float* __restrict__ sc, const float* __restrict__ bi,
                     long in_stride, long out_stride)
{
    __shared__ float red[2][32];
    long row = blockIdx.x;
    const float* ip = in + row * in_stride;
    int tid = threadIdx.x;
    float v[3];
    float s = 0.f, sq = 0.f;
    #pragma unroll
    for (int i = 0; i < 3; i++) {
        v[i] = ip[tid + i * 256];
        s += v[i]; sq += v[i] * v[i];
    }
    #pragma unroll
    for (int o = 16; o > 0; o >>= 1) {
        s  += __shfl_xor_sync(~0u, s, o);
        sq += __shfl_xor_sync(~0u, sq, o);
    }
    int lane = tid & 31, w = tid >> 5;
    if (lane == 0) { red[0][w] = s; red[1][w] = sq; }
    __syncthreads();
    if (w == 0) {
        float a = (lane < 8) ? red[0][lane] : 0.f;
        float b = (lane < 8) ? red[1][lane] : 0.f;
        #pragma unroll
        for (int o = 4; o > 0; o >>= 1) {
            a += __shfl_xor_sync(~0u, a, o);
            b += __shfl_xor_sync(~0u, b, o);
        }
        if (lane == 0) { red[0][0] = a; red[1][0] = b; }
    }
    __syncthreads();
    float mean = red[0][0] * (1.f / Dm);
    float var  = red[1][0] * (1.f / Dm) - mean * mean;
    float r = rsqrtf(var + 1e-5f);
    #pragma unroll
    for (int i = 0; i < 3; i++) {
        int d = tid + i * 256;
        float y = (v[i] - mean) * r * sc[d] + bi[d];
        if (HL) {
            __nv_bfloat16 h = __float2bfloat16(y);
            oh[row * out_stride + d] = h;
            ol[row * out_stride + d] = __float2bfloat16(y - __bfloat162float(h));
        } else {
            outf[row * out_stride + d] = y;
        }
    }
}

// ------------------------- fused attention ---------------------------------
__global__ __launch_bounds__(256) void k_attn(const float* __restrict__ QKV,
                                              __nv_bfloat16* __restrict__ oh,
                                              __nv_bfloat16* __restrict__ ol)
{
    extern __shared__ float sm[];
    float* Ks = sm;                       // 197*65
    float* Vs = Ks + Ss * 65;             // 197*65
    float* Qs = Vs + Ss * 65;             // 8*64
    float* Ps = Qs + 8 * 64;              // 8*200
    int bh = blockIdx.x;
    int b = bh / Hh, h = bh % Hh;
    int tid = threadIdx.x, lane = tid & 31, w = tid >> 5;
    const size_t base = (size_t)b * Ss * (3 * Dm) + (size_t)h * HD;

    for (int idx = tid; idx < Ss * HD; idx += 256) {
        int s = idx >> 6, d = idx & 63;
        Ks[s * 65 + d] = QKV[base + (size_t)s * (3 * Dm) + Dm + d];
        Vs[s * 65 + d] = QKV[base + (size_t)s * (3 * Dm) + 2 * Dm + d];
    }
    __syncthreads();

    for (int q = w; q < Ss; q += 8) {
        Qs[w * 64 + lane]      = QKV[base + (size_t)q * (3 * Dm) + lane] * 0.125f;
        Qs[w * 64 + lane + 32] = QKV[base + (size_t)q * (3 * Dm) + lane + 32] * 0.125f;
        __syncwarp();
        float mx = -1e30f;
        for (int k = lane; k < Ss; k += 32) {
            float s = 0.f;
            #pragma unroll
            for (int d = 0; d < HD; d++) s += Qs[w * 64 + d] * Ks[k * 65 + d];
            Ps[w * 200 + k] = s;
            mx = fmaxf(mx, s);
        }
        #pragma unroll
        for (int o = 16; o > 0; o >>= 1) mx = fmaxf(mx, __shfl_xor_sync(~0u, mx, o));
        float sum = 0.f;
        for (int k = lane; k < Ss; k += 32) {
            float p = __expf(Ps[w * 200 + k] - mx);
            Ps[w * 200 + k] = p;
            sum += p;
        }
        #pragma unroll
        for (int o = 16; o > 0; o >>= 1) sum += __shfl_xor_sync(~0u, sum, o);
        float inv = 1.f / sum;
        __syncwarp();
        float o0 = 0.f, o1 = 0.f;
        #pragma unroll 4
        for (int k = 0; k < Ss; k++) {
            float p = Ps[w * 200 + k];
            o0 += p * Vs[k * 65 + lane];
            o1 += p * Vs[k * 65 + lane + 32];
        }
        o0 *= inv; o1 *= inv;
        size_t orow = ((size_t)b * Ss + q) * Dm + h * HD;
        __nv_bfloat16 h0 = __float2bfloat16(o0);
        __nv_bfloat16 h1 = __float2bfloat16(o1);
        oh[orow + lane]      = h0;
        ol[orow + lane]      = __float2bfloat16(o0 - __bfloat162float(h0));
        oh[orow + lane + 32] = h1;
        ol[orow + lane + 32] = __float2bfloat16(o1 - __bfloat162float(h1));
        __syncwarp();
    }
}

// ------------------------- head: cls_ln @ vis_proj -------------------------
__global__ void k_head(const float* __restrict__ cls, const float* __restrict__ Wp,
                       float* __restrict__ out)
{
    __shared__ float row[Dm];
    int b = blockIdx.x;
    for (int i = threadIdx.x; i < Dm; i += 256) row[i] = cls[(size_t)b * Dm + i];
    __syncthreads();
    for (int o = threadIdx.x; o < Oo; o += 256) {
        float acc = 0.f;
        for (int d = 0; d < Dm; d++) acc += row[d] * Wp[(size_t)d * Oo + o];
        out[(size_t)b * Oo + o] = acc;
    }
}

// ---------------------------------------------------------------------------
extern "C" void kernel_launch(void* const* d_in, const int* in_sizes, int n_in,
                              void* d_out, int out_size)
{
    const float* images   = (const float*)d_in[0];
    const float* conv_w   = (const float*)d_in[1];
    const float* cls_emb  = (const float*)d_in[2];
    const float* pos_emb  = (const float*)d_in[3];
    const float* ln_pre_s = (const float*)d_in[4];
    const float* ln_pre_b = (const float*)d_in[5];
    const float* ln1_s    = (const float*)d_in[6];
    const float* ln1_b    = (const float*)d_in[7];
    const float* qkv_w    = (const float*)d_in[8];
    const float* qkv_b    = (const float*)d_in[9];
    const float* out_w    = (const float*)d_in[10];
    const float* out_b    = (const float*)d_in[11];
    const float* ln2_s    = (const float*)d_in[12];
    const float* ln2_b    = (const float*)d_in[13];
    const float* fc_w     = (const float*)d_in[14];
    const float* fc_b     = (const float*)d_in[15];
    const float* proj_w   = (const float*)d_in[16];
    const float* proj_b   = (const float*)d_in[17];
    const float* lnp_s    = (const float*)d_in[18];
    const float* lnp_b    = (const float*)d_in[19];
    const float* vis_proj = (const float*)d_in[20];
    float* outp = (float*)d_out;

    __nv_bfloat16 *wh, *wl, *xph, *xpl, *hh, *hl, *aoh, *aol, *mlph, *mlpl;
    float *pe, *x, *qkv, *cls;
    cudaGetSymbolAddress((void**)&wh,   g_wh);
    cudaGetSymbolAddress((void**)&wl,   g_wl);
    cudaGetSymbolAddress((void**)&xph,  g_xph);
    cudaGetSymbolAddress((void**)&xpl,  g_xpl);
    cudaGetSymbolAddress((void**)&pe,   g_pe);
    cudaGetSymbolAddress((void**)&x,    g_x);
    cudaGetSymbolAddress((void**)&hh,   g_hh);
    cudaGetSymbolAddress((void**)&hl,   g_hl);
    cudaGetSymbolAddress((void**)&qkv,  g_qkv);
    cudaGetSymbolAddress((void**)&aoh,  g_aoh);
    cudaGetSymbolAddress((void**)&aol,  g_aol);
    cudaGetSymbolAddress((void**)&mlph, g_mlph);
    cudaGetSymbolAddress((void**)&mlpl, g_mlpl);
    cudaGetSymbolAddress((void**)&cls,  g_cls);

    cudaFuncSetAttribute(k_mm<false,false,false,false>, cudaFuncAttributeMaxDynamicSharedMemorySize, MM_SMEM);
    cudaFuncSetAttribute(k_mm<true, false,false,false>, cudaFuncAttributeMaxDynamicSharedMemorySize, MM_SMEM);
    cudaFuncSetAttribute(k_mm<true, true, false,false>, cudaFuncAttributeMaxDynamicSharedMemorySize, MM_SMEM);
    cudaFuncSetAttribute(k_mm<true, false,true, true >, cudaFuncAttributeMaxDynamicSharedMemorySize, MM_SMEM);
    int attn_smem = (2 * Ss * 65 + 8 * 64 + 8 * 200) * sizeof(float);
    cudaFuncSetAttribute(k_attn, cudaFuncAttributeMaxDynamicSharedMemorySize, attn_smem);

    // ---- weight fp32 -> bf16 hi/lo ----
    {
        long n4;
        n4 = 589824 / 4;
        k_cvt<<<(n4 + 255) / 256, 256>>>((const float4*)conv_w,
            (__nv_bfloat162*)(wh + OFF_CONV), (__nv_bfloat162*)(wl + OFF_CONV), n4);
        n4 = 21233664 / 4;
        k_cvt<<<(n4 + 255) / 256, 256>>>((const float4*)qkv_w,
            (__nv_bfloat162*)(wh + OFF_QKV), (__nv_bfloat162*)(wl + OFF_QKV), n4);
        n4 = 7077888 / 4;
        k_cvt<<<(n4 + 255) / 256, 256>>>((const float4*)out_w,
            (__nv_bfloat162*)(wh + OFF_OUT), (__nv_bfloat162*)(wl + OFF_OUT), n4);
        n4 = 28311552 / 4;
        k_cvt<<<(n4 + 255) / 256, 256>>>((const float4*)fc_w,
            (__nv_bfloat162*)(wh + OFF_FC), (__nv_bfloat162*)(wl + OFF_FC), n4);
        n4 = 28311552 / 4;
        k_cvt<<<(n4 + 255) / 256, 256>>>((const float4*)proj_w,
            (__nv_bfloat162*)(wh + OFF_PROJ), (__nv_bfloat162*)(wl + OFF_PROJ), n4);
    }

    // ---- stem ----
    k_patchify<<<(NPROW * Dm + 255) / 256, 256>>>(images, xph, xpl);
    k_mm<false,false,false,false><<<dim3(Dm / 128, (NPROW + 127) / 128), 256, MM_SMEM>>>(
        xph, xpl, wh + OFF_CONV, wl + OFF_CONV, nullptr, nullptr,
        pe, nullptr, nullptr, NPROW, Dm, Dm);
    k_assemble<<<(NTOK * Dm + 255) / 256, 256>>>(pe, cls_emb, pos_emb, x);
    k_ln<false><<<NTOK, 256>>>(x, x, nullptr, nullptr, ln_pre_s, ln_pre_b, Dm, Dm);

    // ---- transformer layers ----
    for (int l = 0; l < Ll; l++) {
        const float* l1s = ln1_s + (size_t)l * Dm;
        const float* l1b = ln1_b + (size_t)l * Dm;
        const float* qb  = qkv_b + (size_t)l * 3 * Dm;
        const float* ob  = out_b + (size_t)l * Dm;
        const float* l2s = ln2_s + (size_t)l * Dm;
        const float* l2b = ln2_b + (size_t)l * Dm;
        const float* fb  = fc_b  + (size_t)l * Ff;
        const float* pb  = proj_b + (size_t)l * Dm;
        const __nv_bfloat16* qwh = wh + OFF_QKV  + (size_t)l * 2304 * 768;
        const __nv_bfloat16* qwl = wl + OFF_QKV  + (size_t)l * 2304 * 768;
        const __nv_bfloat16* owh = wh + OFF_OUT  + (size_t)l * 768 * 768;
        const __nv_bfloat16* owl = wl + OFF_OUT  + (size_t)l * 768 * 768;
        const __nv_bfloat16* fwh = wh + OFF_FC   + (size_t)l * 3072 * 768;
        const __nv_bfloat16* fwl = wl + OFF_FC   + (size_t)l * 3072 * 768;
        const __nv_bfloat16* pwh = wh + OFF_PROJ + (size_t)l * 768 * 3072;
        const __nv_bfloat16* pwl = wl + OFF_PROJ + (size_t)l * 768 * 3072;

        k_ln<true><<<NTOK, 256>>>(x, nullptr, hh, hl, l1s, l1b, Dm, Dm);
        k_mm<true,false,false,false><<<dim3(3 * Dm / 128, (NTOK + 127) / 128), 256, MM_SMEM>>>(
            hh, hl, qwh, qwl, qb, nullptr, qkv, nullptr, nullptr, NTOK, 3 * Dm, Dm);
        k_attn<<<Bsz * Hh, 256, attn_smem>>>(qkv, aoh, aol);
        k_mm<true,true,false,false><<<dim3(Dm / 128, (NTOK + 127) / 128), 256, MM_SMEM>>>(
            aoh, aol, owh, owl, ob, x, x, nullptr, nullptr, NTOK, Dm, Dm);
        k_ln<true><<<NTOK, 256>>>(x, nullptr, hh, hl, l2s, l2b, Dm, Dm);
        k_mm<true,false,true,true><<<dim3(Ff / 128, (NTOK + 127) / 128), 256, MM_SMEM>>>(
            hh, hl, fwh, fwl, fb, nullptr, nullptr, mlph, mlpl, NTOK, Ff, Dm);
        k_mm<true,true,false,false><<<dim3(Dm / 128, (NTOK + 127) / 128), 256, MM_SMEM>>>(
            mlph, mlpl, pwh, pwl, pb, x, x, nullptr, nullptr, NTOK, Dm, Ff);
    }

    // ---- head ----
    k_ln<false><<<Bsz, 256>>>(x, cls, nullptr, nullptr, lnp_s, lnp_b, (long)Ss * Dm, Dm);
    k_head<<<Bsz, 256>>>(cls, vis_proj, outp);
}

// round 6
// speedup vs baseline: 3.9800x; 1.2047x over previous
#include <cuda_runtime.h>
#include <cuda_fp16.h>
#include <math.h>
#include <cstdint>

// ---------------------------------------------------------------------------
// CLIP ViT-B/16 visual tower on GB300 — mma.sync 2-term fp16 split GEMMs.
// A = Ah + Al (fp16 hi/lo), W = fp16 single: C = Ah*W + Al*W.
// ---------------------------------------------------------------------------

#define Bsz 32
#define Dm  768
#define Hh  12
#define HD  64
#define Ff  3072
#define Ll  12
#define Ss  197
#define Oo  512
#define NPATCH 196
#define NTOK (Bsz * Ss)        // 6304
#define NPROW (Bsz * NPATCH)   // 6272

// ------------------------- helpers -----------------------------------------
__device__ __forceinline__ uint32_t smem_u32(const void* p) {
    uint32_t a;
    asm("{ .reg .u64 t; cvta.to.shared.u64 t, %1; cvt.u32.u64 %0, t; }"
        : "=r"(a) : "l"(p));
    return a;
}
__device__ __forceinline__ void cpa16(uint32_t dst, const void* src, uint32_t vsz) {
    asm volatile("cp.async.cg.shared.global [%0], [%1], 16, %2;"
                 :: "r"(dst), "l"(src), "r"(vsz) : "memory");
}
#define CP_COMMIT() asm volatile("cp.async.commit_group;" ::: "memory")
#define CP_WAIT0()  asm volatile("cp.async.wait_group 0;" ::: "memory")
#define CP_WAIT1()  asm volatile("cp.async.wait_group 1;" ::: "memory")

#define MMA16816(c, a0, a1, a2, a3, b0, b1) \
    asm volatile("mma.sync.aligned.m16n8k16.row.col.f32.f16.f16.f32 " \
        "{%0,%1,%2,%3}, {%4,%5,%6,%7}, {%8,%9}, {%0,%1,%2,%3};" \
        : "+f"((c)[0]), "+f"((c)[1]), "+f"((c)[2]), "+f"((c)[3]) \
        : "r"(a0), "r"(a1), "r"(a2), "r"(a3), "r"(b0), "r"(b1))

#define LDSM4(r0, r1, r2, r3, addr) \
    asm volatile("ldmatrix.sync.aligned.m8n8.x4.shared.b16 {%0,%1,%2,%3}, [%4];" \
        : "=r"(r0), "=r"(r1), "=r"(r2), "=r"(r3) : "r"(addr))

// ------------------------- scratch (static device globals) -----------------
#define OFF_CONV 0ul
#define OFF_QKV  589824ul
#define OFF_OUT  21823488ul
#define OFF_FC   28901376ul
#define OFF_PROJ 57212928ul
#define WTOT     85524480ul

__device__ __align__(16) __half g_w[WTOT];                 // fp16 weights (single)
__device__ __align__(16) __half g_xph[NPROW * Dm];
__device__ __align__(16) __half g_xpl[NPROW * Dm];
__device__ float g_pe[NPROW * Dm];
__device__ float g_x [NTOK * Dm];
__device__ __align__(16) __half g_hh[NTOK * Dm];
__device__ __align__(16) __half g_hl[NTOK * Dm];
__device__ float g_qkv[NTOK * 3 * Dm];
__device__ __align__(16) __half g_aoh[NTOK * Dm];
__device__ __align__(16) __half g_aol[NTOK * Dm];
__device__ __align__(16) __half g_mlph[NTOK * Ff];
__device__ __align__(16) __half g_mlpl[NTOK * Ff];
__device__ float g_cls[Bsz * Dm];

// ------------------------- weight fp32 -> fp16 -----------------------------
__global__ void k_cvt(const float4* __restrict__ src, __half2* __restrict__ w, long n4)
{
    long i = (long)blockIdx.x * blockDim.x + threadIdx.x;
    if (i >= n4) return;
    float4 v = src[i];
    w[2 * i]     = __floats2half2_rn(v.x, v.y);
    w[2 * i + 1] = __floats2half2_rn(v.z, v.w);
}

// ------------------------- patchify + normalize -> fp16 hi/lo --------------
__global__ void k_patchify(const float* __restrict__ img,
                           __half* __restrict__ xh, __half* __restrict__ xl)
{
    const float mean[3] = {0.48145466f, 0.4578275f, 0.40821073f};
    const float istd[3] = {1.f/0.26862954f, 1.f/0.26130258f, 1.f/0.27577711f};
    int idx = blockIdx.x * blockDim.x + threadIdx.x;
    if (idx >= NPROW * Dm) return;
    int col = idx % Dm;
    int row = idx / Dm;
    int b  = row / NPATCH;
    int p  = row % NPATCH;
    int py = p / 14, px = p % 14;
    int c  = col >> 8;
    int rem = col & 255;
    int ph = rem >> 4, pw = rem & 15;
    float v = img[(((size_t)b * 3 + c) * 224 + py * 16 + ph) * 224 + px * 16 + pw];
    v = (v - mean[c]) * istd[c];
    __half h = __float2half(v);
    xh[idx] = h;
    xl[idx] = __float2half(v - __half2float(h));
}

// ------------------------- mma.sync 2-term fp16 GEMM -----------------------
// C[M,N] = (Ah+Al)[M,K] @ W[N,K]^T (+bias)(+QuickGELU)(+res). N%128==0, K%64==0.
// Tile 128x128 per CTA, 8 warps (4x2), warp tile 32x64, K chunks of 64,
// 3-stage cp.async pipeline, ldmatrix loads. Row stride 144 B.
#define STG_MAT   18432            // 128 rows * 144 B
#define STG_BYTES 55296            // 3 matrices (Ah, Al, B)
#define MM_SMEM   (3 * STG_BYTES)  // 165888

template<bool BIAS, bool RES, bool GELU_, bool HLO>
__global__ __launch_bounds__(256) void k_mm(
    const __half* __restrict__ Ah, const __half* __restrict__ Al,
    const __half* __restrict__ B,
    const float* __restrict__ bias, const float* __restrict__ resi,
    float* __restrict__ C, __half* __restrict__ Ch, __half* __restrict__ Cl,
    int M, int N, int K)
{
    extern __shared__ char smc[];
    const uint32_t sb = smem_u32(smc);
    const int tid = threadIdx.x, lane = tid & 31, wid = tid >> 5;
    const int warp_m = wid & 3, warp_n = wid >> 2;
    const int bm = blockIdx.y * 128, bn = blockIdx.x * 128;
    const int Kd8 = K >> 3, nch = K >> 6;

    const uint4* A4[2] = {(const uint4*)Ah, (const uint4*)Al};
    const uint4* B4 = (const uint4*)B;

    float acc[2][8][4];
    #pragma unroll
    for (int a = 0; a < 2; a++)
        #pragma unroll
        for (int b = 0; b < 8; b++)
            #pragma unroll
            for (int c = 0; c < 4; c++) acc[a][b][c] = 0.f;

    auto load_chunk = [&](int i, int s) {
        int k0d8 = i << 3;
        uint32_t stg = sb + s * STG_BYTES;
        #pragma unroll
        for (int t = tid; t < 3072; t += 256) {
            int mat = t >> 10, r = (t >> 3) & 127, c8 = t & 7;
            uint32_t dst = stg + mat * STG_MAT + r * 144 + c8 * 16;
            if (mat < 2) {
                int grow = bm + r;
                int ok = grow < M;
                const uint4* src = A4[mat] + (size_t)(ok ? grow : 0) * Kd8 + k0d8 + c8;
                cpa16(dst, src, ok ? 16u : 0u);
            } else {
                const uint4* src = B4 + (size_t)(bn + r) * Kd8 + k0d8 + c8;
                cpa16(dst, src, 16u);
            }
        }
        CP_COMMIT();
    };

    load_chunk(0, 0);
    load_chunk(1, 1);

    // per-warp fragment base offsets (stage-relative)
    const uint32_t aoff = (uint32_t)((warp_m * 32 + (lane & 15)) * 144 + ((lane >> 4) << 4));
    const int brow = (lane & 7) + ((lane >> 4) << 3);
    const uint32_t boff = (uint32_t)(2 * STG_MAT + (warp_n * 64 + brow) * 144
                                     + (((lane >> 3) & 1) << 4));

    int s = 0;
    for (int i = 0; i < nch; i++) {
        if (i + 1 < nch) CP_WAIT1(); else CP_WAIT0();
        __syncthreads();
        if (i + 2 < nch) {
            int s2 = s + 2; if (s2 >= 3) s2 -= 3;
            load_chunk(i + 2, s2);
        }
        uint32_t stg = sb + s * STG_BYTES;
        uint32_t aH = stg + aoff, aL = aH + STG_MAT;
        uint32_t bB = stg + boff;
        #pragma unroll
        for (int k16 = 0; k16 < 4; k16++) {
            uint32_t ah[2][4], al[2][4], bf[4][4];
            #pragma unroll
            for (int mf = 0; mf < 2; mf++) {
                LDSM4(ah[mf][0], ah[mf][1], ah[mf][2], ah[mf][3],
                      aH + mf * (16 * 144) + k16 * 32);
                LDSM4(al[mf][0], al[mf][1], al[mf][2], al[mf][3],
                      aL + mf * (16 * 144) + k16 * 32);
            }
            #pragma unroll
            for (int p = 0; p < 4; p++)
                LDSM4(bf[p][0], bf[p][1], bf[p][2], bf[p][3],
                      bB + p * (16 * 144) + k16 * 32);
            // term 1: Ah * B  (16 independent accumulators)
            #pragma unroll
            for (int p = 0; p < 4; p++)
                #pragma unroll
                for (int sub = 0; sub < 2; sub++)
                    #pragma unroll
                    for (int mf = 0; mf < 2; mf++)
                        MMA16816(acc[mf][p * 2 + sub],
                                 ah[mf][0], ah[mf][1], ah[mf][2], ah[mf][3],
                                 bf[p][2 * sub], bf[p][2 * sub + 1]);
            // term 2: Al * B
            #pragma unroll
            for (int p = 0; p < 4; p++)
                #pragma unroll
                for (int sub = 0; sub < 2; sub++)
                    #pragma unroll
                    for (int mf = 0; mf < 2; mf++)
                        MMA16816(acc[mf][p * 2 + sub],
                                 al[mf][0], al[mf][1], al[mf][2], al[mf][3],
                                 bf[p][2 * sub], bf[p][2 * sub + 1]);
        }
        s++; if (s == 3) s = 0;
    }

    // ---- epilogue ----
    const int qrow = lane >> 2;
    #pragma unroll
    for (int mf = 0; mf < 2; mf++) {
        #pragma unroll
        for (int nf = 0; nf < 8; nf++) {
            int rbase = bm + warp_m * 32 + mf * 16 + qrow;
            int cbase = bn + warp_n * 64 + nf * 8 + ((lane & 3) << 1);
            #pragma unroll
            for (int e = 0; e < 4; e++) {
                int row = rbase + ((e >> 1) << 3);
                int col = cbase + (e & 1);
                if (row >= M) continue;
                float v = acc[mf][nf][e];
                if (BIAS)  v += bias[col];
                if (GELU_) v = v / (1.f + __expf(-1.702f * v));
                if (RES)   v += resi[(size_t)row * N + col];
                if (HLO) {
                    __half h = __float2half(v);
                    Ch[(size_t)row * N + col] = h;
                    Cl[(size_t)row * N + col] = __float2half(v - __half2float(h));
                } else {
                    C[(size_t)row * N + col] = v;
                }
            }
        }
    }
}

// ------------------------- assemble tokens ---------------------------------
__global__ void k_assemble(const float* __restrict__ pe, const float* __restrict__ cls,
                           const float* __restrict__ pos, float* __restrict__ x)
{
    int idx = blockIdx.x * blockDim.x + threadIdx.x;
    if (idx >= NTOK * Dm) return;
    int d = idx % Dm;
    int t = idx / Dm;
    int s = t % Ss, b = t / Ss;
    float v = (s == 0) ? cls[d] : pe[((size_t)b * NPATCH + (s - 1)) * Dm + d];
    x[idx] = v + pos[(size_t)s * Dm + d];
}

// ------------------------- LayerNorm (fp32 out / fp16 hi-lo out) -----------
template<bool HL>
__global__ void k_ln(const float* __restrict__ in, float* __restrict__ outf,
                     __half* __restrict__ oh, __half* __restrict__ ol,
                     const float* __restrict__ sc, const float* __restrict__ bi,
                     long in_stride, long out_stride)
{
    __shared__ float red[2][32];
    long row = blockIdx.x;
    const float* ip = in + row * in_stride;
    int tid = threadIdx.x;
    float v[3];
    float s = 0.f, sq = 0.f;
    #pragma unroll
    for (int i = 0; i < 3; i++) {
        v[i] = ip[tid + i * 256];
        s += v[i]; sq += v[i] * v[i];
    }
    #pragma unroll
    for (int o = 16; o > 0; o >>= 1) {
        s  += __shfl_xor_sync(~0u, s, o);
        sq += __shfl_xor_sync(~0u, sq, o);
    }
    int lane = tid & 31, w = tid >> 5;
    if (lane == 0) { red[0][w] = s; red[1][w] = sq; }
    __syncthreads();
    if (w == 0) {
        float a = (lane < 8) ? red[0][lane] : 0.f;
        float b = (lane < 8) ? red[1][lane] : 0.f;
        #pragma unroll
        for (int o = 4; o > 0; o >>= 1) {
            a += __shfl_xor_sync(~0u, a, o);
            b += __shfl_xor_sync(~0u, b, o);
        }
        if (lane == 0) { red[0][0] = a; red[1][0] = b; }
    }
    __syncthreads();
    float mean = red[0][0] * (1.f / Dm);
    float var  = red[1][0] * (1.f / Dm) - mean * mean;
    float r = rsqrtf(var + 1e-5f);
    #pragma unroll
    for (int i = 0; i < 3; i++) {
        int d = tid + i * 256;
        float y = (v[i] - mean) * r * sc[d] + bi[d];
        if (HL) {
            __half h = __float2half(y);
            oh[row * out_stride + d] = h;
            ol[row * out_stride + d] = __float2half(y - __half2float(h));
        } else {
            outf[row * out_stride + d] = y;
        }
    }
}

// ------------------------- fused attention ---------------------------------
__global__ __launch_bounds__(256) void k_attn(const float* __restrict__ QKV,
                                              __half* __restrict__ oh,
                                              __half* __restrict__ ol)
{
    extern __shared__ float sm[];
    float* Ks = sm;                       // 197*65
    float* Vs = Ks + Ss * 65;             // 197*65
    float* Qs = Vs + Ss * 65;             // 8*64
    float* Ps = Qs + 8 * 64;              // 8*200
    int bh = blockIdx.x;
    int b = bh / Hh, h = bh % Hh;
    int tid = threadIdx.x, lane = tid & 31, w = tid >> 5;
    const size_t base = (size_t)b * Ss * (3 * Dm) + (size_t)h * HD;

    for (int idx = tid; idx < Ss * HD; idx += 256) {
        int s = idx >> 6, d = idx & 63;
        Ks[s * 65 + d] = QKV[base + (size_t)s * (3 * Dm) + Dm + d];
        Vs[s * 65 + d] = QKV[base + (size_t)s * (3 * Dm) + 2 * Dm + d];
    }
    __syncthreads();

    for (int q = w; q < Ss; q += 8) {
        Qs[w * 64 + lane]      = QKV[base + (size_t)q * (3 * Dm) + lane] * 0.125f;
        Qs[w * 64 + lane + 32] = QKV[base + (size_t)q * (3 * Dm) + lane + 32] * 0.125f;
        __syncwarp();
        float mx = -1e30f;
        for (int k = lane; k < Ss; k += 32) {
            float s = 0.f;
            #pragma unroll
            for (int d = 0; d < HD; d++) s += Qs[w * 64 + d] * Ks[k * 65 + d];
            Ps[w * 200 + k] = s;
            mx = fmaxf(mx, s);
        }
        #pragma unroll
        for (int o = 16; o > 0; o >>= 1) mx = fmaxf(mx, __shfl_xor_sync(~0u, mx, o));
        float sum = 0.f;
        for (int k = lane; k < Ss; k += 32) {
            float p = __expf(Ps[w * 200 + k] - mx);
            Ps[w * 200 + k] = p;
            sum += p;
        }
        #pragma unroll
        for (int o = 16; o > 0; o >>= 1) sum += __shfl_xor_sync(~0u, sum, o);
        float inv = 1.f / sum;
        __syncwarp();
        float o0 = 0.f, o1 = 0.f;
        #pragma unroll 4
        for (int k = 0; k < Ss; k++) {
            float p = Ps[w * 200 + k];
            o0 += p * Vs[k * 65 + lane];
            o1 += p * Vs[k * 65 + lane + 32];
        }
        o0 *= inv; o1 *= inv;
        size_t orow = ((size_t)b * Ss + q) * Dm + h * HD;
        __half h0 = __float2half(o0);
        __half h1 = __float2half(o1);
        oh[orow + lane]      = h0;
        ol[orow + lane]      = __float2half(o0 - __half2float(h0));
        oh[orow + lane + 32] = h1;
        ol[orow + lane + 32] = __float2half(o1 - __half2float(h1));
        __syncwarp();
    }
}

// ------------------------- head: cls_ln @ vis_proj -------------------------
__global__ void k_head(const float* __restrict__ cls, const float* __restrict__ Wp,
                       float* __restrict__ out)
{
    __shared__ float row[Dm];
    int b = blockIdx.x;
    for (int i = threadIdx.x; i < Dm; i += 256) row[i] = cls[(size_t)b * Dm + i];
    __syncthreads();
    for (int o = threadIdx.x; o < Oo; o += 256) {
        float acc = 0.f;
        for (int d = 0; d < Dm; d++) acc += row[d] * Wp[(size_t)d * Oo + o];
        out[(size_t)b * Oo + o] = acc;
    }
}

// ---------------------------------------------------------------------------
extern "C" void kernel_launch(void* const* d_in, const int* in_sizes, int n_in,
                              void* d_out, int out_size)
{
    const float* images   = (const float*)d_in[0];
    const float* conv_w   = (const float*)d_in[1];
    const float* cls_emb  = (const float*)d_in[2];
    const float* pos_emb  = (const float*)d_in[3];
    const float* ln_pre_s = (const float*)d_in[4];
    const float* ln_pre_b = (const float*)d_in[5];
    const float* ln1_s    = (const float*)d_in[6];
    const float* ln1_b    = (const float*)d_in[7];
    const float* qkv_w    = (const float*)d_in[8];
    const float* qkv_b    = (const float*)d_in[9];
    const float* out_w    = (const float*)d_in[10];
    const float* out_b    = (const float*)d_in[11];
    const float* ln2_s    = (const float*)d_in[12];
    const float* ln2_b    = (const float*)d_in[13];
    const float* fc_w     = (const float*)d_in[14];
    const float* fc_b     = (const float*)d_in[15];
    const float* proj_w   = (const float*)d_in[16];
    const float* proj_b   = (const float*)d_in[17];
    const float* lnp_s    = (const float*)d_in[18];
    const float* lnp_b    = (const float*)d_in[19];
    const float* vis_proj = (const float*)d_in[20];
    float* outp = (float*)d_out;

    __half *w, *xph, *xpl, *hh, *hl, *aoh, *aol, *mlph, *mlpl;
    float *pe, *x, *qkv, *cls;
    cudaGetSymbolAddress((void**)&w,    g_w);
    cudaGetSymbolAddress((void**)&xph,  g_xph);
    cudaGetSymbolAddress((void**)&xpl,  g_xpl);
    cudaGetSymbolAddress((void**)&pe,   g_pe);
    cudaGetSymbolAddress((void**)&x,    g_x);
    cudaGetSymbolAddress((void**)&hh,   g_hh);
    cudaGetSymbolAddress((void**)&hl,   g_hl);
    cudaGetSymbolAddress((void**)&qkv,  g_qkv);
    cudaGetSymbolAddress((void**)&aoh,  g_aoh);
    cudaGetSymbolAddress((void**)&aol,  g_aol);
    cudaGetSymbolAddress((void**)&mlph, g_mlph);
    cudaGetSymbolAddress((void**)&mlpl, g_mlpl);
    cudaGetSymbolAddress((void**)&cls,  g_cls);

    cudaFuncSetAttribute(k_mm<false,false,false,false>, cudaFuncAttributeMaxDynamicSharedMemorySize, MM_SMEM);
    cudaFuncSetAttribute(k_mm<true, false,false,false>, cudaFuncAttributeMaxDynamicSharedMemorySize, MM_SMEM);
    cudaFuncSetAttribute(k_mm<true, true, false,false>, cudaFuncAttributeMaxDynamicSharedMemorySize, MM_SMEM);
    cudaFuncSetAttribute(k_mm<true, false,true, true >, cudaFuncAttributeMaxDynamicSharedMemorySize, MM_SMEM);
    int attn_smem = (2 * Ss * 65 + 8 * 64 + 8 * 200) * sizeof(float);
    cudaFuncSetAttribute(k_attn, cudaFuncAttributeMaxDynamicSharedMemorySize, attn_smem);

    // ---- weight fp32 -> fp16 ----
    {
        long n4;
        n4 = 589824 / 4;
        k_cvt<<<(n4 + 255) / 256, 256>>>((const float4*)conv_w, (__half2*)(w + OFF_CONV), n4);
        n4 = 21233664 / 4;
        k_cvt<<<(n4 + 255) / 256, 256>>>((const float4*)qkv_w,  (__half2*)(w + OFF_QKV),  n4);
        n4 = 7077888 / 4;
        k_cvt<<<(n4 + 255) / 256, 256>>>((const float4*)out_w,  (__half2*)(w + OFF_OUT),  n4);
        n4 = 28311552 / 4;
        k_cvt<<<(n4 + 255) / 256, 256>>>((const float4*)fc_w,   (__half2*)(w + OFF_FC),   n4);
        n4 = 28311552 / 4;
        k_cvt<<<(n4 + 255) / 256, 256>>>((const float4*)proj_w, (__half2*)(w + OFF_PROJ), n4);
    }

    // ---- stem ----
    k_patchify<<<(NPROW * Dm + 255) / 256, 256>>>(images, xph, xpl);
    k_mm<false,false,false,false><<<dim3(Dm / 128, (NPROW + 127) / 128), 256, MM_SMEM>>>(
        xph, xpl, w + OFF_CONV, nullptr, nullptr,
        pe, nullptr, nullptr, NPROW, Dm, Dm);
    k_assemble<<<(NTOK * Dm + 255) / 256, 256>>>(pe, cls_emb, pos_emb, x);
    k_ln<false><<<NTOK, 256>>>(x, x, nullptr, nullptr, ln_pre_s, ln_pre_b, Dm, Dm);

    // ---- transformer layers ----
    for (int l = 0; l < Ll; l++) {
        const float* l1s = ln1_s + (size_t)l * Dm;
        const float* l1b = ln1_b + (size_t)l * Dm;
        const float* qb  = qkv_b + (size_t)l * 3 * Dm;
        const float* ob  = out_b + (size_t)l * Dm;
        const float* l2s = ln2_s + (size_t)l * Dm;
        const float* l2b = ln2_b + (size_t)l * Dm;
        const float* fb  = fc_b  + (size_t)l * Ff;
        const float* pb  = proj_b + (size_t)l * Dm;
        const __half* qw = w + OFF_QKV  + (size_t)l * 2304 * 768;
        const __half* ow = w + OFF_OUT  + (size_t)l * 768 * 768;
        const __half* fw = w + OFF_FC   + (size_t)l * 3072 * 768;
        const __half* pw = w + OFF_PROJ + (size_t)l * 768 * 3072;

        k_ln<true><<<NTOK, 256>>>(x, nullptr, hh, hl, l1s, l1b, Dm, Dm);
        k_mm<true,false,false,false><<<dim3(3 * Dm / 128, (NTOK + 127) / 128), 256, MM_SMEM>>>(
            hh, hl, qw, qb, nullptr, qkv, nullptr, nullptr, NTOK, 3 * Dm, Dm);
        k_attn<<<Bsz * Hh, 256, attn_smem>>>(qkv, aoh, aol);
        k_mm<true,true,false,false><<<dim3(Dm / 128, (NTOK + 127) / 128), 256, MM_SMEM>>>(
            aoh, aol, ow, ob, x, x, nullptr, nullptr, NTOK, Dm, Dm);
        k_ln<true><<<NTOK, 256>>>(x, nullptr, hh, hl, l2s, l2b, Dm, Dm);
        k_mm<true,false,true,true><<<dim3(Ff / 128, (NTOK + 127) / 128), 256, MM_SMEM>>>(
            hh, hl, fw, fb, nullptr, nullptr, mlph, mlpl, NTOK, Ff, Dm);
        k_mm<true,true,false,false><<<dim3(Dm / 128, (NTOK + 127) / 128), 256, MM_SMEM>>>(
            mlph, mlpl, pw, pb, x, x, nullptr, nullptr, NTOK, Dm, Ff);
    }

    // ---- head ----
    k_ln<false><<<Bsz, 256>>>(x, cls, nullptr, nullptr, lnp_s, lnp_b, (long)Ss * Dm, Dm);
    k_head<<<Bsz, 256>>>(cls, vis_proj, outp);
}

// round 7
// speedup vs baseline: 9.9617x; 2.5030x over previous
#include <cuda_runtime.h>
#include <cuda_fp16.h>
#include <math.h>
#include <cstdint>

// ---------------------------------------------------------------------------
// CLIP ViT-B/16 visual tower on GB300 — 1-term fp16 mma.sync GEMMs
// + tensor-core flash-style attention.
// ---------------------------------------------------------------------------

#define Bsz 32
#define Dm  768
#define Hh  12
#define HD  64
#define Ff  3072
#define Ll  12
#define Ss  197
#define Oo  512
#define NPATCH 196
#define NTOK (Bsz * Ss)        // 6304
#define NPROW (Bsz * NPATCH)   // 6272

// ------------------------- helpers -----------------------------------------
__device__ __forceinline__ uint32_t smem_u32(const void* p) {
    uint32_t a;
    asm("{ .reg .u64 t; cvta.to.shared.u64 t, %1; cvt.u32.u64 %0, t; }"
        : "=r"(a) : "l"(p));
    return a;
}
__device__ __forceinline__ void cpa16(uint32_t dst, const void* src, uint32_t vsz) {
    asm volatile("cp.async.cg.shared.global [%0], [%1], 16, %2;"
                 :: "r"(dst), "l"(src), "r"(vsz) : "memory");
}
#define CP_COMMIT() asm volatile("cp.async.commit_group;" ::: "memory")
#define CP_WAIT0()  asm volatile("cp.async.wait_group 0;" ::: "memory")
#define CP_WAIT1()  asm volatile("cp.async.wait_group 1;" ::: "memory")

#define MMA16816(c, a0, a1, a2, a3, b0, b1) \
    asm volatile("mma.sync.aligned.m16n8k16.row.col.f32.f16.f16.f32 " \
        "{%0,%1,%2,%3}, {%4,%5,%6,%7}, {%8,%9}, {%0,%1,%2,%3};" \
        : "+f"((c)[0]), "+f"((c)[1]), "+f"((c)[2]), "+f"((c)[3]) \
        : "r"(a0), "r"(a1), "r"(a2), "r"(a3), "r"(b0), "r"(b1))

#define LDSM4(r0, r1, r2, r3, addr) \
    asm volatile("ldmatrix.sync.aligned.m8n8.x4.shared.b16 {%0,%1,%2,%3}, [%4];" \
        : "=r"(r0), "=r"(r1), "=r"(r2), "=r"(r3) : "r"(addr))

// ------------------------- scratch (static device globals) -----------------
#define OFF_CONV 0ul
#define OFF_QKV  589824ul
#define OFF_OUT  21823488ul
#define OFF_FC   28901376ul
#define OFF_PROJ 57212928ul
#define WTOT     85524480ul

__device__ __align__(16) __half g_w[WTOT];        // fp16 weights
__device__ __align__(16) __half g_xp[NPROW * Dm]; // fp16 patch matrix
__device__ float g_pe[NPROW * Dm];
__device__ float g_x [NTOK * Dm];                 // fp32 residual stream
__device__ __align__(16) __half g_h[NTOK * Dm];   // fp16 LN output
__device__ float g_qkv[NTOK * 3 * Dm];
__device__ __align__(16) __half g_ao[NTOK * Dm];  // fp16 attn out
__device__ __align__(16) __half g_mlp[NTOK * Ff]; // fp16 mlp hidden
__device__ float g_cls[Bsz * Dm];

// ------------------------- weight fp32 -> fp16 -----------------------------
__global__ void k_cvt(const float4* __restrict__ src, __half2* __restrict__ w, long n4)
{
    long i = (long)blockIdx.x * blockDim.x + threadIdx.x;
    if (i >= n4) return;
    float4 v = src[i];
    w[2 * i]     = __floats2half2_rn(v.x, v.y);
    w[2 * i + 1] = __floats2half2_rn(v.z, v.w);
}

// ------------------------- patchify + normalize -> fp16 --------------------
__global__ void k_patchify(const float* __restrict__ img, __half* __restrict__ xh)
{
    const float mean[3] = {0.48145466f, 0.4578275f, 0.40821073f};
    const float istd[3] = {1.f/0.26862954f, 1.f/0.26130258f, 1.f/0.27577711f};
    int idx = blockIdx.x * blockDim.x + threadIdx.x;
    if (idx >= NPROW * Dm) return;
    int col = idx % Dm;
    int row = idx / Dm;
    int b  = row / NPATCH;
    int p  = row % NPATCH;
    int py = p / 14, px = p % 14;
    int c  = col >> 8;
    int rem = col & 255;
    int ph = rem >> 4, pw = rem & 15;
    float v = img[(((size_t)b * 3 + c) * 224 + py * 16 + ph) * 224 + px * 16 + pw];
    xh[idx] = __float2half((v - mean[c]) * istd[c]);
}

// ------------------------- mma.sync fp16 GEMM ------------------------------
// C[M,N] = A[M,K] @ W[N,K]^T (+bias)(+QuickGELU)(+res). N%128==0, K%64==0.
// Tile 128x128 per CTA, 8 warps (4x2), warp tile 32x64, K chunks of 64,
// 3-stage cp.async pipeline, ldmatrix loads. Row stride 144 B.
#define STG_MAT   18432            // 128 rows * 144 B
#define STG_BYTES 36864            // 2 matrices (A, B)
#define MM_SMEM   (3 * STG_BYTES)  // 110592

template<bool BIAS, bool RES, bool GELU_, bool F16O>
__global__ __launch_bounds__(256) void k_mm(
    const __half* __restrict__ A, const __half* __restrict__ B,
    const float* __restrict__ bias, const float* __restrict__ resi,
    float* __restrict__ C, __half* __restrict__ Ch,
    int M, int N, int K)
{
    extern __shared__ char smc[];
    const uint32_t sb = smem_u32(smc);
    const int tid = threadIdx.x, lane = tid & 31, wid = tid >> 5;
    const int warp_m = wid & 3, warp_n = wid >> 2;
    const int bm = blockIdx.y * 128, bn = blockIdx.x * 128;
    const int Kd8 = K >> 3, nch = K >> 6;

    const uint4* A4 = (const uint4*)A;
    const uint4* B4 = (const uint4*)B;

    float acc[2][8][4];
    #pragma unroll
    for (int a = 0; a < 2; a++)
        #pragma unroll
        for (int b = 0; b < 8; b++)
            #pragma unroll
            for (int c = 0; c < 4; c++) acc[a][b][c] = 0.f;

    auto load_chunk = [&](int i, int s) {
        int k0d8 = i << 3;
        uint32_t stg = sb + s * STG_BYTES;
        #pragma unroll
        for (int t = tid; t < 2048; t += 256) {
            int mat = t >> 10, r = (t >> 3) & 127, c8 = t & 7;
            uint32_t dst = stg + mat * STG_MAT + r * 144 + c8 * 16;
            if (mat == 0) {
                int grow = bm + r;
                int ok = grow < M;
                const uint4* src = A4 + (size_t)(ok ? grow : 0) * Kd8 + k0d8 + c8;
                cpa16(dst, src, ok ? 16u : 0u);
            } else {
                const uint4* src = B4 + (size_t)(bn + r) * Kd8 + k0d8 + c8;
                cpa16(dst, src, 16u);
            }
        }
        CP_COMMIT();
    };

    load_chunk(0, 0);
    load_chunk(1, 1);

    const uint32_t aoff = (uint32_t)((warp_m * 32 + (lane & 15)) * 144 + ((lane >> 4) << 4));
    const int brow = (lane & 7) + ((lane >> 4) << 3);
    const uint32_t boff = (uint32_t)(STG_MAT + (warp_n * 64 + brow) * 144
                                     + (((lane >> 3) & 1) << 4));

    int s = 0;
    for (int i = 0; i < nch; i++) {
        if (i + 1 < nch) CP_WAIT1(); else CP_WAIT0();
        __syncthreads();
        if (i + 2 < nch) {
            int s2 = s + 2; if (s2 >= 3) s2 -= 3;
            load_chunk(i + 2, s2);
        }
        uint32_t stg = sb + s * STG_BYTES;
        uint32_t aA = stg + aoff, bB = stg + boff;
        #pragma unroll
        for (int k16 = 0; k16 < 4; k16++) {
            uint32_t ah[2][4], bf[4][4];
            #pragma unroll
            for (int mf = 0; mf < 2; mf++)
                LDSM4(ah[mf][0], ah[mf][1], ah[mf][2], ah[mf][3],
                      aA + mf * (16 * 144) + k16 * 32);
            #pragma unroll
            for (int p = 0; p < 4; p++)
                LDSM4(bf[p][0], bf[p][1], bf[p][2], bf[p][3],
                      bB + p * (16 * 144) + k16 * 32);
            #pragma unroll
            for (int p = 0; p < 4; p++)
                #pragma unroll
                for (int sub = 0; sub < 2; sub++)
                    #pragma unroll
                    for (int mf = 0; mf < 2; mf++)
                        MMA16816(acc[mf][p * 2 + sub],
                                 ah[mf][0], ah[mf][1], ah[mf][2], ah[mf][3],
                                 bf[p][2 * sub], bf[p][2 * sub + 1]);
        }
        s++; if (s == 3) s = 0;
    }

    // ---- epilogue ----
    const int qrow = lane >> 2;
    #pragma unroll
    for (int mf = 0; mf < 2; mf++) {
        #pragma unroll
        for (int nf = 0; nf < 8; nf++) {
            int rbase = bm + warp_m * 32 + mf * 16 + qrow;
            int cbase = bn + warp_n * 64 + nf * 8 + ((lane & 3) << 1);
            #pragma unroll
            for (int e = 0; e < 4; e++) {
                int row = rbase + ((e >> 1) << 3);
                int col = cbase + (e & 1);
                if (row >= M) continue;
                float v = acc[mf][nf][e];
                if (BIAS)  v += bias[col];
                if (GELU_) v = v / (1.f + __expf(-1.702f * v));
                if (RES)   v += resi[(size_t)row * N + col];
                if (F16O) Ch[(size_t)row * N + col] = __float2half(v);
                else      C [(size_t)row * N + col] = v;
            }
        }
    }
}

// ------------------------- tensor-core attention ---------------------------
// one CTA per (b, head), 8 warps. Q/K/V fp16 in smem (V transposed),
// S = Q K^T via mma (fp32 acc), fp32 softmax, P fp16 -> P V via mma.
// Padded to 208 keys / 13 q-tiles of 16.
#define ATT_SMEM 87552  // Q 208x72 + K 208x72 + Vt 64x216 halves

__global__ __launch_bounds__(256) void k_attn(const float* __restrict__ QKV,
                                              __half* __restrict__ out)
{
    extern __shared__ __half sm[];
    __half* Qs = sm;             // 208 rows x 72 halves (144 B stride)
    __half* Ks = sm + 14976;     // 208 x 72
    __half* Vt = sm + 29952;     // 64 x 216 halves (432 B stride)
    const int bh = blockIdx.x, b = bh / Hh, h = bh % Hh;
    const int tid = threadIdx.x, lane = tid & 31, wid = tid >> 5;

    {   // zero smem (padding safety: masked scores select -inf; Vt must be finite)
        uint4* z = (uint4*)sm;
        for (int i = tid; i < ATT_SMEM / 16; i += 256) z[i] = make_uint4(0, 0, 0, 0);
    }
    __syncthreads();

    const float* qp = QKV + (size_t)b * Ss * (3 * Dm) + h * HD;
    for (int idx = tid; idx < Ss * HD; idx += 256) {
        int s_ = idx >> 6, d = idx & 63;
        const float* row = qp + (size_t)s_ * (3 * Dm);
        Qs[s_ * 72 + d] = __float2half(row[d] * 0.125f);
        Ks[s_ * 72 + d] = __float2half(row[Dm + d]);
        Vt[d * 216 + s_] = __float2half(row[2 * Dm + d]);
    }
    __syncthreads();

    const uint32_t qsb = smem_u32(Qs), ksb = smem_u32(Ks), vtb = smem_u32(Vt);
    const uint32_t arow = (uint32_t)((lane & 15) * 144 + ((lane >> 4) << 4));
    const uint32_t brow = (uint32_t)(((lane & 7) + ((lane >> 4) << 3)) * 144
                                     + (((lane >> 3) & 1) << 4));
    const uint32_t vrow = (uint32_t)(((lane & 7) + ((lane >> 4) << 3)) * 432
                                     + (((lane >> 3) & 1) << 4));
    const int r = lane >> 2, cq = (lane & 3) << 1;

    for (int qt = wid; qt < 13; qt += 8) {
        // ---- S = Q K^T : 16 queries x 208 keys ----
        float sacc[26][4];
        #pragma unroll
        for (int f = 0; f < 26; f++)
            #pragma unroll
            for (int e = 0; e < 4; e++) sacc[f][e] = 0.f;
        #pragma unroll
        for (int k16 = 0; k16 < 4; k16++) {
            uint32_t aq0, aq1, aq2, aq3;
            LDSM4(aq0, aq1, aq2, aq3, qsb + qt * (16 * 144) + arow + k16 * 32);
            #pragma unroll
            for (int p = 0; p < 13; p++) {
                uint32_t kb[4];
                LDSM4(kb[0], kb[1], kb[2], kb[3], ksb + p * (16 * 144) + brow + k16 * 32);
                MMA16816(sacc[2 * p],     aq0, aq1, aq2, aq3, kb[0], kb[1]);
                MMA16816(sacc[2 * p + 1], aq0, aq1, aq2, aq3, kb[2], kb[3]);
            }
        }
        // ---- mask padded keys ----
        #pragma unroll
        for (int f = 0; f < 26; f++) {
            int c0 = 8 * f + cq;
            if (c0 >= Ss)     { sacc[f][0] = -1e30f; sacc[f][2] = -1e30f; }
            if (c0 + 1 >= Ss) { sacc[f][1] = -1e30f; sacc[f][3] = -1e30f; }
        }
        // ---- softmax (rows r and r+8) ----
        float mx0 = -1e30f, mx1 = -1e30f;
        #pragma unroll
        for (int f = 0; f < 26; f++) {
            mx0 = fmaxf(mx0, fmaxf(sacc[f][0], sacc[f][1]));
            mx1 = fmaxf(mx1, fmaxf(sacc[f][2], sacc[f][3]));
        }
        mx0 = fmaxf(mx0, __shfl_xor_sync(~0u, mx0, 1));
        mx0 = fmaxf(mx0, __shfl_xor_sync(~0u, mx0, 2));
        mx1 = fmaxf(mx1, __shfl_xor_sync(~0u, mx1, 1));
        mx1 = fmaxf(mx1, __shfl_xor_sync(~0u, mx1, 2));
        float sum0 = 0.f, sum1 = 0.f;
        #pragma unroll
        for (int f = 0; f < 26; f++) {
            sacc[f][0] = __expf(sacc[f][0] - mx0);
            sacc[f][1] = __expf(sacc[f][1] - mx0);
            sacc[f][2] = __expf(sacc[f][2] - mx1);
            sacc[f][3] = __expf(sacc[f][3] - mx1);
            sum0 += sacc[f][0] + sacc[f][1];
            sum1 += sacc[f][2] + sacc[f][3];
        }
        sum0 += __shfl_xor_sync(~0u, sum0, 1);
        sum0 += __shfl_xor_sync(~0u, sum0, 2);
        sum1 += __shfl_xor_sync(~0u, sum1, 1);
        sum1 += __shfl_xor_sync(~0u, sum1, 2);
        float inv0 = 1.f / sum0, inv1 = 1.f / sum1;
        // ---- pack P into A-fragments (C-frag -> A-frag identity) ----
        uint32_t pa[13][4];
        #pragma unroll
        for (int kk = 0; kk < 13; kk++) {
            __half2 t0 = __floats2half2_rn(sacc[2*kk][0] * inv0,   sacc[2*kk][1] * inv0);
            __half2 t1 = __floats2half2_rn(sacc[2*kk][2] * inv1,   sacc[2*kk][3] * inv1);
            __half2 t2 = __floats2half2_rn(sacc[2*kk+1][0] * inv0, sacc[2*kk+1][1] * inv0);
            __half2 t3 = __floats2half2_rn(sacc[2*kk+1][2] * inv1, sacc[2*kk+1][3] * inv1);
            pa[kk][0] = *(uint32_t*)&t0;
            pa[kk][1] = *(uint32_t*)&t1;
            pa[kk][2] = *(uint32_t*)&t2;
            pa[kk][3] = *(uint32_t*)&t3;
        }
        // ---- O = P V ----
        float oacc[8][4];
        #pragma unroll
        for (int f = 0; f < 8; f++)
            #pragma unroll
            for (int e = 0; e < 4; e++) oacc[f][e] = 0.f;
        #pragma unroll
        for (int kk = 0; kk < 13; kk++) {
            #pragma unroll
            for (int pv = 0; pv < 4; pv++) {
                uint32_t vb[4];
                LDSM4(vb[0], vb[1], vb[2], vb[3], vtb + pv * (16 * 432) + vrow + kk * 32);
                MMA16816(oacc[2 * pv],     pa[kk][0], pa[kk][1], pa[kk][2], pa[kk][3],
                         vb[0], vb[1]);
                MMA16816(oacc[2 * pv + 1], pa[kk][0], pa[kk][1], pa[kk][2], pa[kk][3],
                         vb[2], vb[3]);
            }
        }
        // ---- store ----
        #pragma unroll
        for (int f = 0; f < 8; f++) {
            int d = 8 * f + cq;
            #pragma unroll
            for (int e = 0; e < 4; e++) {
                int q = qt * 16 + r + ((e >> 1) << 3);
                if (q < Ss)
                    out[((size_t)(b * Ss + q)) * Dm + h * HD + d + (e & 1)]
                        = __float2half(oacc[f][e]);
            }
        }
    }
}

// ------------------------- assemble tokens ---------------------------------
__global__ void k_assemble(const float* __restrict__ pe, const float* __restrict__ cls,
                           const float* __restrict__ pos, float* __restrict__ x)
{
    int idx = blockIdx.x * blockDim.x + threadIdx.x;
    if (idx >= NTOK * Dm) return;
    int d = idx % Dm;
    int t = idx / Dm;
    int s = t % Ss, b = t / Ss;
    float v = (s == 0) ? cls[d] : pe[((size_t)b * NPATCH + (s - 1)) * Dm + d];
    x[idx] = v + pos[(size_t)s * Dm + d];
}

// ------------------------- LayerNorm (fp32 out / fp16 out) -----------------
template<bool F16>
__global__ void k_ln(const float* __restrict__ in, float* __restrict__ outf,
                     __half* __restrict__ oh,
                     const float* __restrict__ sc, const float* __restrict__ bi,
                     long in_stride, long out_stride)
{
    __shared__ float red[2][32];
    long row = blockIdx.x;
    const float* ip = in + row * in_stride;
    int tid = threadIdx.x;
    float v[3];
    float s = 0.f, sq = 0.f;
    #pragma unroll
    for (int i = 0; i < 3; i++) {
        v[i] = ip[tid + i * 256];
        s += v[i]; sq += v[i] * v[i];
    }
    #pragma unroll
    for (int o = 16; o > 0; o >>= 1) {
        s  += __shfl_xor_sync(~0u, s, o);
        sq += __shfl_xor_sync(~0u, sq, o);
    }
    int lane = tid & 31, w = tid >> 5;
    if (lane == 0) { red[0][w] = s; red[1][w] = sq; }
    __syncthreads();
    if (w == 0) {
        float a = (lane < 8) ? red[0][lane] : 0.f;
        float b = (lane < 8) ? red[1][lane] : 0.f;
        #pragma unroll
        for (int o = 4; o > 0; o >>= 1) {
            a += __shfl_xor_sync(~0u, a, o);
            b += __shfl_xor_sync(~0u, b, o);
        }
        if (lane == 0) { red[0][0] = a; red[1][0] = b; }
    }
    __syncthreads();
    float mean = red[0][0] * (1.f / Dm);
    float var  = red[1][0] * (1.f / Dm) - mean * mean;
    float r = rsqrtf(var + 1e-5f);
    #pragma unroll
    for (int i = 0; i < 3; i++) {
        int d = tid + i * 256;
        float y = (v[i] - mean) * r * sc[d] + bi[d];
        if (F16) oh[row * out_stride + d] = __float2half(y);
        else     outf[row * out_stride + d] = y;
    }
}

// ------------------------- head: cls_ln @ vis_proj -------------------------
__global__ void k_head(const float* __restrict__ cls, const float* __restrict__ Wp,
                       float* __restrict__ out)
{
    __shared__ float row[Dm];
    int b = blockIdx.x;
    for (int i = threadIdx.x; i < Dm; i += 256) row[i] = cls[(size_t)b * Dm + i];
    __syncthreads();
    for (int o = threadIdx.x; o < Oo; o += 256) {
        float acc = 0.f;
        for (int d = 0; d < Dm; d++) acc += row[d] * Wp[(size_t)d * Oo + o];
        out[(size_t)b * Oo + o] = acc;
    }
}

// ---------------------------------------------------------------------------
extern "C" void kernel_launch(void* const* d_in, const int* in_sizes, int n_in,
                              void* d_out, int out_size)
{
    const float* images   = (const float*)d_in[0];
    const float* conv_w   = (const float*)d_in[1];
    const float* cls_emb  = (const float*)d_in[2];
    const float* pos_emb  = (const float*)d_in[3];
    const float* ln_pre_s = (const float*)d_in[4];
    const float* ln_pre_b = (const float*)d_in[5];
    const float* ln1_s    = (const float*)d_in[6];
    const float* ln1_b    = (const float*)d_in[7];
    const float* qkv_w    = (const float*)d_in[8];
    const float* qkv_b    = (const float*)d_in[9];
    const float* out_w    = (const float*)d_in[10];
    const float* out_b    = (const float*)d_in[11];
    const float* ln2_s    = (const float*)d_in[12];
    const float* ln2_b    = (const float*)d_in[13];
    const float* fc_w     = (const float*)d_in[14];
    const float* fc_b     = (const float*)d_in[15];
    const float* proj_w   = (const float*)d_in[16];
    const float* proj_b   = (const float*)d_in[17];
    const float* lnp_s    = (const float*)d_in[18];
    const float* lnp_b    = (const float*)d_in[19];
    const float* vis_proj = (const float*)d_in[20];
    float* outp = (float*)d_out;

    __half *w, *xp, *h, *ao, *mlp;
    float *pe, *x, *qkv, *cls;
    cudaGetSymbolAddress((void**)&w,   g_w);
    cudaGetSymbolAddress((void**)&xp,  g_xp);
    cudaGetSymbolAddress((void**)&pe,  g_pe);
    cudaGetSymbolAddress((void**)&x,   g_x);
    cudaGetSymbolAddress((void**)&h,   g_h);
    cudaGetSymbolAddress((void**)&qkv, g_qkv);
    cudaGetSymbolAddress((void**)&ao,  g_ao);
    cudaGetSymbolAddress((void**)&mlp, g_mlp);
    cudaGetSymbolAddress((void**)&cls, g_cls);

    cudaFuncSetAttribute(k_mm<false,false,false,false>, cudaFuncAttributeMaxDynamicSharedMemorySize, MM_SMEM);
    cudaFuncSetAttribute(k_mm<true, false,false,false>, cudaFuncAttributeMaxDynamicSharedMemorySize, MM_SMEM);
    cudaFuncSetAttribute(k_mm<true, true, false,false>, cudaFuncAttributeMaxDynamicSharedMemorySize, MM_SMEM);
    cudaFuncSetAttribute(k_mm<true, false,true, true >, cudaFuncAttributeMaxDynamicSharedMemorySize, MM_SMEM);
    cudaFuncSetAttribute(k_attn, cudaFuncAttributeMaxDynamicSharedMemorySize, ATT_SMEM);

    // ---- weight fp32 -> fp16 ----
    {
        long n4;
        n4 = 589824 / 4;
        k_cvt<<<(n4 + 255) / 256, 256>>>((const float4*)conv_w, (__half2*)(w + OFF_CONV), n4);
        n4 = 21233664 / 4;
        k_cvt<<<(n4 + 255) / 256, 256>>>((const float4*)qkv_w,  (__half2*)(w + OFF_QKV),  n4);
        n4 = 7077888 / 4;
        k_cvt<<<(n4 + 255) / 256, 256>>>((const float4*)out_w,  (__half2*)(w + OFF_OUT),  n4);
        n4 = 28311552 / 4;
        k_cvt<<<(n4 + 255) / 256, 256>>>((const float4*)fc_w,   (__half2*)(w + OFF_FC),   n4);
        n4 = 28311552 / 4;
        k_cvt<<<(n4 + 255) / 256, 256>>>((const float4*)proj_w, (__half2*)(w + OFF_PROJ), n4);
    }

    // ---- stem ----
    k_patchify<<<(NPROW * Dm + 255) / 256, 256>>>(images, xp);
    k_mm<false,false,false,false><<<dim3(Dm / 128, (NPROW + 127) / 128), 256, MM_SMEM>>>(
        xp, w + OFF_CONV, nullptr, nullptr, pe, nullptr, NPROW, Dm, Dm);
    k_assemble<<<(NTOK * Dm + 255) / 256, 256>>>(pe, cls_emb, pos_emb, x);
    k_ln<false><<<NTOK, 256>>>(x, x, nullptr, ln_pre_s, ln_pre_b, Dm, Dm);

    // ---- transformer layers ----
    for (int l = 0; l < Ll; l++) {
        const float* l1s = ln1_s + (size_t)l * Dm;
        const float* l1b = ln1_b + (size_t)l * Dm;
        const float* qb  = qkv_b + (size_t)l * 3 * Dm;
        const float* ob  = out_b + (size_t)l * Dm;
        const float* l2s = ln2_s + (size_t)l * Dm;
        const float* l2b = ln2_b + (size_t)l * Dm;
        const float* fb  = fc_b  + (size_t)l * Ff;
        const float* pb  = proj_b + (size_t)l * Dm;
        const __half* qw = w + OFF_QKV  + (size_t)l * 2304 * 768;
        const __half* ow = w + OFF_OUT  + (size_t)l * 768 * 768;
        const __half* fw = w + OFF_FC   + (size_t)l * 3072 * 768;
        const __half* pw = w + OFF_PROJ + (size_t)l * 768 * 3072;

        k_ln<true><<<NTOK, 256>>>(x, nullptr, h, l1s, l1b, Dm, Dm);
        k_mm<true,false,false,false><<<dim3(3 * Dm / 128, (NTOK + 127) / 128), 256, MM_SMEM>>>(
            h, qw, qb, nullptr, qkv, nullptr, NTOK, 3 * Dm, Dm);
        k_attn<<<Bsz * Hh, 256, ATT_SMEM>>>(qkv, ao);
        k_mm<true,true,false,false><<<dim3(Dm / 128, (NTOK + 127) / 128), 256, MM_SMEM>>>(
            ao, ow, ob, x, x, nullptr, NTOK, Dm, Dm);
        k_ln<true><<<NTOK, 256>>>(x, nullptr, h, l2s, l2b, Dm, Dm);
        k_mm<true,false,true,true><<<dim3(Ff / 128, (NTOK + 127) / 128), 256, MM_SMEM>>>(
            h, fw, fb, nullptr, nullptr, mlp, NTOK, Ff, Dm);
        k_mm<true,true,false,false><<<dim3(Dm / 128, (NTOK + 127) / 128), 256, MM_SMEM>>>(
            mlp, pw, pb, x, x, nullptr, NTOK, Dm, Ff);
    }

    // ---- head ----
    k_ln<false><<<Bsz, 256>>>(x, cls, nullptr, lnp_s, lnp_b, (long)Ss * Dm, Dm);
    k_head<<<Bsz, 256>>>(cls, vis_proj, outp);
}

// round 8
// speedup vs baseline: 12.0418x; 1.2088x over previous
#include <cuda_runtime.h>
#include <cuda_fp16.h>
#include <math.h>
#include <cstdint>

// ---------------------------------------------------------------------------
// CLIP ViT-B/16 visual tower on GB300 — 1-term fp16 mma.sync GEMMs
// + tensor-core attention + vectorized warp-per-row LN / fused stem.
// ---------------------------------------------------------------------------

#define Bsz 32
#define Dm  768
#define Hh  12
#define HD  64
#define Ff  3072
#define Ll  12
#define Ss  197
#define Oo  512
#define NPATCH 196
#define NTOK (Bsz * Ss)        // 6304
#define NPROW (Bsz * NPATCH)   // 6272

// ------------------------- helpers -----------------------------------------
__device__ __forceinline__ uint32_t smem_u32(const void* p) {
    uint32_t a;
    asm("{ .reg .u64 t; cvta.to.shared.u64 t, %1; cvt.u32.u64 %0, t; }"
        : "=r"(a) : "l"(p));
    return a;
}
__device__ __forceinline__ void cpa16(uint32_t dst, const void* src, uint32_t vsz) {
    asm volatile("cp.async.cg.shared.global [%0], [%1], 16, %2;"
                 :: "r"(dst), "l"(src), "r"(vsz) : "memory");
}
#define CP_COMMIT() asm volatile("cp.async.commit_group;" ::: "memory")
#define CP_WAIT0()  asm volatile("cp.async.wait_group 0;" ::: "memory")
#define CP_WAIT1()  asm volatile("cp.async.wait_group 1;" ::: "memory")

#define MMA16816(c, a0, a1, a2, a3, b0, b1) \
    asm volatile("mma.sync.aligned.m16n8k16.row.col.f32.f16.f16.f32 " \
        "{%0,%1,%2,%3}, {%4,%5,%6,%7}, {%8,%9}, {%0,%1,%2,%3};" \
        : "+f"((c)[0]), "+f"((c)[1]), "+f"((c)[2]), "+f"((c)[3]) \
        : "r"(a0), "r"(a1), "r"(a2), "r"(a3), "r"(b0), "r"(b1))

#define LDSM4(r0, r1, r2, r3, addr) \
    asm volatile("ldmatrix.sync.aligned.m8n8.x4.shared.b16 {%0,%1,%2,%3}, [%4];" \
        : "=r"(r0), "=r"(r1), "=r"(r2), "=r"(r3) : "r"(addr))

// ------------------------- scratch (static device globals) -----------------
#define OFF_CONV 0ul
#define OFF_QKV  589824ul
#define OFF_OUT  21823488ul
#define OFF_FC   28901376ul
#define OFF_PROJ 57212928ul
#define WTOT     85524480ul

__device__ __align__(16) __half g_w[WTOT];         // fp16 weights
__device__ __align__(16) __half g_xp[NPROW * Dm];  // fp16 patch matrix
__device__ __align__(16) float g_pe[NPROW * Dm];
__device__ __align__(16) float g_x [NTOK * Dm];    // fp32 residual stream
__device__ __align__(16) __half g_h[NTOK * Dm];    // fp16 LN output
__device__ __align__(16) __half g_qkvh[NTOK * 3 * Dm]; // fp16 qkv
__device__ __align__(16) __half g_ao[NTOK * Dm];   // fp16 attn out
__device__ __align__(16) __half g_mlp[NTOK * Ff];  // fp16 mlp hidden
__device__ __align__(16) float g_cls[Bsz * Dm];

// ------------------------- weight fp32 -> fp16 -----------------------------
__global__ void k_cvt(const float4* __restrict__ src, __half2* __restrict__ w, long n4)
{
    long i = (long)blockIdx.x * blockDim.x + threadIdx.x;
    if (i >= n4) return;
    float4 v = src[i];
    w[2 * i]     = __floats2half2_rn(v.x, v.y);
    w[2 * i + 1] = __floats2half2_rn(v.z, v.w);
}

// ------------------------- patchify + normalize -> fp16 --------------------
__global__ void k_patchify(const float* __restrict__ img, __half* __restrict__ xh)
{
    const float mean[3] = {0.48145466f, 0.4578275f, 0.40821073f};
    const float istd[3] = {1.f/0.26862954f, 1.f/0.26130258f, 1.f/0.27577711f};
    int idx = blockIdx.x * blockDim.x + threadIdx.x;
    if (idx >= NPROW * Dm) return;
    int col = idx % Dm;
    int row = idx / Dm;
    int b  = row / NPATCH;
    int p  = row % NPATCH;
    int py = p / 14, px = p % 14;
    int c  = col >> 8;
    int rem = col & 255;
    int ph = rem >> 4, pw = rem & 15;
    float v = img[(((size_t)b * 3 + c) * 224 + py * 16 + ph) * 224 + px * 16 + pw];
    xh[idx] = __float2half((v - mean[c]) * istd[c]);
}

// ------------------------- mma.sync fp16 GEMM ------------------------------
// C[M,N] = A[M,K] @ W[N,K]^T (+bias)(+QuickGELU)(+res). N%128==0, K%64==0.
#define STG_MAT   18432            // 128 rows * 144 B
#define STG_BYTES 36864            // 2 matrices (A, B)
#define MM_SMEM   (3 * STG_BYTES)  // 110592

template<bool BIAS, bool RES, bool GELU_, bool F16O>
__global__ __launch_bounds__(256) void k_mm(
    const __half* __restrict__ A, const __half* __restrict__ B,
    const float* __restrict__ bias, const float* __restrict__ resi,
    float* __restrict__ C, __half* __restrict__ Ch,
    int M, int N, int K)
{
    extern __shared__ char smc[];
    const uint32_t sb = smem_u32(smc);
    const int tid = threadIdx.x, lane = tid & 31, wid = tid >> 5;
    const int warp_m = wid & 3, warp_n = wid >> 2;
    const int bm = blockIdx.y * 128, bn = blockIdx.x * 128;
    const int Kd8 = K >> 3, nch = K >> 6;

    const uint4* A4 = (const uint4*)A;
    const uint4* B4 = (const uint4*)B;

    float acc[2][8][4];
    #pragma unroll
    for (int a = 0; a < 2; a++)
        #pragma unroll
        for (int b = 0; b < 8; b++)
            #pragma unroll
            for (int c = 0; c < 4; c++) acc[a][b][c] = 0.f;

    auto load_chunk = [&](int i, int s) {
        int k0d8 = i << 3;
        uint32_t stg = sb + s * STG_BYTES;
        #pragma unroll
        for (int t = tid; t < 2048; t += 256) {
            int mat = t >> 10, r = (t >> 3) & 127, c8 = t & 7;
            uint32_t dst = stg + mat * STG_MAT + r * 144 + c8 * 16;
            if (mat == 0) {
                int grow = bm + r;
                int ok = grow < M;
                const uint4* src = A4 + (size_t)(ok ? grow : 0) * Kd8 + k0d8 + c8;
                cpa16(dst, src, ok ? 16u : 0u);
            } else {
                const uint4* src = B4 + (size_t)(bn + r) * Kd8 + k0d8 + c8;
                cpa16(dst, src, 16u);
            }
        }
        CP_COMMIT();
    };

    load_chunk(0, 0);
    load_chunk(1, 1);

    const uint32_t aoff = (uint32_t)((warp_m * 32 + (lane & 15)) * 144 + ((lane >> 4) << 4));
    const int brow = (lane & 7) + ((lane >> 4) << 3);
    const uint32_t boff = (uint32_t)(STG_MAT + (warp_n * 64 + brow) * 144
                                     + (((lane >> 3) & 1) << 4));

    int s = 0;
    for (int i = 0; i < nch; i++) {
        if (i + 1 < nch) CP_WAIT1(); else CP_WAIT0();
        __syncthreads();
        if (i + 2 < nch) {
            int s2 = s + 2; if (s2 >= 3) s2 -= 3;
            load_chunk(i + 2, s2);
        }
        uint32_t stg = sb + s * STG_BYTES;
        uint32_t aA = stg + aoff, bB = stg + boff;
        #pragma unroll
        for (int k16 = 0; k16 < 4; k16++) {
            uint32_t ah[2][4], bf[4][4];
            #pragma unroll
            for (int mf = 0; mf < 2; mf++)
                LDSM4(ah[mf][0], ah[mf][1], ah[mf][2], ah[mf][3],
                      aA + mf * (16 * 144) + k16 * 32);
            #pragma unroll
            for (int p = 0; p < 4; p++)
                LDSM4(bf[p][0], bf[p][1], bf[p][2], bf[p][3],
                      bB + p * (16 * 144) + k16 * 32);
            #pragma unroll
            for (int p = 0; p < 4; p++)
                #pragma unroll
                for (int sub = 0; sub < 2; sub++)
                    #pragma unroll
                    for (int mf = 0; mf < 2; mf++)
                        MMA16816(acc[mf][p * 2 + sub],
                                 ah[mf][0], ah[mf][1], ah[mf][2], ah[mf][3],
                                 bf[p][2 * sub], bf[p][2 * sub + 1]);
        }
        s++; if (s == 3) s = 0;
    }

    // ---- epilogue (paired stores) ----
    const int qrow = lane >> 2;
    #pragma unroll
    for (int mf = 0; mf < 2; mf++) {
        #pragma unroll
        for (int nf = 0; nf < 8; nf++) {
            int col = bn + warp_n * 64 + nf * 8 + ((lane & 3) << 1);
            float b0 = 0.f, b1 = 0.f;
            if (BIAS) { b0 = bias[col]; b1 = bias[col + 1]; }
            #pragma unroll
            for (int er = 0; er < 2; er++) {
                int row = bm + warp_m * 32 + mf * 16 + qrow + er * 8;
                if (row >= M) continue;
                float v0 = acc[mf][nf][er * 2 + 0] + b0;
                float v1 = acc[mf][nf][er * 2 + 1] + b1;
                if (GELU_) {
                    v0 = v0 / (1.f + __expf(-1.702f * v0));
                    v1 = v1 / (1.f + __expf(-1.702f * v1));
                }
                if (RES) {
                    float2 rr = *(const float2*)(resi + (size_t)row * N + col);
                    v0 += rr.x; v1 += rr.y;
                }
                if (F16O) {
                    *(__half2*)(Ch + (size_t)row * N + col) = __floats2half2_rn(v0, v1);
                } else {
                    float2 o; o.x = v0; o.y = v1;
                    *(float2*)(C + (size_t)row * N + col) = o;
                }
            }
        }
    }
}

// ------------------------- tensor-core attention ---------------------------
// one CTA per (b, head), 8 warps. fp16 qkv in gmem. V transposed in smem.
#define ATT_SMEM 87552  // Q 208x72 + K 208x72 + Vt 64x216 halves

__global__ __launch_bounds__(256) void k_attn(const __half* __restrict__ QKV,
                                              __half* __restrict__ out)
{
    extern __shared__ __half sm[];
    __half* Qs = sm;             // 208 rows x 72 halves (144 B stride)
    __half* Ks = sm + 14976;     // 208 x 72
    __half* Vt = sm + 29952;     // 64 x 216 halves (432 B stride)
    const int bh = blockIdx.x, b = bh / Hh, h = bh % Hh;
    const int tid = threadIdx.x, lane = tid & 31, wid = tid >> 5;

    // zero ONLY the Vt pad columns (padded keys have P==0 exactly; 0*garbage
    // would still poison output if garbage were NaN). Q/K pad rows are either
    // masked (K) or never stored (Q).
    for (int i = tid; i < 64 * 19; i += 256) {
        int d = i / 19, s_ = 197 + i % 19;
        Vt[d * 216 + s_] = __ushort_as_half(0);
    }

    const __half* qp = QKV + (size_t)b * Ss * (3 * Dm) + h * HD;
    const __half2 qscale = __float2half2_rn(0.125f);
    for (int idx = tid; idx < Ss * 8; idx += 256) {
        int s_ = idx >> 3, c8 = idx & 7;
        const uint4* row = (const uint4*)(qp + (size_t)s_ * (3 * Dm));
        uint4 qv = row[c8];
        uint4 kv = row[Dm / 8 + c8];
        uint4 vv = row[2 * Dm / 8 + c8];
        __half2* q2 = (__half2*)&qv;
        #pragma unroll
        for (int j = 0; j < 4; j++) q2[j] = __hmul2(q2[j], qscale);
        *(uint4*)(Qs + s_ * 72 + c8 * 8) = qv;
        *(uint4*)(Ks + s_ * 72 + c8 * 8) = kv;
        __half* hv = (__half*)&vv;
        #pragma unroll
        for (int j = 0; j < 8; j++) Vt[(c8 * 8 + j) * 216 + s_] = hv[j];
    }
    __syncthreads();

    const uint32_t qsb = smem_u32(Qs), ksb = smem_u32(Ks), vtb = smem_u32(Vt);
    const uint32_t arow = (uint32_t)((lane & 15) * 144 + ((lane >> 4) << 4));
    const uint32_t brow = (uint32_t)(((lane & 7) + ((lane >> 4) << 3)) * 144
                                     + (((lane >> 3) & 1) << 4));
    const uint32_t vrow = (uint32_t)(((lane & 7) + ((lane >> 4) << 3)) * 432
                                     + (((lane >> 3) & 1) << 4));
    const int r = lane >> 2, cq = (lane & 3) << 1;

    for (int qt = wid; qt < 13; qt += 8) {
        float sacc[26][4];
        #pragma unroll
        for (int f = 0; f < 26; f++)
            #pragma unroll
            for (int e = 0; e < 4; e++) sacc[f][e] = 0.f;
        #pragma unroll
        for (int k16 = 0; k16 < 4; k16++) {
            uint32_t aq0, aq1, aq2, aq3;
            LDSM4(aq0, aq1, aq2, aq3, qsb + qt * (16 * 144) + arow + k16 * 32);
            #pragma unroll
            for (int p = 0; p < 13; p++) {
                uint32_t kb[4];
                LDSM4(kb[0], kb[1], kb[2], kb[3], ksb + p * (16 * 144) + brow + k16 * 32);
                MMA16816(sacc[2 * p],     aq0, aq1, aq2, aq3, kb[0], kb[1]);
                MMA16816(sacc[2 * p + 1], aq0, aq1, aq2, aq3, kb[2], kb[3]);
            }
        }
        #pragma unroll
        for (int f = 0; f < 26; f++) {
            int c0 = 8 * f + cq;
            if (c0 >= Ss)     { sacc[f][0] = -1e30f; sacc[f][2] = -1e30f; }
            if (c0 + 1 >= Ss) { sacc[f][1] = -1e30f; sacc[f][3] = -1e30f; }
        }
        float mx0 = -1e30f, mx1 = -1e30f;
        #pragma unroll
        for (int f = 0; f < 26; f++) {
            mx0 = fmaxf(mx0, fmaxf(sacc[f][0], sacc[f][1]));
            mx1 = fmaxf(mx1, fmaxf(sacc[f][2], sacc[f][3]));
        }
        mx0 = fmaxf(mx0, __shfl_xor_sync(~0u, mx0, 1));
        mx0 = fmaxf(mx0, __shfl_xor_sync(~0u, mx0, 2));
        mx1 = fmaxf(mx1, __shfl_xor_sync(~0u, mx1, 1));
        mx1 = fmaxf(mx1, __shfl_xor_sync(~0u, mx1, 2));
        float sum0 = 0.f, sum1 = 0.f;
        #pragma unroll
        for (int f = 0; f < 26; f++) {
            sacc[f][0] = __expf(sacc[f][0] - mx0);
            sacc[f][1] = __expf(sacc[f][1] - mx0);
            sacc[f][2] = __expf(sacc[f][2] - mx1);
            sacc[f][3] = __expf(sacc[f][3] - mx1);
            sum0 += sacc[f][0] + sacc[f][1];
            sum1 += sacc[f][2] + sacc[f][3];
        }
        sum0 += __shfl_xor_sync(~0u, sum0, 1);
        sum0 += __shfl_xor_sync(~0u, sum0, 2);
        sum1 += __shfl_xor_sync(~0u, sum1, 1);
        sum1 += __shfl_xor_sync(~0u, sum1, 2);
        float inv0 = 1.f / sum0, inv1 = 1.f / sum1;
        uint32_t pa[13][4];
        #pragma unroll
        for (int kk = 0; kk < 13; kk++) {
            __half2 t0 = __floats2half2_rn(sacc[2*kk][0] * inv0,   sacc[2*kk][1] * inv0);
            __half2 t1 = __floats2half2_rn(sacc[2*kk][2] * inv1,   sacc[2*kk][3] * inv1);
            __half2 t2 = __floats2half2_rn(sacc[2*kk+1][0] * inv0, sacc[2*kk+1][1] * inv0);
            __half2 t3 = __floats2half2_rn(sacc[2*kk+1][2] * inv1, sacc[2*kk+1][3] * inv1);
            pa[kk][0] = *(uint32_t*)&t0;
            pa[kk][1] = *(uint32_t*)&t1;
            pa[kk][2] = *(uint32_t*)&t2;
            pa[kk][3] = *(uint32_t*)&t3;
        }
        float oacc[8][4];
        #pragma unroll
        for (int f = 0; f < 8; f++)
            #pragma unroll
            for (int e = 0; e < 4; e++) oacc[f][e] = 0.f;
        #pragma unroll
        for (int kk = 0; kk < 13; kk++) {
            #pragma unroll
            for (int pv = 0; pv < 4; pv++) {
                uint32_t vb[4];
                LDSM4(vb[0], vb[1], vb[2], vb[3], vtb + pv * (16 * 432) + vrow + kk * 32);
                MMA16816(oacc[2 * pv],     pa[kk][0], pa[kk][1], pa[kk][2], pa[kk][3],
                         vb[0], vb[1]);
                MMA16816(oacc[2 * pv + 1], pa[kk][0], pa[kk][1], pa[kk][2], pa[kk][3],
                         vb[2], vb[3]);
            }
        }
        #pragma unroll
        for (int f = 0; f < 8; f++) {
            int d = 8 * f + cq;
            #pragma unroll
            for (int er = 0; er < 2; er++) {
                int q = qt * 16 + r + er * 8;
                if (q < Ss)
                    *(__half2*)(out + ((size_t)(b * Ss + q)) * Dm + h * HD + d)
                        = __floats2half2_rn(oacc[f][er * 2], oacc[f][er * 2 + 1]);
            }
        }
    }
}

// ------------------------- warp-per-row LayerNorm --------------------------
// 8 warps/block, one row of 768 per warp, float4 I/O.
template<bool F16>
__global__ __launch_bounds__(256) void k_ln(
    const float* __restrict__ in, float* __restrict__ outf, __half* __restrict__ oh,
    const float* __restrict__ sc, const float* __restrict__ bi,
    long in_stride, long out_stride, int nrows)
{
    int row = blockIdx.x * 8 + (threadIdx.x >> 5);
    if (row >= nrows) return;
    int lane = threadIdx.x & 31;
    const float4* ip = (const float4*)(in + (size_t)row * in_stride);
    float4 v[6];
    float s = 0.f, sq = 0.f;
    #pragma unroll
    for (int j = 0; j < 6; j++) {
        v[j] = ip[j * 32 + lane];
        s  += v[j].x + v[j].y + v[j].z + v[j].w;
        sq += v[j].x*v[j].x + v[j].y*v[j].y + v[j].z*v[j].z + v[j].w*v[j].w;
    }
    #pragma unroll
    for (int o = 16; o > 0; o >>= 1) {
        s  += __shfl_xor_sync(~0u, s, o);
        sq += __shfl_xor_sync(~0u, sq, o);
    }
    float mean = s * (1.f / Dm);
    float var  = sq * (1.f / Dm) - mean * mean;
    float r = rsqrtf(var + 1e-5f);
    const float4* sc4 = (const float4*)sc;
    const float4* bi4 = (const float4*)bi;
    #pragma unroll
    for (int j = 0; j < 6; j++) {
        float4 g = sc4[j * 32 + lane], be = bi4[j * 32 + lane];
        float y0 = (v[j].x - mean) * r * g.x + be.x;
        float y1 = (v[j].y - mean) * r * g.y + be.y;
        float y2 = (v[j].z - mean) * r * g.z + be.z;
        float y3 = (v[j].w - mean) * r * g.w + be.w;
        if (F16) {
            __half2 h0 = __floats2half2_rn(y0, y1);
            __half2 h1 = __floats2half2_rn(y2, y3);
            uint2 pk; pk.x = *(uint32_t*)&h0; pk.y = *(uint32_t*)&h1;
            ((uint2*)(oh + (size_t)row * out_stride))[j * 32 + lane] = pk;
        } else {
            float4 o; o.x = y0; o.y = y1; o.z = y2; o.w = y3;
            ((float4*)(outf + (size_t)row * out_stride))[j * 32 + lane] = o;
        }
    }
}

// --------------- fused assemble (cls+patch+pos) + ln_pre -> x --------------
__global__ __launch_bounds__(256) void k_asmln(
    const float* __restrict__ pe, const float* __restrict__ cls,
    const float* __restrict__ pos,
    const float* __restrict__ sc, const float* __restrict__ bi,
    float* __restrict__ x)
{
    int t = blockIdx.x * 8 + (threadIdx.x >> 5);
    if (t >= NTOK) return;
    int lane = threadIdx.x & 31;
    int s_ = t % Ss, b = t / Ss;
    const float4* src4 = (s_ == 0) ? (const float4*)cls
                       : (const float4*)(pe + (size_t)(b * NPATCH + s_ - 1) * Dm);
    const float4* pos4 = (const float4*)(pos + (size_t)s_ * Dm);
    float4 v[6];
    float s = 0.f, sq = 0.f;
    #pragma unroll
    for (int j = 0; j < 6; j++) {
        float4 a = src4[j * 32 + lane], p = pos4[j * 32 + lane];
        v[j].x = a.x + p.x; v[j].y = a.y + p.y; v[j].z = a.z + p.z; v[j].w = a.w + p.w;
        s  += v[j].x + v[j].y + v[j].z + v[j].w;
        sq += v[j].x*v[j].x + v[j].y*v[j].y + v[j].z*v[j].z + v[j].w*v[j].w;
    }
    #pragma unroll
    for (int o = 16; o > 0; o >>= 1) {
        s  += __shfl_xor_sync(~0u, s, o);
        sq += __shfl_xor_sync(~0u, sq, o);
    }
    float mean = s * (1.f / Dm);
    float var  = sq * (1.f / Dm) - mean * mean;
    float r = rsqrtf(var + 1e-5f);
    const float4* sc4 = (const float4*)sc;
    const float4* bi4 = (const float4*)bi;
    #pragma unroll
    for (int j = 0; j < 6; j++) {
        float4 g = sc4[j * 32 + lane], be = bi4[j * 32 + lane];
        float4 o;
        o.x = (v[j].x - mean) * r * g.x + be.x;
        o.y = (v[j].y - mean) * r * g.y + be.y;
        o.z = (v[j].z - mean) * r * g.z + be.z;
        o.w = (v[j].w - mean) * r * g.w + be.w;
        ((float4*)(x + (size_t)t * Dm))[j * 32 + lane] = o;
    }
}

// ------------------------- head: cls_ln @ vis_proj -------------------------
__global__ __launch_bounds__(512) void k_head(const float* __restrict__ cls,
                                              const float* __restrict__ Wp,
                                              float* __restrict__ out)
{
    __shared__ float row[Dm];
    int b = blockIdx.x;
    for (int i = threadIdx.x; i < Dm; i += 512) row[i] = cls[(size_t)b * Dm + i];
    __syncthreads();
    int o = threadIdx.x;
    float acc = 0.f;
    for (int d = 0; d < Dm; d++) acc += row[d] * Wp[(size_t)d * Oo + o];
    out[(size_t)b * Oo + o] = acc;
}

// ---------------------------------------------------------------------------
extern "C" void kernel_launch(void* const* d_in, const int* in_sizes, int n_in,
                              void* d_out, int out_size)
{
    const float* images   = (const float*)d_in[0];
    const float* conv_w   = (const float*)d_in[1];
    const float* cls_emb  = (const float*)d_in[2];
    const float* pos_emb  = (const float*)d_in[3];
    const float* ln_pre_s = (const float*)d_in[4];
    const float* ln_pre_b = (const float*)d_in[5];
    const float* ln1_s    = (const float*)d_in[6];
    const float* ln1_b    = (const float*)d_in[7];
    const float* qkv_w    = (const float*)d_in[8];
    const float* qkv_b    = (const float*)d_in[9];
    const float* out_w    = (const float*)d_in[10];
    const float* out_b    = (const float*)d_in[11];
    const float* ln2_s    = (const float*)d_in[12];
    const float* ln2_b    = (const float*)d_in[13];
    const float* fc_w     = (const float*)d_in[14];
    const float* fc_b     = (const float*)d_in[15];
    const float* proj_w   = (const float*)d_in[16];
    const float* proj_b   = (const float*)d_in[17];
    const float* lnp_s    = (const float*)d_in[18];
    const float* lnp_b    = (const float*)d_in[19];
    const float* vis_proj = (const float*)d_in[20];
    float* outp = (float*)d_out;

    __half *w, *xp, *h, *qkvh, *ao, *mlp;
    float *pe, *x, *cls;
    cudaGetSymbolAddress((void**)&w,    g_w);
    cudaGetSymbolAddress((void**)&xp,   g_xp);
    cudaGetSymbolAddress((void**)&pe,   g_pe);
    cudaGetSymbolAddress((void**)&x,    g_x);
    cudaGetSymbolAddress((void**)&h,    g_h);
    cudaGetSymbolAddress((void**)&qkvh, g_qkvh);
    cudaGetSymbolAddress((void**)&ao,   g_ao);
    cudaGetSymbolAddress((void**)&mlp,  g_mlp);
    cudaGetSymbolAddress((void**)&cls,  g_cls);

    cudaFuncSetAttribute(k_mm<false,false,false,false>, cudaFuncAttributeMaxDynamicSharedMemorySize, MM_SMEM);
    cudaFuncSetAttribute(k_mm<true, false,false,true >, cudaFuncAttributeMaxDynamicSharedMemorySize, MM_SMEM);
    cudaFuncSetAttribute(k_mm<true, true, false,false>, cudaFuncAttributeMaxDynamicSharedMemorySize, MM_SMEM);
    cudaFuncSetAttribute(k_mm<true, false,true, true >, cudaFuncAttributeMaxDynamicSharedMemorySize, MM_SMEM);
    cudaFuncSetAttribute(k_attn, cudaFuncAttributeMaxDynamicSharedMemorySize, ATT_SMEM);

    // ---- weight fp32 -> fp16 ----
    {
        long n4;
        n4 = 589824 / 4;
        k_cvt<<<(n4 + 255) / 256, 256>>>((const float4*)conv_w, (__half2*)(w + OFF_CONV), n4);
        n4 = 21233664 / 4;
        k_cvt<<<(n4 + 255) / 256, 256>>>((const float4*)qkv_w,  (__half2*)(w + OFF_QKV),  n4);
        n4 = 7077888 / 4;
        k_cvt<<<(n4 + 255) / 256, 256>>>((const float4*)out_w,  (__half2*)(w + OFF_OUT),  n4);
        n4 = 28311552 / 4;
        k_cvt<<<(n4 + 255) / 256, 256>>>((const float4*)fc_w,   (__half2*)(w + OFF_FC),   n4);
        n4 = 28311552 / 4;
        k_cvt<<<(n4 + 255) / 256, 256>>>((const float4*)proj_w, (__half2*)(w + OFF_PROJ), n4);
    }

    // ---- stem ----
    k_patchify<<<(NPROW * Dm + 255) / 256, 256>>>(images, xp);
    k_mm<false,false,false,false><<<dim3(Dm / 128, (NPROW + 127) / 128), 256, MM_SMEM>>>(
        xp, w + OFF_CONV, nullptr, nullptr, pe, nullptr, NPROW, Dm, Dm);
    k_asmln<<<(NTOK + 7) / 8, 256>>>(pe, cls_emb, pos_emb, ln_pre_s, ln_pre_b, x);

    // ---- transformer layers ----
    for (int l = 0; l < Ll; l++) {
        const float* l1s = ln1_s + (size_t)l * Dm;
        const float* l1b = ln1_b + (size_t)l * Dm;
        const float* qb  = qkv_b + (size_t)l * 3 * Dm;
        const float* ob  = out_b + (size_t)l * Dm;
        const float* l2s = ln2_s + (size_t)l * Dm;
        const float* l2b = ln2_b + (size_t)l * Dm;
        const float* fb  = fc_b  + (size_t)l * Ff;
        const float* pb  = proj_b + (size_t)l * Dm;
        const __half* qw = w + OFF_QKV  + (size_t)l * 2304 * 768;
        const __half* ow = w + OFF_OUT  + (size_t)l * 768 * 768;
        const __half* fw = w + OFF_FC   + (size_t)l * 3072 * 768;
        const __half* pw = w + OFF_PROJ + (size_t)l * 768 * 3072;

        k_ln<true><<<(NTOK + 7) / 8, 256>>>(x, nullptr, h, l1s, l1b, Dm, Dm, NTOK);
        k_mm<true,false,false,true><<<dim3(3 * Dm / 128, (NTOK + 127) / 128), 256, MM_SMEM>>>(
            h, qw, qb, nullptr, nullptr, qkvh, NTOK, 3 * Dm, Dm);
        k_attn<<<Bsz * Hh, 256, ATT_SMEM>>>(qkvh, ao);
        k_mm<true,true,false,false><<<dim3(Dm / 128, (NTOK + 127) / 128), 256, MM_SMEM>>>(
            ao, ow, ob, x, x, nullptr, NTOK, Dm, Dm);
        k_ln<true><<<(NTOK + 7) / 8, 256>>>(x, nullptr, h, l2s, l2b, Dm, Dm, NTOK);
        k_mm<true,false,true,true><<<dim3(Ff / 128, (NTOK + 127) / 128), 256, MM_SMEM>>>(
            h, fw, fb, nullptr, nullptr, mlp, NTOK, Ff, Dm);
        k_mm<true,true,false,false><<<dim3(Dm / 128, (NTOK + 127) / 128), 256, MM_SMEM>>>(
            mlp, pw, pb, x, x, nullptr, NTOK, Dm, Ff);
    }

    // ---- head ----
    k_ln<false><<<4, 256>>>(x, cls, nullptr, lnp_s, lnp_b, (long)Ss * Dm, Dm, Bsz);
    k_head<<<Bsz, 512>>>(cls, vis_proj, outp);
}

// round 11
// speedup vs baseline: 12.1018x; 1.0050x over previous
#include <cuda_runtime.h>
#include <cuda_fp16.h>
#include <math.h>
#include <cstdint>

// ---------------------------------------------------------------------------
// CLIP ViT-B/16 visual tower on GB300 — 1-term fp16 mma.sync GEMMs (occ=2)
// + tensor-core attention + vectorized warp-per-row LN / fused stem.
// ---------------------------------------------------------------------------

#define Bsz 32
#define Dm  768
#define Hh  12
#define HD  64
#define Ff  3072
#define Ll  12
#define Ss  197
#define Oo  512
#define NPATCH 196
#define NTOK (Bsz * Ss)        // 6304
#define NPROW (Bsz * NPATCH)   // 6272

// ------------------------- helpers -----------------------------------------
__device__ __forceinline__ uint32_t smem_u32(const void* p) {
    uint32_t a;
    asm("{ .reg .u64 t; cvta.to.shared.u64 t, %1; cvt.u32.u64 %0, t; }"
        : "=r"(a) : "l"(p));
    return a;
}
__device__ __forceinline__ void cpa16(uint32_t dst, const void* src, uint32_t vsz) {
    asm volatile("cp.async.cg.shared.global [%0], [%1], 16, %2;"
                 :: "r"(dst), "l"(src), "r"(vsz) : "memory");
}
#define CP_COMMIT() asm volatile("cp.async.commit_group;" ::: "memory")
#define CP_WAIT0()  asm volatile("cp.async.wait_group 0;" ::: "memory")
#define CP_WAIT1()  asm volatile("cp.async.wait_group 1;" ::: "memory")

#define MMA16816(c, a0, a1, a2, a3, b0, b1) \
    asm volatile("mma.sync.aligned.m16n8k16.row.col.f32.f16.f16.f32 " \
        "{%0,%1,%2,%3}, {%4,%5,%6,%7}, {%8,%9}, {%0,%1,%2,%3};" \
        : "+f"((c)[0]), "+f"((c)[1]), "+f"((c)[2]), "+f"((c)[3]) \
        : "r"(a0), "r"(a1), "r"(a2), "r"(a3), "r"(b0), "r"(b1))

#define LDSM4(r0, r1, r2, r3, addr) \
    asm volatile("ldmatrix.sync.aligned.m8n8.x4.shared.b16 {%0,%1,%2,%3}, [%4];" \
        : "=r"(r0), "=r"(r1), "=r"(r2), "=r"(r3) : "r"(addr))

// ------------------------- scratch (static device globals) -----------------
#define OFF_CONV 0ul
#define OFF_QKV  589824ul
#define OFF_OUT  21823488ul
#define OFF_FC   28901376ul
#define OFF_PROJ 57212928ul
#define WTOT     85524480ul

__device__ __align__(16) __half g_w[WTOT];         // fp16 weights
__device__ __align__(16) __half g_xp[NPROW * Dm];  // fp16 patch matrix
__device__ __align__(16) float g_pe[NPROW * Dm];
__device__ __align__(16) float g_x [NTOK * Dm];    // fp32 residual stream
__device__ __align__(16) __half g_h[NTOK * Dm];    // fp16 LN output
__device__ __align__(16) __half g_qkvh[NTOK * 3 * Dm]; // fp16 qkv
__device__ __align__(16) __half g_ao[NTOK * Dm];   // fp16 attn out
__device__ __align__(16) __half g_mlp[NTOK * Ff];  // fp16 mlp hidden
__device__ __align__(16) float g_cls[Bsz * Dm];

// --------------- all weights fp32 -> fp16, one kernel ----------------------
// segment sizes in float4 units (compile-time)
#define F4_CONV (589824 / 4)
#define F4_QKV  (21233664 / 4)
#define F4_OUT  (7077888 / 4)
#define F4_FC   (28311552 / 4)
#define F4_PROJ (28311552 / 4)
#define F4_TOT  (F4_CONV + F4_QKV + F4_OUT + F4_FC + F4_PROJ)

__global__ __launch_bounds__(256) void k_cvt_all(
    const float4* __restrict__ s_conv, const float4* __restrict__ s_qkv,
    const float4* __restrict__ s_out,  const float4* __restrict__ s_fc,
    const float4* __restrict__ s_proj, __half2* __restrict__ w)
{
    long i = (long)blockIdx.x * blockDim.x + threadIdx.x;
    if (i >= F4_TOT) return;
    const float4* src;
    long loc; unsigned long dst;
    if (i < F4_CONV) { src = s_conv; loc = i; dst = OFF_CONV / 2 + loc * 2; }
    else if (i < F4_CONV + F4_QKV) { src = s_qkv; loc = i - F4_CONV; dst = OFF_QKV / 2 + loc * 2; }
    else if (i < F4_CONV + F4_QKV + F4_OUT) { src = s_out; loc = i - F4_CONV - F4_QKV; dst = OFF_OUT / 2 + loc * 2; }
    else if (i < F4_CONV + F4_QKV + F4_OUT + F4_FC) { src = s_fc; loc = i - F4_CONV - F4_QKV - F4_OUT; dst = OFF_FC / 2 + loc * 2; }
    else { src = s_proj; loc = i - F4_CONV - F4_QKV - F4_OUT - F4_FC; dst = OFF_PROJ / 2 + loc * 2; }
    float4 v = src[loc];
    w[dst]     = __floats2half2_rn(v.x, v.y);
    w[dst + 1] = __floats2half2_rn(v.z, v.w);
}

// ------------------------- patchify + normalize -> fp16 --------------------
__global__ void k_patchify(const float* __restrict__ img, __half* __restrict__ xh)
{
    const float mean[3] = {0.48145466f, 0.4578275f, 0.40821073f};
    const float istd[3] = {1.f/0.26862954f, 1.f/0.26130258f, 1.f/0.27577711f};
    int idx = blockIdx.x * blockDim.x + threadIdx.x;
    if (idx >= NPROW * Dm) return;
    int col = idx % Dm;
    int row = idx / Dm;
    int b  = row / NPATCH;
    int p  = row % NPATCH;
    int py = p / 14, px = p % 14;
    int c  = col >> 8;
    int rem = col & 255;
    int ph = rem >> 4, pw = rem & 15;
    float v = img[(((size_t)b * 3 + c) * 224 + py * 16 + ph) * 224 + px * 16 + pw];
    xh[idx] = __float2half((v - mean[c]) * istd[c]);
}

// ------------------------- mma.sync fp16 GEMM (occ=2) ----------------------
// C[M,N] = A[M,K] @ W[N,K]^T (+bias)(+QuickGELU)(+res). N%128==0, K%64==0.
#define STG_MAT   18432            // 128 rows * 144 B
#define STG_BYTES 36864            // 2 matrices (A, B)
#define MM_SMEM   (3 * STG_BYTES)  // 110592

template<bool BIAS, bool RES, bool GELU_, bool F16O>
__global__ __launch_bounds__(256, 2) void k_mm(
    const __half* __restrict__ A, const __half* __restrict__ B,
    const float* __restrict__ bias, const float* __restrict__ resi,
    float* __restrict__ C, __half* __restrict__ Ch,
    int M, int N, int K)
{
    extern __shared__ char smc[];
    const uint32_t sb = smem_u32(smc);
    const int tid = threadIdx.x, lane = tid & 31, wid = tid >> 5;
    const int warp_m = wid & 3, warp_n = wid >> 2;
    const int bm = blockIdx.y * 128, bn = blockIdx.x * 128;
    const int Kd8 = K >> 3, nch = K >> 6;

    const uint4* A4 = (const uint4*)A;
    const uint4* B4 = (const uint4*)B;

    float acc[2][8][4];
    #pragma unroll
    for (int a = 0; a < 2; a++)
        #pragma unroll
        for (int b = 0; b < 8; b++)
            #pragma unroll
            for (int c = 0; c < 4; c++) acc[a][b][c] = 0.f;

    auto load_chunk = [&](int i, int s) {
        int k0d8 = i << 3;
        uint32_t stg = sb + s * STG_BYTES;
        #pragma unroll
        for (int t = tid; t < 2048; t += 256) {
            int mat = t >> 10, r = (t >> 3) & 127, c8 = t & 7;
            uint32_t dst = stg + mat * STG_MAT + r * 144 + c8 * 16;
            if (mat == 0) {
                int grow = bm + r;
                int ok = grow < M;
                const uint4* src = A4 + (size_t)(ok ? grow : 0) * Kd8 + k0d8 + c8;
                cpa16(dst, src, ok ? 16u : 0u);
            } else {
                const uint4* src = B4 + (size_t)(bn + r) * Kd8 + k0d8 + c8;
                cpa16(dst, src, 16u);
            }
        }
        CP_COMMIT();
    };

    load_chunk(0, 0);
    load_chunk(1, 1);

    const uint32_t aoff = (uint32_t)((warp_m * 32 + (lane & 15)) * 144 + ((lane >> 4) << 4));
    const int brow = (lane & 7) + ((lane >> 4) << 3);
    const uint32_t boff = (uint32_t)(STG_MAT + (warp_n * 64 + brow) * 144
                                     + (((lane >> 3) & 1) << 4));

    int s = 0;
    for (int i = 0; i < nch; i++) {
        if (i + 1 < nch) CP_WAIT1(); else CP_WAIT0();
        __syncthreads();
        if (i + 2 < nch) {
            int s2 = s + 2; if (s2 >= 3) s2 -= 3;
            load_chunk(i + 2, s2);
        }
        uint32_t stg = sb + s * STG_BYTES;
        uint32_t aA = stg + aoff, bB = stg + boff;
        #pragma unroll
        for (int k16 = 0; k16 < 4; k16++) {
            uint32_t ah[2][4], bf[4][4];
            #pragma unroll
            for (int mf = 0; mf < 2; mf++)
                LDSM4(ah[mf][0], ah[mf][1], ah[mf][2], ah[mf][3],
                      aA + mf * (16 * 144) + k16 * 32);
            #pragma unroll
            for (int p = 0; p < 4; p++)
                LDSM4(bf[p][0], bf[p][1], bf[p][2], bf[p][3],
                      bB + p * (16 * 144) + k16 * 32);
            #pragma unroll
            for (int p = 0; p < 4; p++)
                #pragma unroll
                for (int sub = 0; sub < 2; sub++)
                    #pragma unroll
                    for (int mf = 0; mf < 2; mf++)
                        MMA16816(acc[mf][p * 2 + sub],
                                 ah[mf][0], ah[mf][1], ah[mf][2], ah[mf][3],
                                 bf[p][2 * sub], bf[p][2 * sub + 1]);
        }
        s++; if (s == 3) s = 0;
    }

    // ---- epilogue (paired stores) ----
    const int qrow = lane >> 2;
    #pragma unroll
    for (int mf = 0; mf < 2; mf++) {
        #pragma unroll
        for (int nf = 0; nf < 8; nf++) {
            int col = bn + warp_n * 64 + nf * 8 + ((lane & 3) << 1);
            float b0 = 0.f, b1 = 0.f;
            if (BIAS) { b0 = bias[col]; b1 = bias[col + 1]; }
            #pragma unroll
            for (int er = 0; er < 2; er++) {
                int row = bm + warp_m * 32 + mf * 16 + qrow + er * 8;
                if (row >= M) continue;
                float v0 = acc[mf][nf][er * 2 + 0] + b0;
                float v1 = acc[mf][nf][er * 2 + 1] + b1;
                if (GELU_) {
                    v0 = v0 / (1.f + __expf(-1.702f * v0));
                    v1 = v1 / (1.f + __expf(-1.702f * v1));
                }
                if (RES) {
                    float2 rr = *(const float2*)(resi + (size_t)row * N + col);
                    v0 += rr.x; v1 += rr.y;
                }
                if (F16O) {
                    *(__half2*)(Ch + (size_t)row * N + col) = __floats2half2_rn(v0, v1);
                } else {
                    float2 o; o.x = v0; o.y = v1;
                    *(float2*)(C + (size_t)row * N + col) = o;
                }
            }
        }
    }
}

// ------------------------- tensor-core attention ---------------------------
#define ATT_SMEM 87552  // Q 208x72 + K 208x72 + Vt 64x216 halves

__global__ __launch_bounds__(256) void k_attn(const __half* __restrict__ QKV,
                                              __half* __restrict__ out)
{
    extern __shared__ __half sm[];
    __half* Qs = sm;             // 208 rows x 72 halves (144 B stride)
    __half* Ks = sm + 14976;     // 208 x 72
    __half* Vt = sm + 29952;     // 64 x 216 halves (432 B stride)
    const int bh = blockIdx.x, b = bh / Hh, h = bh % Hh;
    const int tid = threadIdx.x, lane = tid & 31, wid = tid >> 5;

    for (int i = tid; i < 64 * 19; i += 256) {
        int d = i / 19, s_ = 197 + i % 19;
        Vt[d * 216 + s_] = __ushort_as_half(0);
    }

    const __half* qp = QKV + (size_t)b * Ss * (3 * Dm) + h * HD;
    const __half2 qscale = __float2half2_rn(0.125f);
    for (int idx = tid; idx < Ss * 8; idx += 256) {
        int s_ = idx >> 3, c8 = idx & 7;
        const uint4* row = (const uint4*)(qp + (size_t)s_ * (3 * Dm));
        uint4 qv = row[c8];
        uint4 kv = row[Dm / 8 + c8];
        uint4 vv = row[2 * Dm / 8 + c8];
        __half2* q2 = (__half2*)&qv;
        #pragma unroll
        for (int j = 0; j < 4; j++) q2[j] = __hmul2(q2[j], qscale);
        *(uint4*)(Qs + s_ * 72 + c8 * 8) = qv;
        *(uint4*)(Ks + s_ * 72 + c8 * 8) = kv;
        __half* hv = (__half*)&vv;
        #pragma unroll
        for (int j = 0; j < 8; j++) Vt[(c8 * 8 + j) * 216 + s_] = hv[j];
    }
    __syncthreads();

    const uint32_t qsb = smem_u32(Qs), ksb = smem_u32(Ks), vtb = smem_u32(Vt);
    const uint32_t arow = (uint32_t)((lane & 15) * 144 + ((lane >> 4) << 4));
    const uint32_t brow = (uint32_t)(((lane & 7) + ((lane >> 4) << 3)) * 144
                                     + (((lane >> 3) & 1) << 4));
    const uint32_t vrow = (uint32_t)(((lane & 7) + ((lane >> 4) << 3)) * 432
                                     + (((lane >> 3) & 1) << 4));
    const int r = lane >> 2, cq = (lane & 3) << 1;

    for (int qt = wid; qt < 13; qt += 8) {
        float sacc[26][4];
        #pragma unroll
        for (int f = 0; f < 26; f++)
            #pragma unroll
            for (int e = 0; e < 4; e++) sacc[f][e] = 0.f;
        #pragma unroll
        for (int k16 = 0; k16 < 4; k16++) {
            uint32_t aq0, aq1, aq2, aq3;
            LDSM4(aq0, aq1, aq2, aq3, qsb + qt * (16 * 144) + arow + k16 * 32);
            #pragma unroll
            for (int p = 0; p < 13; p++) {
                uint32_t kb[4];
                LDSM4(kb[0], kb[1], kb[2], kb[3], ksb + p * (16 * 144) + brow + k16 * 32);
                MMA16816(sacc[2 * p],     aq0, aq1, aq2, aq3, kb[0], kb[1]);
                MMA16816(sacc[2 * p + 1], aq0, aq1, aq2, aq3, kb[2], kb[3]);
            }
        }
        #pragma unroll
        for (int f = 0; f < 26; f++) {
            int c0 = 8 * f + cq;
            if (c0 >= Ss)     { sacc[f][0] = -1e30f; sacc[f][2] = -1e30f; }
            if (c0 + 1 >= Ss) { sacc[f][1] = -1e30f; sacc[f][3] = -1e30f; }
        }
        float mx0 = -1e30f, mx1 = -1e30f;
        #pragma unroll
        for (int f = 0; f < 26; f++) {
            mx0 = fmaxf(mx0, fmaxf(sacc[f][0], sacc[f][1]));
            mx1 = fmaxf(mx1, fmaxf(sacc[f][2], sacc[f][3]));
        }
        mx0 = fmaxf(mx0, __shfl_xor_sync(~0u, mx0, 1));
        mx0 = fmaxf(mx0, __shfl_xor_sync(~0u, mx0, 2));
        mx1 = fmaxf(mx1, __shfl_xor_sync(~0u, mx1, 1));
        mx1 = fmaxf(mx1, __shfl_xor_sync(~0u, mx1, 2));
        float sum0 = 0.f, sum1 = 0.f;
        #pragma unroll
        for (int f = 0; f < 26; f++) {
            sacc[f][0] = __expf(sacc[f][0] - mx0);
            sacc[f][1] = __expf(sacc[f][1] - mx0);
            sacc[f][2] = __expf(sacc[f][2] - mx1);
            sacc[f][3] = __expf(sacc[f][3] - mx1);
            sum0 += sacc[f][0] + sacc[f][1];
            sum1 += sacc[f][2] + sacc[f][3];
        }
        sum0 += __shfl_xor_sync(~0u, sum0, 1);
        sum0 += __shfl_xor_sync(~0u, sum0, 2);
        sum1 += __shfl_xor_sync(~0u, sum1, 1);
        sum1 += __shfl_xor_sync(~0u, sum1, 2);
        float inv0 = 1.f / sum0, inv1 = 1.f / sum1;
        uint32_t pa[13][4];
        #pragma unroll
        for (int kk = 0; kk < 13; kk++) {
            __half2 t0 = __floats2half2_rn(sacc[2*kk][0] * inv0,   sacc[2*kk][1] * inv0);
            __half2 t1 = __floats2half2_rn(sacc[2*kk][2] * inv1,   sacc[2*kk][3] * inv1);
            __half2 t2 = __floats2half2_rn(sacc[2*kk+1][0] * inv0, sacc[2*kk+1][1] * inv0);
            __half2 t3 = __floats2half2_rn(sacc[2*kk+1][2] * inv1, sacc[2*kk+1][3] * inv1);
            pa[kk][0] = *(uint32_t*)&t0;
            pa[kk][1] = *(uint32_t*)&t1;
            pa[kk][2] = *(uint32_t*)&t2;
            pa[kk][3] = *(uint32_t*)&t3;
        }
        float oacc[8][4];
        #pragma unroll
        for (int f = 0; f < 8; f++)
            #pragma unroll
            for (int e = 0; e < 4; e++) oacc[f][e] = 0.f;
        #pragma unroll
        for (int kk = 0; kk < 13; kk++) {
            #pragma unroll
            for (int pv = 0; pv < 4; pv++) {
                uint32_t vb[4];
                LDSM4(vb[0], vb[1], vb[2], vb[3], vtb + pv * (16 * 432) + vrow + kk * 32);
                MMA16816(oacc[2 * pv],     pa[kk][0], pa[kk][1], pa[kk][2], pa[kk][3],
                         vb[0], vb[1]);
                MMA16816(oacc[2 * pv + 1], pa[kk][0], pa[kk][1], pa[kk][2], pa[kk][3],
                         vb[2], vb[3]);
            }
        }
        #pragma unroll
        for (int f = 0; f < 8; f++) {
            int d = 8 * f + cq;
            #pragma unroll
            for (int er = 0; er < 2; er++) {
                int q = qt * 16 + r + er * 8;
                if (q < Ss)
                    *(__half2*)(out + ((size_t)(b * Ss + q)) * Dm + h * HD + d)
                        = __floats2half2_rn(oacc[f][er * 2], oacc[f][er * 2 + 1]);
            }
        }
    }
}

// ------------------------- warp-per-row LayerNorm --------------------------
template<bool F16>
__global__ __launch_bounds__(256) void k_ln(
    const float* __restrict__ in, float* __restrict__ outf, __half* __restrict__ oh,
    const float* __restrict__ sc, const float* __restrict__ bi,
    long in_stride, long out_stride, int nrows)
{
    int row = blockIdx.x * 8 + (threadIdx.x >> 5);
    if (row >= nrows) return;
    int lane = threadIdx.x & 31;
    const float4* ip = (const float4*)(in + (size_t)row * in_stride);
    float4 v[6];
    float s = 0.f, sq = 0.f;
    #pragma unroll
    for (int j = 0; j < 6; j++) {
        v[j] = ip[j * 32 + lane];
        s  += v[j].x + v[j].y + v[j].z + v[j].w;
        sq += v[j].x*v[j].x + v[j].y*v[j].y + v[j].z*v[j].z + v[j].w*v[j].w;
    }
    #pragma unroll
    for (int o = 16; o > 0; o >>= 1) {
        s  += __shfl_xor_sync(~0u, s, o);
        sq += __shfl_xor_sync(~0u, sq, o);
    }
    float mean = s * (1.f / Dm);
    float var  = sq * (1.f / Dm) - mean * mean;
    float r = rsqrtf(var + 1e-5f);
    const float4* sc4 = (const float4*)sc;
    const float4* bi4 = (const float4*)bi;
    #pragma unroll
    for (int j = 0; j < 6; j++) {
        float4 g = sc4[j * 32 + lane], be = bi4[j * 32 + lane];
        float y0 = (v[j].x - mean) * r * g.x + be.x;
        float y1 = (v[j].y - mean) * r * g.y + be.y;
        float y2 = (v[j].z - mean) * r * g.z + be.z;
        float y3 = (v[j].w - mean) * r * g.w + be.w;
        if (F16) {
            __half2 h0 = __floats2half2_rn(y0, y1);
            __half2 h1 = __floats2half2_rn(y2, y3);
            uint2 pk; pk.x = *(uint32_t*)&h0; pk.y = *(uint32_t*)&h1;
            ((uint2*)(oh + (size_t)row * out_stride))[j * 32 + lane] = pk;
        } else {
            float4 o; o.x = y0; o.y = y1; o.z = y2; o.w = y3;
            ((float4*)(outf + (size_t)row * out_stride))[j * 32 + lane] = o;
        }
    }
}

// --------------- fused assemble (cls+patch+pos) + ln_pre -> x --------------
__global__ __launch_bounds__(256) void k_asmln(
    const float* __restrict__ pe, const float* __restrict__ cls,
    const float* __restrict__ pos,
    const float* __restrict__ sc, const float* __restrict__ bi,
    float* __restrict__ x)
{
    int t = blockIdx.x * 8 + (threadIdx.x >> 5);
    if (t >= NTOK) return;
    int lane = threadIdx.x & 31;
    int s_ = t % Ss, b = t / Ss;
    const float4* src4 = (s_ == 0) ? (const float4*)cls
                       : (const float4*)(pe + (size_t)(b * NPATCH + s_ - 1) * Dm);
    const float4* pos4 = (const float4*)(pos + (size_t)s_ * Dm);
    float4 v[6];
    float s = 0.f, sq = 0.f;
    #pragma unroll
    for (int j = 0; j < 6; j++) {
        float4 a = src4[j * 32 + lane], p = pos4[j * 32 + lane];
        v[j].x = a.x + p.x; v[j].y = a.y + p.y; v[j].z = a.z + p.z; v[j].w = a.w + p.w;
        s  += v[j].x + v[j].y + v[j].z + v[j].w;
        sq += v[j].x*v[j].x + v[j].y*v[j].y + v[j].z*v[j].z + v[j].w*v[j].w;
    }
    #pragma unroll
    for (int o = 16; o > 0; o >>= 1) {
        s  += __shfl_xor_sync(~0u, s, o);
        sq += __shfl_xor_sync(~0u, sq, o);
    }
    float mean = s * (1.f / Dm);
    float var  = sq * (1.f / Dm) - mean * mean;
    float r = rsqrtf(var + 1e-5f);
    const float4* sc4 = (const float4*)sc;
    const float4* bi4 = (const float4*)bi;
    #pragma unroll
    for (int j = 0; j < 6; j++) {
        float4 g = sc4[j * 32 + lane], be = bi4[j * 32 + lane];
        float4 o;
        o.x = (v[j].x - mean) * r * g.x + be.x;
        o.y = (v[j].y - mean) * r * g.y + be.y;
        o.z = (v[j].z - mean) * r * g.z + be.z;
        o.w = (v[j].w - mean) * r * g.w + be.w;
        ((float4*)(x + (size_t)t * Dm))[j * 32 + lane] = o;
    }
}

// ------------------------- head: cls_ln @ vis_proj -------------------------
__global__ __launch_bounds__(512) void k_head(const float* __restrict__ cls,
                                              const float* __restrict__ Wp,
                                              float* __restrict__ out)
{
    __shared__ float row[Dm];
    int b = blockIdx.x;
    for (int i = threadIdx.x; i < Dm; i += 512) row[i] = cls[(size_t)b * Dm + i];
    __syncthreads();
    int o = threadIdx.x;
    float acc = 0.f;
    for (int d = 0; d < Dm; d++) acc += row[d] * Wp[(size_t)d * Oo + o];
    out[(size_t)b * Oo + o] = acc;
}

// ---------------------------------------------------------------------------
extern "C" void kernel_launch(void* const* d_in, const int* in_sizes, int n_in,
                              void* d_out, int out_size)
{
    const float* images   = (const float*)d_in[0];
    const float* conv_w   = (const float*)d_in[1];
    const float* cls_emb  = (const float*)d_in[2];
    const float* pos_emb  = (const float*)d_in[3];
    const float* ln_pre_s = (const float*)d_in[4];
    const float* ln_pre_b = (const float*)d_in[5];
    const float* ln1_s    = (const float*)d_in[6];
    const float* ln1_b    = (const float*)d_in[7];
    const float* qkv_w    = (const float*)d_in[8];
    const float* qkv_b    = (const float*)d_in[9];
    const float* out_w    = (const float*)d_in[10];
    const float* out_b    = (const float*)d_in[11];
    const float* ln2_s    = (const float*)d_in[12];
    const float* ln2_b    = (const float*)d_in[13];
    const float* fc_w     = (const float*)d_in[14];
    const float* fc_b     = (const float*)d_in[15];
    const float* proj_w   = (const float*)d_in[16];
    const float* proj_b   = (const float*)d_in[17];
    const float* lnp_s    = (const float*)d_in[18];
    const float* lnp_b    = (const float*)d_in[19];
    const float* vis_proj = (const float*)d_in[20];
    float* outp = (float*)d_out;

    __half *w, *xp, *h, *qkvh, *ao, *mlp;
    float *pe, *x, *cls;
    cudaGetSymbolAddress((void**)&w,    g_w);
    cudaGetSymbolAddress((void**)&xp,   g_xp);
    cudaGetSymbolAddress((void**)&pe,   g_pe);
    cudaGetSymbolAddress((void**)&x,    g_x);
    cudaGetSymbolAddress((void**)&h,    g_h);
    cudaGetSymbolAddress((void**)&qkvh, g_qkvh);
    cudaGetSymbolAddress((void**)&ao,   g_ao);
    cudaGetSymbolAddress((void**)&mlp,  g_mlp);
    cudaGetSymbolAddress((void**)&cls,  g_cls);

    cudaFuncSetAttribute(k_mm<false,false,false,false>, cudaFuncAttributeMaxDynamicSharedMemorySize, MM_SMEM);
    cudaFuncSetAttribute(k_mm<true, false,false,true >, cudaFuncAttributeMaxDynamicSharedMemorySize, MM_SMEM);
    cudaFuncSetAttribute(k_mm<true, true, false,false>, cudaFuncAttributeMaxDynamicSharedMemorySize, MM_SMEM);
    cudaFuncSetAttribute(k_mm<true, false,true, true >, cudaFuncAttributeMaxDynamicSharedMemorySize, MM_SMEM);
    cudaFuncSetAttribute(k_attn, cudaFuncAttributeMaxDynamicSharedMemorySize, ATT_SMEM);

    // ---- all weights fp32 -> fp16, one launch ----
    k_cvt_all<<<(F4_TOT + 255) / 256, 256>>>(
        (const float4*)conv_w, (const float4*)qkv_w, (const float4*)out_w,
        (const float4*)fc_w, (const float4*)proj_w, (__half2*)w);

    // ---- stem ----
    k_patchify<<<(NPROW * Dm + 255) / 256, 256>>>(images, xp);
    k_mm<false,false,false,false><<<dim3(Dm / 128, (NPROW + 127) / 128), 256, MM_SMEM>>>(
        xp, w + OFF_CONV, nullptr, nullptr, pe, nullptr, NPROW, Dm, Dm);
    k_asmln<<<(NTOK + 7) / 8, 256>>>(pe, cls_emb, pos_emb, ln_pre_s, ln_pre_b, x);

    // ---- transformer layers ----
    for (int l = 0; l < Ll; l++) {
        const float* l1s = ln1_s + (size_t)l * Dm;
        const float* l1b = ln1_b + (size_t)l * Dm;
        const float* qb  = qkv_b + (size_t)l * 3 * Dm;
        const float* ob  = out_b + (size_t)l * Dm;
        const float* l2s = ln2_s + (size_t)l * Dm;
        const float* l2b = ln2_b + (size_t)l * Dm;
        const float* fb  = fc_b  + (size_t)l * Ff;
        const float* pb  = proj_b + (size_t)l * Dm;
        const __half* qw = w + OFF_QKV  + (size_t)l * 2304 * 768;
        const __half* ow = w + OFF_OUT  + (size_t)l * 768 * 768;
        const __half* fw = w + OFF_FC   + (size_t)l * 3072 * 768;
        const __half* pw = w + OFF_PROJ + (size_t)l * 768 * 3072;

        k_ln<true><<<(NTOK + 7) / 8, 256>>>(x, nullptr, h, l1s, l1b, Dm, Dm, NTOK);
        k_mm<true,false,false,true><<<dim3(3 * Dm / 128, (NTOK + 127) / 128), 256, MM_SMEM>>>(
            h, qw, qb, nullptr, nullptr, qkvh, NTOK, 3 * Dm, Dm);
        k_attn<<<Bsz * Hh, 256, ATT_SMEM>>>(qkvh, ao);
        k_mm<true,true,false,false><<<dim3(Dm / 128, (NTOK + 127) / 128), 256, MM_SMEM>>>(
            ao, ow, ob, x, x, nullptr, NTOK, Dm, Dm);
        k_ln<true><<<(NTOK + 7) / 8, 256>>>(x, nullptr, h, l2s, l2b, Dm, Dm, NTOK);
        k_mm<true,false,true,true><<<dim3(Ff / 128, (NTOK + 127) / 128), 256, MM_SMEM>>>(
            h, fw, fb, nullptr, nullptr, mlp, NTOK, Ff, Dm);
        k_mm<true,true,false,false><<<dim3(Dm / 128, (NTOK + 127) / 128), 256, MM_SMEM>>>(
            mlp, pw, pb, x, x, nullptr, NTOK, Dm, Ff);
    }

    // ---- head ----
    k_ln<false><<<4, 256>>>(x, cls, nullptr, lnp_s, lnp_b, (long)Ss * Dm, Dm, Bsz);
    k_head<<<Bsz, 512>>>(cls, vis_proj, outp);
}